// round 11
// baseline (speedup 1.0000x reference)
#include <cuda_runtime.h>
#include <cuda_bf16.h>
#include <math.h>
#include <stdint.h>

#define NLAYER 12
#define EPSV 1e-5f
typedef unsigned short u16;

// ---------------- f32 scratch ------------------------------------------------
__device__ float g_e  [1048576];
__device__ float g_q  [1048576];
__device__ float g_big[4194304];
__device__ float g_s  [8388608];

// ---------------- bf16 hi/lo buffers -----------------------------------------
#define OFF_E1 0L
#define OFF_E2 1048576L
#define OFF_EI 1572864L
#define OFF_Q  2621440L
#define OFF_K  8912896L
#define OFF_V  15204352L
#define OFF_O  21495808L
#define OFF_F1 27787264L
#define OFF_F2 52953088L
#define OFF_D1 78118912L
#define OFF_D2 79167488L
#define OFF_DI 81264640L
#define W_TOT  82313216L
__device__ u16 g_wh[W_TOT];
__device__ u16 g_wl[W_TOT];
__device__ u16 g_ath[4194304], g_atl[4194304];
__device__ u16 g_hth[1048576], g_htl[1048576];
__device__ u16 g_qth[1048576], g_qtl[1048576];
__device__ u16 g_kth[1048576], g_ktl[1048576];
__device__ u16 g_vh [1048576], g_vl [1048576];
__device__ u16 g_ph [8388608], g_pl [8388608];
__device__ u16 g_oth[1048576], g_otl[1048576];

// ---------------- helpers ----------------------------------------------------
__device__ __forceinline__ uint32_t smem_u32(const void* p) {
    uint32_t a;
    asm("{ .reg .u64 t; cvta.to.shared.u64 t, %1; cvt.u32.u64 %0, t; }" : "=r"(a) : "l"(p));
    return a;
}
#define SWZ(x) ((x) ^ (((x) >> 3) & 0x70))

__device__ __forceinline__ void cp16(uint32_t d, const void* g) {
    asm volatile("cp.async.cg.shared.global [%0], [%1], 16;" :: "r"(d), "l"(g));
}
__device__ __forceinline__ void cp_commit() { asm volatile("cp.async.commit_group;"); }
template<int N> __device__ __forceinline__ void cp_wait() {
    asm volatile("cp.async.wait_group %0;" :: "n"(N));
}
__device__ __forceinline__ void ldsm4(uint32_t* r, uint32_t a) {
    asm volatile("ldmatrix.sync.aligned.m8n8.x4.shared.b16 {%0,%1,%2,%3}, [%4];"
                 : "=r"(r[0]), "=r"(r[1]), "=r"(r[2]), "=r"(r[3]) : "r"(a));
}
__device__ __forceinline__ void mma16816(float* c, const uint32_t* a, const uint32_t* b) {
    asm volatile(
        "mma.sync.aligned.m16n8k16.row.col.f32.bf16.bf16.f32 "
        "{%0,%1,%2,%3}, {%4,%5,%6,%7}, {%8,%9}, {%0,%1,%2,%3};"
        : "+f"(c[0]), "+f"(c[1]), "+f"(c[2]), "+f"(c[3])
        : "r"(a[0]), "r"(a[1]), "r"(a[2]), "r"(a[3]), "r"(b[0]), "r"(b[1]));
}
__device__ __forceinline__ void splt(float v, u16& h, u16& l) {
    __nv_bfloat16 hb = __float2bfloat16(v);
    h = __bfloat16_as_ushort(hb);
    l = __bfloat16_as_ushort(__float2bfloat16(v - __bfloat162float(hb)));
}

// warp computes 32m x (NT*8)n over one K-chunk of 64, 3-term split (verified)
template<int NT>
__device__ __forceinline__ void mma_chunk(
    float (&acc)[2][NT][4], uint32_t aHi, uint32_t aLo, uint32_t bHi, uint32_t bLo,
    int wm, int wn, int lane)
{
    int la = lane & 7, j = lane >> 3;
    #pragma unroll
    for (int ks = 0; ks < 4; ks++) {
        uint32_t ah[2][4], al[2][4];
        #pragma unroll
        for (int mi = 0; mi < 2; mi++) {
            uint32_t off = SWZ((uint32_t)((wm * 32 + mi * 16 + ((j & 1) << 3) + la) * 128 + ks * 32 + ((j >> 1) << 4)));
            ldsm4(ah[mi], aHi + off);
            ldsm4(al[mi], aLo + off);
        }
        uint32_t bh[NT][2], bl[NT][2];
        #pragma unroll
        for (int nt = 0; nt < NT; nt += 2) {
            uint32_t off = SWZ((uint32_t)((wn * NT * 8 + nt * 8 + ((j >> 1) << 3) + la) * 128 + ks * 32 + ((j & 1) << 4)));
            uint32_t t[4];
            ldsm4(t, bHi + off);
            bh[nt][0] = t[0]; bh[nt][1] = t[1]; bh[nt + 1][0] = t[2]; bh[nt + 1][1] = t[3];
            ldsm4(t, bLo + off);
            bl[nt][0] = t[0]; bl[nt][1] = t[1]; bl[nt + 1][0] = t[2]; bl[nt + 1][1] = t[3];
        }
        #pragma unroll
        for (int mi = 0; mi < 2; mi++)
            #pragma unroll
            for (int nt = 0; nt < NT; nt++) {
                mma16816(acc[mi][nt], ah[mi], bh[nt]);
                mma16816(acc[mi][nt], ah[mi], bl[nt]);
                mma16816(acc[mi][nt], al[mi], bh[nt]);
            }
    }
}

// ---------------- one-time weight split --------------------------------------
__global__ void __launch_bounds__(256) split_w(
    const float* p0, const float* p1, const float* p2, const float* p3,
    const float* p4, const float* p5, const float* p6, const float* p7,
    const float* p8, const float* p9, const float* p10, const float* p11)
{
    const long offs[12] = {OFF_E1, OFF_E2, OFF_EI, OFF_Q, OFF_K, OFF_V,
                           OFF_O, OFF_F1, OFF_F2, OFF_D1, OFF_D2, OFF_DI};
    const float* ptrs[12] = {p0, p1, p2, p3, p4, p5, p6, p7, p8, p9, p10, p11};
    long base = ((long)blockIdx.x * 256 + threadIdx.x) * 16;
    if (base >= W_TOT) return;
    int seg = 0;
    #pragma unroll
    for (int i = 1; i < 12; i++) if (base >= offs[i]) seg = i;
    const float* src = ptrs[seg] + (base - offs[seg]);
    u16 hb[16], lb[16];
    #pragma unroll
    for (int t = 0; t < 16; t += 4) {
        float4 x = *reinterpret_cast<const float4*>(src + t);
        splt(x.x, hb[t], lb[t]); splt(x.y, hb[t+1], lb[t+1]);
        splt(x.z, hb[t+2], lb[t+2]); splt(x.w, hb[t+3], lb[t+3]);
    }
    uint4* dh = reinterpret_cast<uint4*>(&g_wh[base]);
    uint4* dl = reinterpret_cast<uint4*>(&g_wl[base]);
    dh[0] = ((uint4*)hb)[0]; dh[1] = ((uint4*)hb)[1];
    dl[0] = ((uint4*)lb)[0]; dl[1] = ((uint4*)lb)[1];
}

// ---------------- transpose-split (plain) ------------------------------------
__global__ void __launch_bounds__(256) tsplit(
    const float* __restrict__ X, u16* __restrict__ Th, u16* __restrict__ Tl, int R)
{
    __shared__ float s[64][65];
    int tid = threadIdx.x;
    int z = blockIdx.z, f0 = blockIdx.y * 64, w0 = blockIdx.x * 64;
    const float* Xb = X + ((size_t)z * R + f0) * 512 + w0;
    for (int it = tid; it < 1024; it += 256) {
        int r = it >> 4, cg = it & 15;
        float4 v = *reinterpret_cast<const float4*>(Xb + (size_t)r * 512 + cg * 4);
        s[r][cg * 4 + 0] = v.x; s[r][cg * 4 + 1] = v.y;
        s[r][cg * 4 + 2] = v.z; s[r][cg * 4 + 3] = v.w;
    }
    __syncthreads();
    for (int it = tid; it < 512; it += 256) {
        int w = it >> 3, cg = it & 7;
        u16 hb[8], lb[8];
        #pragma unroll
        for (int j = 0; j < 8; j++) splt(s[cg * 8 + j][w], hb[j], lb[j]);
        size_t o = ((size_t)z * 512 + w0 + w) * R + f0 + cg * 8;
        *reinterpret_cast<uint4*>(Th + o) = *reinterpret_cast<uint4*>(hb);
        *reinterpret_cast<uint4*>(Tl + o) = *reinterpret_cast<uint4*>(lb);
    }
}

// ---------------- frame_norm fused with transpose-split ----------------------
__global__ void __launch_bounds__(256) fn_tsplit(
    const float* __restrict__ X, const float* __restrict__ gw, const float* __restrict__ gb,
    u16* __restrict__ Th, u16* __restrict__ Tl)
{
    int tid = threadIdx.x;
    int bc = blockIdx.y, c = bc & 1;
    int w0 = blockIdx.x * 64;
    const float* Xb = X + (size_t)bc * 262144;

    int wl = tid & 63, part = tid >> 6;
    float sum = 0.f, sq = 0.f;
    for (int f = part; f < 512; f += 4) {
        float v = Xb[(size_t)f * 512 + w0 + wl];
        sum += v; sq += v * v;
    }
    __shared__ float r1[4][64], r2[4][64];
    __shared__ float smu[64], srs[64];
    r1[part][wl] = sum; r2[part][wl] = sq;
    __syncthreads();
    if (tid < 64) {
        float s = r1[0][tid] + r1[1][tid] + r1[2][tid] + r1[3][tid];
        float q = r2[0][tid] + r2[1][tid] + r2[2][tid] + r2[3][tid];
        float mu = s * (1.f / 512.f);
        float var = q * (1.f / 512.f) - mu * mu;
        smu[tid] = mu; srs[tid] = rsqrtf(var + EPSV);
    }
    __syncthreads();

    __shared__ float tile[64][65];
    for (int ft = 0; ft < 8; ft++) {
        for (int it = tid; it < 1024; it += 256) {
            int r = it >> 4, cg = it & 15;
            float4 v = *reinterpret_cast<const float4*>(Xb + (size_t)(ft * 64 + r) * 512 + w0 + cg * 4);
            tile[r][cg * 4 + 0] = v.x; tile[r][cg * 4 + 1] = v.y;
            tile[r][cg * 4 + 2] = v.z; tile[r][cg * 4 + 3] = v.w;
        }
        __syncthreads();
        int w = tid >> 2, seg = tid & 3;
        float mu = smu[w], rs = srs[w];
        u16 hb[16], lb[16];
        #pragma unroll
        for (int j = 0; j < 16; j++) {
            int f = seg * 16 + j, fg = ft * 64 + f;
            float v = (tile[f][w] - mu) * rs * gw[c * 512 + fg] + gb[c * 512 + fg];
            splt(v, hb[j], lb[j]);
        }
        size_t o = ((size_t)bc * 512 + w0 + w) * 512 + ft * 64 + seg * 16;
        reinterpret_cast<uint4*>(Th + o)[0] = ((uint4*)hb)[0];
        reinterpret_cast<uint4*>(Th + o)[1] = ((uint4*)hb)[1];
        reinterpret_cast<uint4*>(Tl + o)[0] = ((uint4*)lb)[0];
        reinterpret_cast<uint4*>(Tl + o)[1] = ((uint4*)lb)[1];
        __syncthreads();
    }
}

// ---------------- channel-mix + RoPE + transpose-split (Q,K) -----------------
__global__ void __launch_bounds__(256) rope_tsplit(
    const float* __restrict__ big, const float* __restrict__ qdw, const float* __restrict__ kdw,
    u16* __restrict__ Qh, u16* __restrict__ Ql, u16* __restrict__ Kh, u16* __restrict__ Kl)
{
    __shared__ float tile[64][65];
    int tid = threadIdx.x;
    int zz = blockIdx.z;
    int proj = zz >> 2, bd = zz & 3;
    int b = bd >> 1, d = bd & 1;
    int f0 = blockIdx.y * 64, w0 = blockIdx.x * 64;
    const float* dw = proj ? kdw : qdw;
    float d0 = dw[d * 2 + 0], d1 = dw[d * 2 + 1];
    const float* X0 = big + ((size_t)(proj * 4 + b * 2) * 512 + f0) * 512 + w0;
    const float* X1 = X0 + 262144;
    for (int it = tid; it < 1024; it += 256) {
        int r = it >> 4, cg = it & 15;
        float4 a = *reinterpret_cast<const float4*>(X0 + (size_t)r * 512 + cg * 4);
        float4 bb = *reinterpret_cast<const float4*>(X1 + (size_t)r * 512 + cg * 4);
        tile[r][cg * 4 + 0] = d0 * a.x + d1 * bb.x;
        tile[r][cg * 4 + 1] = d0 * a.y + d1 * bb.y;
        tile[r][cg * 4 + 2] = d0 * a.z + d1 * bb.z;
        tile[r][cg * 4 + 3] = d0 * a.w + d1 * bb.w;
    }
    __syncthreads();
    int w = tid >> 2, seg = tid & 3;
    int wg = w0 + w;
    u16 hb[16], lb[16];
    #pragma unroll
    for (int j2 = 0; j2 < 8; j2++) {
        int fe = seg * 16 + j2 * 2, fg = f0 + fe;
        int i = (fg & 63) >> 1;
        float inv = powf(10000.f, -(float)(2 * i) / 64.f);
        float sn, cs;
        sincosf((float)wg * inv, &sn, &cs);
        float v0 = tile[fe][w], v1 = tile[fe + 1][w];
        splt(v0 * cs - v1 * sn, hb[j2 * 2], lb[j2 * 2]);
        splt(v1 * cs + v0 * sn, hb[j2 * 2 + 1], lb[j2 * 2 + 1]);
    }
    u16* Th = proj ? Kh : Qh;
    u16* Tl = proj ? Kl : Ql;
    size_t o = ((size_t)bd * 512 + wg) * 512 + f0 + seg * 16;
    reinterpret_cast<uint4*>(Th + o)[0] = ((uint4*)hb)[0];
    reinterpret_cast<uint4*>(Th + o)[1] = ((uint4*)hb)[1];
    reinterpret_cast<uint4*>(Tl + o)[0] = ((uint4*)lb)[0];
    reinterpret_cast<uint4*>(Tl + o)[1] = ((uint4*)lb)[1];
}

// ---------------- V channel-mix -> bf16 hi/lo natural ------------------------
__global__ void __launch_bounds__(256) qkv_v(
    const float* __restrict__ big, const float* __restrict__ vdw,
    u16* __restrict__ Vh, u16* __restrict__ Vl)
{
    int idx = blockIdx.x * 256 + threadIdx.x;
    int w = idx & 511, f = (idx >> 9) & 511, bd = idx >> 18;
    int b = bd >> 1, d = bd & 1;
    size_t base = ((size_t)(8 + b * 2) * 512 + f) * 512 + w;
    float v = vdw[d * 2 + 0] * big[base] + vdw[d * 2 + 1] * big[base + 262144];
    u16 h, l;
    splt(v, h, l);
    size_t o = ((size_t)bd * 512 + f) * 512 + w;
    Vh[o] = h; Vl[o] = l;
}

// ---------------- pipelined bf16 GEMM (verified R7; now 2 blocks/SM) ---------
template<int OUT>  // 0 f32 ; 2 f32+res ; 3 sqrelu -> bf16T
__global__ void __launch_bounds__(256, 2) gemm_bb(
    const u16* __restrict__ Ah, const u16* __restrict__ Al,
    const u16* __restrict__ Bh, const u16* __restrict__ Bl,
    const float* __restrict__ Res, float* __restrict__ C,
    u16* __restrict__ CTh, u16* __restrict__ CTl,
    int M, int K, long projStride)
{
    extern __shared__ char sm[];
    uint32_t sb = smem_u32(sm);
    int tid = threadIdx.x, wid = tid >> 5, lane = tid & 31;
    int wm = wid >> 2, wn = wid & 3;
    int proj = blockIdx.z >> 2, bc = blockIdx.z & 3, c = bc & 1;
    const u16* Ab_h = Ah + proj * projStride + (size_t)c * M * K;
    const u16* Ab_l = Al + proj * projStride + (size_t)c * M * K;
    const u16* Bb_h = Bh + (size_t)bc * 512 * K;
    const u16* Bb_l = Bl + (size_t)bc * 512 * K;
    int m0 = blockIdx.y * 64, n0 = blockIdx.x * 128;

    auto load_stage = [&](int ch, int s) {
        uint32_t st = sb + s * 49152;
        const u16* ah = Ab_h + (size_t)m0 * K + ch * 64;
        const u16* al = Ab_l + (size_t)m0 * K + ch * 64;
        for (int it = tid; it < 512; it += 256) {
            int r = it >> 3, cg = it & 7;
            uint32_t o = SWZ((uint32_t)(r * 128 + cg * 16));
            size_t gof = (size_t)r * K + cg * 8;
            cp16(st + o, ah + gof);
            cp16(st + 8192 + o, al + gof);
        }
        const u16* bh = Bb_h + (size_t)n0 * K + ch * 64;
        const u16* bl = Bb_l + (size_t)n0 * K + ch * 64;
        for (int it = tid; it < 1024; it += 256) {
            int r = it >> 3, cg = it & 7;
            uint32_t o = SWZ((uint32_t)(r * 128 + cg * 16));
            size_t gof = (size_t)r * K + cg * 8;
            cp16(st + 16384 + o, bh + gof);
            cp16(st + 32768 + o, bl + gof);
        }
    };

    float acc[2][4][4] = {};
    int NC = K >> 6;
    load_stage(0, 0); cp_commit();
    for (int ch = 0; ch < NC; ch++) {
        if (ch + 1 < NC) { load_stage(ch + 1, (ch + 1) & 1); cp_commit(); cp_wait<1>(); }
        else cp_wait<0>();
        __syncthreads();
        uint32_t st = sb + (ch & 1) * 49152;
        mma_chunk<4>(acc, st, st + 8192, st + 16384, st + 32768, wm, wn, lane);
        __syncthreads();
    }

    float* stg = (float*)sm;  // 64 x 132
    #pragma unroll
    for (int mi = 0; mi < 2; mi++)
        #pragma unroll
        for (int nt = 0; nt < 4; nt++) {
            int row = wm * 32 + mi * 16 + (lane >> 2);
            int col = wn * 32 + nt * 8 + (lane & 3) * 2;
            stg[row * 132 + col] = acc[mi][nt][0];
            stg[row * 132 + col + 1] = acc[mi][nt][1];
            stg[(row + 8) * 132 + col] = acc[mi][nt][2];
            stg[(row + 8) * 132 + col + 1] = acc[mi][nt][3];
        }
    __syncthreads();

    if (OUT == 3) {
        int j = tid >> 1, msel = tid & 1;
        u16 hb[32], lb[32];
        #pragma unroll
        for (int i = 0; i < 32; i++) {
            float v = stg[(msel * 32 + i) * 132 + j];
            float r = fmaxf(v, 0.f); v = r * r;
            splt(v, hb[i], lb[i]);
        }
        size_t o = ((size_t)bc * 512 + n0 + j) * (size_t)M + m0 + msel * 32;
        #pragma unroll
        for (int t = 0; t < 4; t++) {
            reinterpret_cast<uint4*>(CTh + o)[t] = ((uint4*)hb)[t];
            reinterpret_cast<uint4*>(CTl + o)[t] = ((uint4*)lb)[t];
        }
    } else {
        float* Cb = C + (size_t)(proj * 4 + bc) * M * 512;
        #pragma unroll
        for (int r8 = 0; r8 < 8; r8++) {
            int row = wid + r8 * 8;
            float4 v = *reinterpret_cast<float4*>(stg + row * 132 + lane * 4);
            float vv[4] = {v.x, v.y, v.z, v.w};
            if (OUT == 2) {
                float4 rv = *reinterpret_cast<const float4*>(
                    Res + (size_t)bc * M * 512 + (size_t)(m0 + row) * 512 + n0 + lane * 4);
                vv[0] += rv.x; vv[1] += rv.y; vv[2] += rv.z; vv[3] += rv.w;
            }
            float4 ov = {vv[0], vv[1], vv[2], vv[3]};
            *reinterpret_cast<float4*>(Cb + (size_t)(m0 + row) * 512 + n0 + lane * 4) = ov;
        }
    }
}

// ---------------- attention scores: S = scale * QT @ KT^T --------------------
__global__ void __launch_bounds__(256, 2) attn_qk_bb(
    const u16* __restrict__ QTh, const u16* __restrict__ QTl,
    const u16* __restrict__ KTh, const u16* __restrict__ KTl,
    float* __restrict__ S)
{
    __shared__ char sm[49152];
    uint32_t sb = smem_u32(sm);
    int tid = threadIdx.x, wid = tid >> 5, lane = tid & 31;
    int wm = wid >> 2, wn = wid & 3;
    int z = blockIdx.z, bc = z >> 3, hd = z & 7;
    int q0 = blockIdx.y * 64, k0 = blockIdx.x * 128;
    size_t qbase = ((size_t)bc * 512 + q0) * 512 + hd * 64;
    size_t kbase = ((size_t)bc * 512 + k0) * 512 + hd * 64;

    for (int it = tid; it < 512; it += 256) {
        int r = it >> 3, cg = it & 7;
        uint32_t o = SWZ((uint32_t)(r * 128 + cg * 16));
        cp16(sb + o, QTh + qbase + (size_t)r * 512 + cg * 8);
        cp16(sb + 8192 + o, QTl + qbase + (size_t)r * 512 + cg * 8);
    }
    for (int it = tid; it < 1024; it += 256) {
        int r = it >> 3, cg = it & 7;
        uint32_t o = SWZ((uint32_t)(r * 128 + cg * 16));
        cp16(sb + 16384 + o, KTh + kbase + (size_t)r * 512 + cg * 8);
        cp16(sb + 32768 + o, KTl + kbase + (size_t)r * 512 + cg * 8);
    }
    cp_commit(); cp_wait<0>();
    __syncthreads();

    float acc[2][4][4] = {};
    mma_chunk<4>(acc, sb, sb + 8192, sb + 16384, sb + 32768, wm, wn, lane);
    __syncthreads();
    float* stg = (float*)sm;
    #pragma unroll
    for (int mi = 0; mi < 2; mi++)
        #pragma unroll
        for (int nt = 0; nt < 4; nt++) {
            int row = wm * 32 + mi * 16 + (lane >> 2);
            int col = wn * 32 + nt * 8 + (lane & 3) * 2;
            stg[row * 132 + col] = acc[mi][nt][0];
            stg[row * 132 + col + 1] = acc[mi][nt][1];
            stg[(row + 8) * 132 + col] = acc[mi][nt][2];
            stg[(row + 8) * 132 + col + 1] = acc[mi][nt][3];
        }
    __syncthreads();
    const float scale = 0.044194173824159216f;  // 1/sqrt(512)
    float* Sb = S + (size_t)z * 262144;
    #pragma unroll
    for (int r8 = 0; r8 < 8; r8++) {
        int row = wid + r8 * 8;
        float4 v = *reinterpret_cast<float4*>(stg + row * 132 + lane * 4);
        float4 o = {v.x * scale, v.y * scale, v.z * scale, v.w * scale};
        *reinterpret_cast<float4*>(Sb + (size_t)(q0 + row) * 512 + k0 + lane * 4) = o;
    }
}

// ---------------- softmax: S f32 -> P bf16 hi/lo -----------------------------
__global__ void __launch_bounds__(256) softmax_split(
    const float* __restrict__ S, u16* __restrict__ Ph, u16* __restrict__ Pl)
{
    int row = blockIdx.x * 8 + (threadIdx.x >> 5);
    int lane = threadIdx.x & 31;
    const float* p = S + (size_t)row * 512 + lane * 16;
    float v[16];
    #pragma unroll
    for (int g = 0; g < 4; g++) {
        float4 x = *reinterpret_cast<const float4*>(p + g * 4);
        v[g*4] = x.x; v[g*4+1] = x.y; v[g*4+2] = x.z; v[g*4+3] = x.w;
    }
    float mx = -1e30f;
    #pragma unroll
    for (int i = 0; i < 16; i++) mx = fmaxf(mx, v[i]);
    #pragma unroll
    for (int o = 16; o; o >>= 1) mx = fmaxf(mx, __shfl_xor_sync(0xffffffffu, mx, o));
    float sum = 0.f;
    #pragma unroll
    for (int i = 0; i < 16; i++) { v[i] = __expf(v[i] - mx); sum += v[i]; }
    #pragma unroll
    for (int o = 16; o; o >>= 1) sum += __shfl_xor_sync(0xffffffffu, sum, o);
    float inv = 1.f / sum;
    u16 hb[16], lb[16];
    #pragma unroll
    for (int i = 0; i < 16; i++) splt(v[i] * inv, hb[i], lb[i]);
    size_t o = (size_t)row * 512 + lane * 16;
    reinterpret_cast<uint4*>(Ph + o)[0] = ((uint4*)hb)[0];
    reinterpret_cast<uint4*>(Ph + o)[1] = ((uint4*)hb)[1];
    reinterpret_cast<uint4*>(Pl + o)[0] = ((uint4*)lb)[0];
    reinterpret_cast<uint4*>(Pl + o)[1] = ((uint4*)lb)[1];
}

// ---------------- attention output: OT[q,d] = sum_k P[q,k] V[d,k] ------------
__global__ void __launch_bounds__(256, 2) attn_pv_bb(
    const u16* __restrict__ Ph, const u16* __restrict__ Pl,
    const u16* __restrict__ Vh, const u16* __restrict__ Vl,
    u16* __restrict__ OTh, u16* __restrict__ OTl)
{
    extern __shared__ char sm[];
    uint32_t sb = smem_u32(sm);
    int tid = threadIdx.x, wid = tid >> 5, lane = tid & 31;
    int wm = wid >> 2, wn = wid & 3;
    int z = blockIdx.z, bc = z >> 3, hd = z & 7;
    int q0 = blockIdx.x * 64;
    size_t pbase = ((size_t)z * 512 + q0) * 512;
    size_t vbase = ((size_t)bc * 512 + hd * 64) * 512;

    auto load_stage = [&](int ch, int s) {
        uint32_t st = sb + s * 32768;
        for (int it = tid; it < 512; it += 256) {
            int r = it >> 3, cg = it & 7;
            uint32_t o = SWZ((uint32_t)(r * 128 + cg * 16));
            size_t pof = pbase + (size_t)r * 512 + ch * 64 + cg * 8;
            size_t vof = vbase + (size_t)r * 512 + ch * 64 + cg * 8;
            cp16(st + o, Ph + pof);
            cp16(st + 8192 + o, Pl + pof);
            cp16(st + 16384 + o, Vh + vof);
            cp16(st + 24576 + o, Vl + vof);
        }
    };

    float acc[2][2][4] = {};
    load_stage(0, 0); cp_commit();
    for (int ch = 0; ch < 8; ch++) {
        if (ch + 1 < 8) { load_stage(ch + 1, (ch + 1) & 1); cp_commit(); cp_wait<1>(); }
        else cp_wait<0>();
        __syncthreads();
        uint32_t st = sb + (ch & 1) * 32768;
        mma_chunk<2>(acc, st, st + 8192, st + 16384, st + 24576, wm, wn, lane);
        __syncthreads();
    }
    float* stg = (float*)sm;  // 64 x 68
    #pragma unroll
    for (int mi = 0; mi < 2; mi++)
        #pragma unroll
        for (int nt = 0; nt < 2; nt++) {
            int row = wm * 32 + mi * 16 + (lane >> 2);
            int col = wn * 16 + nt * 8 + (lane & 3) * 2;
            stg[row * 68 + col] = acc[mi][nt][0];
            stg[row * 68 + col + 1] = acc[mi][nt][1];
            stg[(row + 8) * 68 + col] = acc[mi][nt][2];
            stg[(row + 8) * 68 + col + 1] = acc[mi][nt][3];
        }
    __syncthreads();
    int row = tid >> 2, dseg = tid & 3;
    u16 hb[16], lb[16];
    #pragma unroll
    for (int j = 0; j < 16; j++) splt(stg[row * 68 + dseg * 16 + j], hb[j], lb[j]);
    size_t o = ((size_t)bc * 512 + q0 + row) * 512 + hd * 64 + dseg * 16;
    reinterpret_cast<uint4*>(OTh + o)[0] = ((uint4*)hb)[0];
    reinterpret_cast<uint4*>(OTh + o)[1] = ((uint4*)hb)[1];
    reinterpret_cast<uint4*>(OTl + o)[0] = ((uint4*)lb)[0];
    reinterpret_cast<uint4*>(OTl + o)[1] = ((uint4*)lb)[1];
}

// ---------------- channel mix (enc/dec, f32) ---------------------------------
template<bool SQRELU, bool HASADD>
__global__ void __launch_bounds__(256) mix_k(
    const float* __restrict__ X, const float* __restrict__ dw,
    const float* __restrict__ Add, float* __restrict__ Y, int Fd)
{
    int idx = blockIdx.x * 256 + threadIdx.x;
    int w = idx & 511;
    int f = (idx >> 9) % Fd;
    int bd = idx / (512 * Fd);
    int b = bd >> 1, d = bd & 1;
    size_t base = ((size_t)(b * 2) * Fd + f) * 512 + w;
    float v = dw[d * 2 + 0] * X[base] + dw[d * 2 + 1] * X[base + (size_t)Fd * 512];
    if (SQRELU) { float r = fmaxf(v, 0.f); v = r * r; }
    if (HASADD) v += Add[idx];
    Y[idx] = v;
}

// ---------------- host --------------------------------------------------------
extern "C" void kernel_launch(void* const* d_in, const int* in_sizes, int n_in,
                              void* d_out, int out_size)
{
    const float* x     = (const float*)d_in[0];
    const float* e1_pw = (const float*)d_in[1];
    const float* e1_dw = (const float*)d_in[2];
    const float* e2_pw = (const float*)d_in[3];
    const float* e2_dw = (const float*)d_in[4];
    const float* ei_pw = (const float*)d_in[5];
    const float* ei_dw = (const float*)d_in[6];
    const float* n1_w  = (const float*)d_in[7];
    const float* n1_b  = (const float*)d_in[8];
    const float* q_dw  = (const float*)d_in[10];
    const float* k_dw  = (const float*)d_in[12];
    const float* v_dw  = (const float*)d_in[14];
    const float* n2_w  = (const float*)d_in[16];
    const float* n2_b  = (const float*)d_in[17];
    const float* d1_dw = (const float*)d_in[21];
    const float* d2_dw = (const float*)d_in[23];
    const float* di_dw = (const float*)d_in[25];
    float* out = (float*)d_out;
    (void)in_sizes; (void)n_in; (void)out_size;

    float *e, *q, *big, *s;
    cudaGetSymbolAddress((void**)&e, g_e);
    cudaGetSymbolAddress((void**)&q, g_q);
    cudaGetSymbolAddress((void**)&big, g_big);
    cudaGetSymbolAddress((void**)&s, g_s);
    u16 *wh, *wl, *ath, *atl, *hth, *htl, *qth, *qtl, *kth, *ktl, *vh, *vl, *ph, *pl, *oth, *otl;
    cudaGetSymbolAddress((void**)&wh, g_wh);   cudaGetSymbolAddress((void**)&wl, g_wl);
    cudaGetSymbolAddress((void**)&ath, g_ath); cudaGetSymbolAddress((void**)&atl, g_atl);
    cudaGetSymbolAddress((void**)&hth, g_hth); cudaGetSymbolAddress((void**)&htl, g_htl);
    cudaGetSymbolAddress((void**)&qth, g_qth); cudaGetSymbolAddress((void**)&qtl, g_qtl);
    cudaGetSymbolAddress((void**)&kth, g_kth); cudaGetSymbolAddress((void**)&ktl, g_ktl);
    cudaGetSymbolAddress((void**)&vh, g_vh);   cudaGetSymbolAddress((void**)&vl, g_vl);
    cudaGetSymbolAddress((void**)&ph, g_ph);   cudaGetSymbolAddress((void**)&pl, g_pl);
    cudaGetSymbolAddress((void**)&oth, g_oth); cudaGetSymbolAddress((void**)&otl, g_otl);

    const int SMG = 98304, SMPV = 65536;
    cudaFuncSetAttribute(gemm_bb<0>, cudaFuncAttributeMaxDynamicSharedMemorySize, SMG);
    cudaFuncSetAttribute(gemm_bb<2>, cudaFuncAttributeMaxDynamicSharedMemorySize, SMG);
    cudaFuncSetAttribute(gemm_bb<3>, cudaFuncAttributeMaxDynamicSharedMemorySize, SMG);
    cudaFuncSetAttribute(attn_pv_bb, cudaFuncAttributeMaxDynamicSharedMemorySize, SMPV);

    dim3 tsG512(8, 8, 4), tsG1024(8, 16, 4);

    split_w<<<20096, 256>>>(e1_pw, e2_pw, ei_pw,
        (const float*)d_in[9], (const float*)d_in[11], (const float*)d_in[13],
        (const float*)d_in[15], (const float*)d_in[18], (const float*)d_in[19],
        (const float*)d_in[20], (const float*)d_in[22], (const float*)d_in[24]);

    // encoder
    tsplit<<<tsG1024, 256>>>(x, ath, atl, 1024);
    gemm_bb<0><<<dim3(4, 8, 4), 256, SMG>>>(wh + OFF_E1, wl + OFF_E1, ath, atl, nullptr, big, nullptr, nullptr, 512, 1024, 0);
    mix_k<true, false><<<4096, 256>>>(big, e1_dw, nullptr, q, 512);
    tsplit<<<tsG512, 256>>>(q, hth, htl, 512);
    gemm_bb<0><<<dim3(4, 8, 4), 256, SMG>>>(wh + OFF_E2, wl + OFF_E2, hth, htl, nullptr, big, nullptr, nullptr, 512, 512, 0);
    mix_k<false, false><<<4096, 256>>>(big, e2_dw, nullptr, s, 512);
    gemm_bb<0><<<dim3(4, 8, 4), 256, SMG>>>(wh + OFF_EI, wl + OFF_EI, ath, atl, nullptr, big, nullptr, nullptr, 512, 1024, 0);
    mix_k<false, true><<<4096, 256>>>(big, ei_dw, s, e, 512);

    for (int i = 0; i < NLAYER; i++) {
        long lw = (long)i * 524288;
        fn_tsplit<<<dim3(8, 4), 256>>>(e, n1_w + (size_t)i * 1024, n1_b + (size_t)i * 1024, hth, htl);
        gemm_bb<0><<<dim3(4, 8, 12), 256, SMG>>>(wh + OFF_Q + lw, wl + OFF_Q + lw, hth, htl,
                                                 nullptr, big, nullptr, nullptr, 512, 512, OFF_K - OFF_Q);
        rope_tsplit<<<dim3(8, 8, 8), 256>>>(big, q_dw + i * 4, k_dw + i * 4, qth, qtl, kth, ktl);
        qkv_v<<<4096, 256>>>(big, v_dw + i * 4, vh, vl);
        attn_qk_bb<<<dim3(4, 8, 32), 256>>>(qth, qtl, kth, ktl, s);
        softmax_split<<<2048, 256>>>(s, ph, pl);
        attn_pv_bb<<<dim3(8, 1, 32), 256, SMPV>>>(ph, pl, vh, vl, oth, otl);
        gemm_bb<2><<<dim3(4, 8, 4), 256, SMG>>>(wh + OFF_O + lw, wl + OFF_O + lw, oth, otl,
                                                e, e, nullptr, nullptr, 512, 512, 0);
        fn_tsplit<<<dim3(8, 4), 256>>>(e, n2_w + (size_t)i * 1024, n2_b + (size_t)i * 1024, hth, htl);
        long lf = (long)i * 2097152;
        gemm_bb<3><<<dim3(4, 32, 4), 256, SMG>>>(wh + OFF_F1 + lf, wl + OFF_F1 + lf, hth, htl,
                                                 nullptr, nullptr, ath, atl, 2048, 512, 0);
        gemm_bb<2><<<dim3(4, 8, 4), 256, SMG>>>(wh + OFF_F2 + lf, wl + OFF_F2 + lf, ath, atl,
                                                e, e, nullptr, nullptr, 512, 2048, 0);
    }

    // decoder
    tsplit<<<tsG512, 256>>>(e, hth, htl, 512);
    gemm_bb<0><<<dim3(4, 16, 4), 256, SMG>>>(wh + OFF_D1, wl + OFF_D1, hth, htl, nullptr, big, nullptr, nullptr, 1024, 512, 0);
    mix_k<true, false><<<8192, 256>>>(big, d1_dw, nullptr, s, 1024);
    tsplit<<<tsG1024, 256>>>(s, ath, atl, 1024);
    gemm_bb<0><<<dim3(4, 16, 4), 256, SMG>>>(wh + OFF_D2, wl + OFF_D2, ath, atl, nullptr, big + 2097152, nullptr, nullptr, 1024, 1024, 0);
    mix_k<false, false><<<8192, 256>>>(big + 2097152, d2_dw, nullptr, s + 4194304, 1024);
    gemm_bb<0><<<dim3(4, 16, 4), 256, SMG>>>(wh + OFF_DI, wl + OFF_DI, hth, htl, nullptr, big, nullptr, nullptr, 1024, 512, 0);
    mix_k<false, true><<<8192, 256>>>(big, di_dw, s + 4194304, out, 1024);
}

// round 12
// speedup vs baseline: 1.5214x; 1.5214x over previous
#include <cuda_runtime.h>
#include <cuda_bf16.h>
#include <math.h>
#include <stdint.h>

#define NLAYER 12
#define EPSV 1e-5f
typedef unsigned short u16;

// ---------------- f32 scratch ------------------------------------------------
__device__ float g_e  [1048576];
__device__ float g_q  [1048576];
__device__ float g_big[4194304];
__device__ float g_s  [8388608];

// ---------------- bf16 hi/lo buffers -----------------------------------------
#define OFF_E1 0L
#define OFF_E2 1048576L
#define OFF_EI 1572864L
#define OFF_Q  2621440L
#define OFF_K  8912896L
#define OFF_V  15204352L
#define OFF_O  21495808L
#define OFF_F1 27787264L
#define OFF_F2 52953088L
#define OFF_D1 78118912L
#define OFF_D2 79167488L
#define OFF_DI 81264640L
#define W_TOT  82313216L
__device__ u16 g_wh[W_TOT];
__device__ u16 g_wl[W_TOT];
__device__ u16 g_ath[4194304], g_atl[4194304];
__device__ u16 g_hth[1048576], g_htl[1048576];
__device__ u16 g_qth[1048576], g_qtl[1048576];
__device__ u16 g_kth[1048576], g_ktl[1048576];
__device__ u16 g_vh [1048576], g_vl [1048576];
__device__ u16 g_ph [8388608], g_pl [8388608];
__device__ u16 g_oth[1048576], g_otl[1048576];

// ---------------- helpers ----------------------------------------------------
__device__ __forceinline__ uint32_t smem_u32(const void* p) {
    uint32_t a;
    asm("{ .reg .u64 t; cvta.to.shared.u64 t, %1; cvt.u32.u64 %0, t; }" : "=r"(a) : "l"(p));
    return a;
}
#define SWZ(x) ((x) ^ (((x) >> 3) & 0x70))

__device__ __forceinline__ void cp16(uint32_t d, const void* g) {
    asm volatile("cp.async.cg.shared.global [%0], [%1], 16;" :: "r"(d), "l"(g));
}
__device__ __forceinline__ void cp_commit() { asm volatile("cp.async.commit_group;"); }
template<int N> __device__ __forceinline__ void cp_wait() {
    asm volatile("cp.async.wait_group %0;" :: "n"(N));
}
__device__ __forceinline__ void ldsm4(uint32_t* r, uint32_t a) {
    asm volatile("ldmatrix.sync.aligned.m8n8.x4.shared.b16 {%0,%1,%2,%3}, [%4];"
                 : "=r"(r[0]), "=r"(r[1]), "=r"(r[2]), "=r"(r[3]) : "r"(a));
}
__device__ __forceinline__ void mma16816(float* c, const uint32_t* a, const uint32_t* b) {
    asm volatile(
        "mma.sync.aligned.m16n8k16.row.col.f32.bf16.bf16.f32 "
        "{%0,%1,%2,%3}, {%4,%5,%6,%7}, {%8,%9}, {%0,%1,%2,%3};"
        : "+f"(c[0]), "+f"(c[1]), "+f"(c[2]), "+f"(c[3])
        : "r"(a[0]), "r"(a[1]), "r"(a[2]), "r"(a[3]), "r"(b[0]), "r"(b[1]));
}
__device__ __forceinline__ void splt(float v, u16& h, u16& l) {
    __nv_bfloat16 hb = __float2bfloat16(v);
    h = __bfloat16_as_ushort(hb);
    l = __bfloat16_as_ushort(__float2bfloat16(v - __bfloat162float(hb)));
}

// warp computes 32m x (NT*8)n over one K-chunk of 64, 3-term split (verified)
template<int NT>
__device__ __forceinline__ void mma_chunk(
    float (&acc)[2][NT][4], uint32_t aHi, uint32_t aLo, uint32_t bHi, uint32_t bLo,
    int wm, int wn, int lane)
{
    int la = lane & 7, j = lane >> 3;
    #pragma unroll
    for (int ks = 0; ks < 4; ks++) {
        uint32_t ah[2][4], al[2][4];
        #pragma unroll
        for (int mi = 0; mi < 2; mi++) {
            uint32_t off = SWZ((uint32_t)((wm * 32 + mi * 16 + ((j & 1) << 3) + la) * 128 + ks * 32 + ((j >> 1) << 4)));
            ldsm4(ah[mi], aHi + off);
            ldsm4(al[mi], aLo + off);
        }
        uint32_t bh[NT][2], bl[NT][2];
        #pragma unroll
        for (int nt = 0; nt < NT; nt += 2) {
            uint32_t off = SWZ((uint32_t)((wn * NT * 8 + nt * 8 + ((j >> 1) << 3) + la) * 128 + ks * 32 + ((j & 1) << 4)));
            uint32_t t[4];
            ldsm4(t, bHi + off);
            bh[nt][0] = t[0]; bh[nt][1] = t[1]; bh[nt + 1][0] = t[2]; bh[nt + 1][1] = t[3];
            ldsm4(t, bLo + off);
            bl[nt][0] = t[0]; bl[nt][1] = t[1]; bl[nt + 1][0] = t[2]; bl[nt + 1][1] = t[3];
        }
        #pragma unroll
        for (int mi = 0; mi < 2; mi++)
            #pragma unroll
            for (int nt = 0; nt < NT; nt++) {
                mma16816(acc[mi][nt], ah[mi], bh[nt]);
                mma16816(acc[mi][nt], ah[mi], bl[nt]);
                mma16816(acc[mi][nt], al[mi], bh[nt]);
            }
    }
}

// ---------------- one-time weight split --------------------------------------
__global__ void __launch_bounds__(256) split_w(
    const float* p0, const float* p1, const float* p2, const float* p3,
    const float* p4, const float* p5, const float* p6, const float* p7,
    const float* p8, const float* p9, const float* p10, const float* p11)
{
    const long offs[12] = {OFF_E1, OFF_E2, OFF_EI, OFF_Q, OFF_K, OFF_V,
                           OFF_O, OFF_F1, OFF_F2, OFF_D1, OFF_D2, OFF_DI};
    const float* ptrs[12] = {p0, p1, p2, p3, p4, p5, p6, p7, p8, p9, p10, p11};
    long base = ((long)blockIdx.x * 256 + threadIdx.x) * 16;
    if (base >= W_TOT) return;
    int seg = 0;
    #pragma unroll
    for (int i = 1; i < 12; i++) if (base >= offs[i]) seg = i;
    const float* src = ptrs[seg] + (base - offs[seg]);
    u16 hb[16], lb[16];
    #pragma unroll
    for (int t = 0; t < 16; t += 4) {
        float4 x = *reinterpret_cast<const float4*>(src + t);
        splt(x.x, hb[t], lb[t]); splt(x.y, hb[t+1], lb[t+1]);
        splt(x.z, hb[t+2], lb[t+2]); splt(x.w, hb[t+3], lb[t+3]);
    }
    uint4* dh = reinterpret_cast<uint4*>(&g_wh[base]);
    uint4* dl = reinterpret_cast<uint4*>(&g_wl[base]);
    dh[0] = ((uint4*)hb)[0]; dh[1] = ((uint4*)hb)[1];
    dl[0] = ((uint4*)lb)[0]; dl[1] = ((uint4*)lb)[1];
}

// ---------------- transpose-split (plain) ------------------------------------
__global__ void __launch_bounds__(256) tsplit(
    const float* __restrict__ X, u16* __restrict__ Th, u16* __restrict__ Tl, int R)
{
    __shared__ float s[64][65];
    int tid = threadIdx.x;
    int z = blockIdx.z, f0 = blockIdx.y * 64, w0 = blockIdx.x * 64;
    const float* Xb = X + ((size_t)z * R + f0) * 512 + w0;
    for (int it = tid; it < 1024; it += 256) {
        int r = it >> 4, cg = it & 15;
        float4 v = *reinterpret_cast<const float4*>(Xb + (size_t)r * 512 + cg * 4);
        s[r][cg * 4 + 0] = v.x; s[r][cg * 4 + 1] = v.y;
        s[r][cg * 4 + 2] = v.z; s[r][cg * 4 + 3] = v.w;
    }
    __syncthreads();
    for (int it = tid; it < 512; it += 256) {
        int w = it >> 3, cg = it & 7;
        u16 hb[8], lb[8];
        #pragma unroll
        for (int j = 0; j < 8; j++) splt(s[cg * 8 + j][w], hb[j], lb[j]);
        size_t o = ((size_t)z * 512 + w0 + w) * R + f0 + cg * 8;
        *reinterpret_cast<uint4*>(Th + o) = *reinterpret_cast<uint4*>(hb);
        *reinterpret_cast<uint4*>(Tl + o) = *reinterpret_cast<uint4*>(lb);
    }
}

// ---------------- frame_norm fused with transpose-split ----------------------
__global__ void __launch_bounds__(256) fn_tsplit(
    const float* __restrict__ X, const float* __restrict__ gw, const float* __restrict__ gb,
    u16* __restrict__ Th, u16* __restrict__ Tl)
{
    int tid = threadIdx.x;
    int bc = blockIdx.y, c = bc & 1;
    int w0 = blockIdx.x * 64;
    const float* Xb = X + (size_t)bc * 262144;

    int wl = tid & 63, part = tid >> 6;
    float sum = 0.f, sq = 0.f;
    for (int f = part; f < 512; f += 4) {
        float v = Xb[(size_t)f * 512 + w0 + wl];
        sum += v; sq += v * v;
    }
    __shared__ float r1[4][64], r2[4][64];
    __shared__ float smu[64], srs[64];
    r1[part][wl] = sum; r2[part][wl] = sq;
    __syncthreads();
    if (tid < 64) {
        float s = r1[0][tid] + r1[1][tid] + r1[2][tid] + r1[3][tid];
        float q = r2[0][tid] + r2[1][tid] + r2[2][tid] + r2[3][tid];
        float mu = s * (1.f / 512.f);
        float var = q * (1.f / 512.f) - mu * mu;
        smu[tid] = mu; srs[tid] = rsqrtf(var + EPSV);
    }
    __syncthreads();

    __shared__ float tile[64][65];
    for (int ft = 0; ft < 8; ft++) {
        for (int it = tid; it < 1024; it += 256) {
            int r = it >> 4, cg = it & 15;
            float4 v = *reinterpret_cast<const float4*>(Xb + (size_t)(ft * 64 + r) * 512 + w0 + cg * 4);
            tile[r][cg * 4 + 0] = v.x; tile[r][cg * 4 + 1] = v.y;
            tile[r][cg * 4 + 2] = v.z; tile[r][cg * 4 + 3] = v.w;
        }
        __syncthreads();
        int w = tid >> 2, seg = tid & 3;
        float mu = smu[w], rs = srs[w];
        u16 hb[16], lb[16];
        #pragma unroll
        for (int j = 0; j < 16; j++) {
            int f = seg * 16 + j, fg = ft * 64 + f;
            float v = (tile[f][w] - mu) * rs * gw[c * 512 + fg] + gb[c * 512 + fg];
            splt(v, hb[j], lb[j]);
        }
        size_t o = ((size_t)bc * 512 + w0 + w) * 512 + ft * 64 + seg * 16;
        reinterpret_cast<uint4*>(Th + o)[0] = ((uint4*)hb)[0];
        reinterpret_cast<uint4*>(Th + o)[1] = ((uint4*)hb)[1];
        reinterpret_cast<uint4*>(Tl + o)[0] = ((uint4*)lb)[0];
        reinterpret_cast<uint4*>(Tl + o)[1] = ((uint4*)lb)[1];
        __syncthreads();
    }
}

// ---------------- channel-mix + RoPE + transpose-split (Q,K) -----------------
__global__ void __launch_bounds__(256) rope_tsplit(
    const float* __restrict__ big, const float* __restrict__ qdw, const float* __restrict__ kdw,
    u16* __restrict__ Qh, u16* __restrict__ Ql, u16* __restrict__ Kh, u16* __restrict__ Kl)
{
    __shared__ float tile[64][65];
    int tid = threadIdx.x;
    int zz = blockIdx.z;
    int proj = zz >> 2, bd = zz & 3;
    int b = bd >> 1, d = bd & 1;
    int f0 = blockIdx.y * 64, w0 = blockIdx.x * 64;
    const float* dw = proj ? kdw : qdw;
    float d0 = dw[d * 2 + 0], d1 = dw[d * 2 + 1];
    const float* X0 = big + ((size_t)(proj * 4 + b * 2) * 512 + f0) * 512 + w0;
    const float* X1 = X0 + 262144;
    for (int it = tid; it < 1024; it += 256) {
        int r = it >> 4, cg = it & 15;
        float4 a = *reinterpret_cast<const float4*>(X0 + (size_t)r * 512 + cg * 4);
        float4 bb = *reinterpret_cast<const float4*>(X1 + (size_t)r * 512 + cg * 4);
        tile[r][cg * 4 + 0] = d0 * a.x + d1 * bb.x;
        tile[r][cg * 4 + 1] = d0 * a.y + d1 * bb.y;
        tile[r][cg * 4 + 2] = d0 * a.z + d1 * bb.z;
        tile[r][cg * 4 + 3] = d0 * a.w + d1 * bb.w;
    }
    __syncthreads();
    int w = tid >> 2, seg = tid & 3;
    int wg = w0 + w;
    u16 hb[16], lb[16];
    #pragma unroll
    for (int j2 = 0; j2 < 8; j2++) {
        int fe = seg * 16 + j2 * 2, fg = f0 + fe;
        int i = (fg & 63) >> 1;
        float inv = powf(10000.f, -(float)(2 * i) / 64.f);
        float sn, cs;
        sincosf((float)wg * inv, &sn, &cs);
        float v0 = tile[fe][w], v1 = tile[fe + 1][w];
        splt(v0 * cs - v1 * sn, hb[j2 * 2], lb[j2 * 2]);
        splt(v1 * cs + v0 * sn, hb[j2 * 2 + 1], lb[j2 * 2 + 1]);
    }
    u16* Th = proj ? Kh : Qh;
    u16* Tl = proj ? Kl : Ql;
    size_t o = ((size_t)bd * 512 + wg) * 512 + f0 + seg * 16;
    reinterpret_cast<uint4*>(Th + o)[0] = ((uint4*)hb)[0];
    reinterpret_cast<uint4*>(Th + o)[1] = ((uint4*)hb)[1];
    reinterpret_cast<uint4*>(Tl + o)[0] = ((uint4*)lb)[0];
    reinterpret_cast<uint4*>(Tl + o)[1] = ((uint4*)lb)[1];
}

// ---------------- V channel-mix -> bf16 hi/lo natural ------------------------
__global__ void __launch_bounds__(256) qkv_v(
    const float* __restrict__ big, const float* __restrict__ vdw,
    u16* __restrict__ Vh, u16* __restrict__ Vl)
{
    int idx = blockIdx.x * 256 + threadIdx.x;
    int w = idx & 511, f = (idx >> 9) & 511, bd = idx >> 18;
    int b = bd >> 1, d = bd & 1;
    size_t base = ((size_t)(8 + b * 2) * 512 + f) * 512 + w;
    float v = vdw[d * 2 + 0] * big[base] + vdw[d * 2 + 1] * big[base + 262144];
    u16 h, l;
    splt(v, h, l);
    size_t o = ((size_t)bd * 512 + f) * 512 + w;
    Vh[o] = h; Vl[o] = l;
}

// ---------------- pipelined bf16 GEMM (2 blocks/SM) --------------------------
template<int OUT>  // 0 f32 ; 2 f32+res ; 3 sqrelu -> bf16T
__global__ void __launch_bounds__(256, 2) gemm_bb(
    const u16* __restrict__ Ah, const u16* __restrict__ Al,
    const u16* __restrict__ Bh, const u16* __restrict__ Bl,
    const float* __restrict__ Res, float* __restrict__ C,
    u16* __restrict__ CTh, u16* __restrict__ CTl,
    int M, int K, long projStride)
{
    extern __shared__ char sm[];
    uint32_t sb = smem_u32(sm);
    int tid = threadIdx.x, wid = tid >> 5, lane = tid & 31;
    int wm = wid >> 2, wn = wid & 3;
    int proj = blockIdx.z >> 2, bc = blockIdx.z & 3, c = bc & 1;
    const u16* Ab_h = Ah + proj * projStride + (size_t)c * M * K;
    const u16* Ab_l = Al + proj * projStride + (size_t)c * M * K;
    const u16* Bb_h = Bh + (size_t)bc * 512 * K;
    const u16* Bb_l = Bl + (size_t)bc * 512 * K;
    int m0 = blockIdx.y * 64, n0 = blockIdx.x * 128;

    auto load_stage = [&](int ch, int s) {
        uint32_t st = sb + s * 49152;
        const u16* ah = Ab_h + (size_t)m0 * K + ch * 64;
        const u16* al = Ab_l + (size_t)m0 * K + ch * 64;
        for (int it = tid; it < 512; it += 256) {
            int r = it >> 3, cg = it & 7;
            uint32_t o = SWZ((uint32_t)(r * 128 + cg * 16));
            size_t gof = (size_t)r * K + cg * 8;
            cp16(st + o, ah + gof);
            cp16(st + 8192 + o, al + gof);
        }
        const u16* bh = Bb_h + (size_t)n0 * K + ch * 64;
        const u16* bl = Bb_l + (size_t)n0 * K + ch * 64;
        for (int it = tid; it < 1024; it += 256) {
            int r = it >> 3, cg = it & 7;
            uint32_t o = SWZ((uint32_t)(r * 128 + cg * 16));
            size_t gof = (size_t)r * K + cg * 8;
            cp16(st + 16384 + o, bh + gof);
            cp16(st + 32768 + o, bl + gof);
        }
    };

    float acc[2][4][4] = {};
    int NC = K >> 6;
    load_stage(0, 0); cp_commit();
    for (int ch = 0; ch < NC; ch++) {
        if (ch + 1 < NC) { load_stage(ch + 1, (ch + 1) & 1); cp_commit(); cp_wait<1>(); }
        else cp_wait<0>();
        __syncthreads();
        uint32_t st = sb + (ch & 1) * 49152;
        mma_chunk<4>(acc, st, st + 8192, st + 16384, st + 32768, wm, wn, lane);
        __syncthreads();
    }

    float* stg = (float*)sm;  // 64 x 132
    #pragma unroll
    for (int mi = 0; mi < 2; mi++)
        #pragma unroll
        for (int nt = 0; nt < 4; nt++) {
            int row = wm * 32 + mi * 16 + (lane >> 2);
            int col = wn * 32 + nt * 8 + (lane & 3) * 2;
            stg[row * 132 + col] = acc[mi][nt][0];
            stg[row * 132 + col + 1] = acc[mi][nt][1];
            stg[(row + 8) * 132 + col] = acc[mi][nt][2];
            stg[(row + 8) * 132 + col + 1] = acc[mi][nt][3];
        }
    __syncthreads();

    if (OUT == 3) {
        int j = tid >> 1, msel = tid & 1;
        u16 hb[32], lb[32];
        #pragma unroll
        for (int i = 0; i < 32; i++) {
            float v = stg[(msel * 32 + i) * 132 + j];
            float r = fmaxf(v, 0.f); v = r * r;
            splt(v, hb[i], lb[i]);
        }
        size_t o = ((size_t)bc * 512 + n0 + j) * (size_t)M + m0 + msel * 32;
        #pragma unroll
        for (int t = 0; t < 4; t++) {
            reinterpret_cast<uint4*>(CTh + o)[t] = ((uint4*)hb)[t];
            reinterpret_cast<uint4*>(CTl + o)[t] = ((uint4*)lb)[t];
        }
    } else {
        float* Cb = C + (size_t)(proj * 4 + bc) * M * 512;
        #pragma unroll
        for (int r8 = 0; r8 < 8; r8++) {
            int row = wid + r8 * 8;
            float4 v = *reinterpret_cast<float4*>(stg + row * 132 + lane * 4);
            float vv[4] = {v.x, v.y, v.z, v.w};
            if (OUT == 2) {
                float4 rv = *reinterpret_cast<const float4*>(
                    Res + (size_t)bc * M * 512 + (size_t)(m0 + row) * 512 + n0 + lane * 4);
                vv[0] += rv.x; vv[1] += rv.y; vv[2] += rv.z; vv[3] += rv.w;
            }
            float4 ov = {vv[0], vv[1], vv[2], vv[3]};
            *reinterpret_cast<float4*>(Cb + (size_t)(m0 + row) * 512 + n0 + lane * 4) = ov;
        }
    }
}

// ---------------- attention scores: S = scale * QT @ KT^T --------------------
__global__ void __launch_bounds__(256, 2) attn_qk_bb(
    const u16* __restrict__ QTh, const u16* __restrict__ QTl,
    const u16* __restrict__ KTh, const u16* __restrict__ KTl,
    float* __restrict__ S)
{
    __shared__ char sm[49152];
    uint32_t sb = smem_u32(sm);
    int tid = threadIdx.x, wid = tid >> 5, lane = tid & 31;
    int wm = wid >> 2, wn = wid & 3;
    int z = blockIdx.z, bc = z >> 3, hd = z & 7;
    int q0 = blockIdx.y * 64, k0 = blockIdx.x * 128;
    size_t qbase = ((size_t)bc * 512 + q0) * 512 + hd * 64;
    size_t kbase = ((size_t)bc * 512 + k0) * 512 + hd * 64;

    for (int it = tid; it < 512; it += 256) {
        int r = it >> 3, cg = it & 7;
        uint32_t o = SWZ((uint32_t)(r * 128 + cg * 16));
        cp16(sb + o, QTh + qbase + (size_t)r * 512 + cg * 8);
        cp16(sb + 8192 + o, QTl + qbase + (size_t)r * 512 + cg * 8);
    }
    for (int it = tid; it < 1024; it += 256) {
        int r = it >> 3, cg = it & 7;
        uint32_t o = SWZ((uint32_t)(r * 128 + cg * 16));
        cp16(sb + 16384 + o, KTh + kbase + (size_t)r * 512 + cg * 8);
        cp16(sb + 32768 + o, KTl + kbase + (size_t)r * 512 + cg * 8);
    }
    cp_commit(); cp_wait<0>();
    __syncthreads();

    float acc[2][4][4] = {};
    mma_chunk<4>(acc, sb, sb + 8192, sb + 16384, sb + 32768, wm, wn, lane);
    __syncthreads();
    float* stg = (float*)sm;
    #pragma unroll
    for (int mi = 0; mi < 2; mi++)
        #pragma unroll
        for (int nt = 0; nt < 4; nt++) {
            int row = wm * 32 + mi * 16 + (lane >> 2);
            int col = wn * 32 + nt * 8 + (lane & 3) * 2;
            stg[row * 132 + col] = acc[mi][nt][0];
            stg[row * 132 + col + 1] = acc[mi][nt][1];
            stg[(row + 8) * 132 + col] = acc[mi][nt][2];
            stg[(row + 8) * 132 + col + 1] = acc[mi][nt][3];
        }
    __syncthreads();
    const float scale = 0.044194173824159216f;  // 1/sqrt(512)
    float* Sb = S + (size_t)z * 262144;
    #pragma unroll
    for (int r8 = 0; r8 < 8; r8++) {
        int row = wid + r8 * 8;
        float4 v = *reinterpret_cast<float4*>(stg + row * 132 + lane * 4);
        float4 o = {v.x * scale, v.y * scale, v.z * scale, v.w * scale};
        *reinterpret_cast<float4*>(Sb + (size_t)(q0 + row) * 512 + k0 + lane * 4) = o;
    }
}

// ---------------- softmax: S f32 -> P bf16 hi/lo -----------------------------
__global__ void __launch_bounds__(256) softmax_split(
    const float* __restrict__ S, u16* __restrict__ Ph, u16* __restrict__ Pl)
{
    int row = blockIdx.x * 8 + (threadIdx.x >> 5);
    int lane = threadIdx.x & 31;
    const float* p = S + (size_t)row * 512 + lane * 16;
    float v[16];
    #pragma unroll
    for (int g = 0; g < 4; g++) {
        float4 x = *reinterpret_cast<const float4*>(p + g * 4);
        v[g*4] = x.x; v[g*4+1] = x.y; v[g*4+2] = x.z; v[g*4+3] = x.w;
    }
    float mx = -1e30f;
    #pragma unroll
    for (int i = 0; i < 16; i++) mx = fmaxf(mx, v[i]);
    #pragma unroll
    for (int o = 16; o; o >>= 1) mx = fmaxf(mx, __shfl_xor_sync(0xffffffffu, mx, o));
    float sum = 0.f;
    #pragma unroll
    for (int i = 0; i < 16; i++) { v[i] = __expf(v[i] - mx); sum += v[i]; }
    #pragma unroll
    for (int o = 16; o; o >>= 1) sum += __shfl_xor_sync(0xffffffffu, sum, o);
    float inv = 1.f / sum;
    u16 hb[16], lb[16];
    #pragma unroll
    for (int i = 0; i < 16; i++) splt(v[i] * inv, hb[i], lb[i]);
    size_t o = (size_t)row * 512 + lane * 16;
    reinterpret_cast<uint4*>(Ph + o)[0] = ((uint4*)hb)[0];
    reinterpret_cast<uint4*>(Ph + o)[1] = ((uint4*)hb)[1];
    reinterpret_cast<uint4*>(Pl + o)[0] = ((uint4*)lb)[0];
    reinterpret_cast<uint4*>(Pl + o)[1] = ((uint4*)lb)[1];
}

// ---------------- attention output: OT[q,d] = sum_k P[q,k] V[d,k] ------------
__global__ void __launch_bounds__(256, 2) attn_pv_bb(
    const u16* __restrict__ Ph, const u16* __restrict__ Pl,
    const u16* __restrict__ Vh, const u16* __restrict__ Vl,
    u16* __restrict__ OTh, u16* __restrict__ OTl)
{
    extern __shared__ char sm[];
    uint32_t sb = smem_u32(sm);
    int tid = threadIdx.x, wid = tid >> 5, lane = tid & 31;
    int wm = wid >> 2, wn = wid & 3;
    int z = blockIdx.z, bc = z >> 3, hd = z & 7;
    int q0 = blockIdx.x * 64;
    size_t pbase = ((size_t)z * 512 + q0) * 512;
    size_t vbase = ((size_t)bc * 512 + hd * 64) * 512;

    auto load_stage = [&](int ch, int s) {
        uint32_t st = sb + s * 32768;
        for (int it = tid; it < 512; it += 256) {
            int r = it >> 3, cg = it & 7;
            uint32_t o = SWZ((uint32_t)(r * 128 + cg * 16));
            size_t pof = pbase + (size_t)r * 512 + ch * 64 + cg * 8;
            size_t vof = vbase + (size_t)r * 512 + ch * 64 + cg * 8;
            cp16(st + o, Ph + pof);
            cp16(st + 8192 + o, Pl + pof);
            cp16(st + 16384 + o, Vh + vof);
            cp16(st + 24576 + o, Vl + vof);
        }
    };

    float acc[2][2][4] = {};
    load_stage(0, 0); cp_commit();
    for (int ch = 0; ch < 8; ch++) {
        if (ch + 1 < 8) { load_stage(ch + 1, (ch + 1) & 1); cp_commit(); cp_wait<1>(); }
        else cp_wait<0>();
        __syncthreads();
        uint32_t st = sb + (ch & 1) * 32768;
        mma_chunk<2>(acc, st, st + 8192, st + 16384, st + 24576, wm, wn, lane);
        __syncthreads();
    }
    float* stg = (float*)sm;  // 64 x 68
    #pragma unroll
    for (int mi = 0; mi < 2; mi++)
        #pragma unroll
        for (int nt = 0; nt < 2; nt++) {
            int row = wm * 32 + mi * 16 + (lane >> 2);
            int col = wn * 16 + nt * 8 + (lane & 3) * 2;
            stg[row * 68 + col] = acc[mi][nt][0];
            stg[row * 68 + col + 1] = acc[mi][nt][1];
            stg[(row + 8) * 68 + col] = acc[mi][nt][2];
            stg[(row + 8) * 68 + col + 1] = acc[mi][nt][3];
        }
    __syncthreads();
    int row = tid >> 2, dseg = tid & 3;
    u16 hb[16], lb[16];
    #pragma unroll
    for (int j = 0; j < 16; j++) splt(stg[row * 68 + dseg * 16 + j], hb[j], lb[j]);
    size_t o = ((size_t)bc * 512 + q0 + row) * 512 + hd * 64 + dseg * 16;
    reinterpret_cast<uint4*>(OTh + o)[0] = ((uint4*)hb)[0];
    reinterpret_cast<uint4*>(OTh + o)[1] = ((uint4*)hb)[1];
    reinterpret_cast<uint4*>(OTl + o)[0] = ((uint4*)lb)[0];
    reinterpret_cast<uint4*>(OTl + o)[1] = ((uint4*)lb)[1];
}

// ---------------- channel mix (enc/dec, f32) ---------------------------------
template<bool SQRELU, bool HASADD>
__global__ void __launch_bounds__(256) mix_k(
    const float* __restrict__ X, const float* __restrict__ dw,
    const float* __restrict__ Add, float* __restrict__ Y, int Fd)
{
    int idx = blockIdx.x * 256 + threadIdx.x;
    int w = idx & 511;
    int f = (idx >> 9) % Fd;
    int bd = idx / (512 * Fd);
    int b = bd >> 1, d = bd & 1;
    size_t base = ((size_t)(b * 2) * Fd + f) * 512 + w;
    float v = dw[d * 2 + 0] * X[base] + dw[d * 2 + 1] * X[base + (size_t)Fd * 512];
    if (SQRELU) { float r = fmaxf(v, 0.f); v = r * r; }
    if (HASADD) v += Add[idx];
    Y[idx] = v;
}

// ---------------- host --------------------------------------------------------
extern "C" void kernel_launch(void* const* d_in, const int* in_sizes, int n_in,
                              void* d_out, int out_size)
{
    const float* x     = (const float*)d_in[0];
    const float* e1_pw = (const float*)d_in[1];
    const float* e1_dw = (const float*)d_in[2];
    const float* e2_pw = (const float*)d_in[3];
    const float* e2_dw = (const float*)d_in[4];
    const float* ei_pw = (const float*)d_in[5];
    const float* ei_dw = (const float*)d_in[6];
    const float* n1_w  = (const float*)d_in[7];
    const float* n1_b  = (const float*)d_in[8];
    const float* q_dw  = (const float*)d_in[10];
    const float* k_dw  = (const float*)d_in[12];
    const float* v_dw  = (const float*)d_in[14];
    const float* n2_w  = (const float*)d_in[16];
    const float* n2_b  = (const float*)d_in[17];
    const float* d1_dw = (const float*)d_in[21];
    const float* d2_dw = (const float*)d_in[23];
    const float* di_dw = (const float*)d_in[25];
    float* out = (float*)d_out;
    (void)in_sizes; (void)n_in; (void)out_size;

    float *e, *q, *big, *s;
    cudaGetSymbolAddress((void**)&e, g_e);
    cudaGetSymbolAddress((void**)&q, g_q);
    cudaGetSymbolAddress((void**)&big, g_big);
    cudaGetSymbolAddress((void**)&s, g_s);
    u16 *wh, *wl, *ath, *atl, *hth, *htl, *qth, *qtl, *kth, *ktl, *vh, *vl, *ph, *pl, *oth, *otl;
    cudaGetSymbolAddress((void**)&wh, g_wh);   cudaGetSymbolAddress((void**)&wl, g_wl);
    cudaGetSymbolAddress((void**)&ath, g_ath); cudaGetSymbolAddress((void**)&atl, g_atl);
    cudaGetSymbolAddress((void**)&hth, g_hth); cudaGetSymbolAddress((void**)&htl, g_htl);
    cudaGetSymbolAddress((void**)&qth, g_qth); cudaGetSymbolAddress((void**)&qtl, g_qtl);
    cudaGetSymbolAddress((void**)&kth, g_kth); cudaGetSymbolAddress((void**)&ktl, g_ktl);
    cudaGetSymbolAddress((void**)&vh, g_vh);   cudaGetSymbolAddress((void**)&vl, g_vl);
    cudaGetSymbolAddress((void**)&ph, g_ph);   cudaGetSymbolAddress((void**)&pl, g_pl);
    cudaGetSymbolAddress((void**)&oth, g_oth); cudaGetSymbolAddress((void**)&otl, g_otl);

    const int SMG = 98304, SMPV = 65536;
    cudaFuncSetAttribute(gemm_bb<0>, cudaFuncAttributeMaxDynamicSharedMemorySize, SMG);
    cudaFuncSetAttribute(gemm_bb<2>, cudaFuncAttributeMaxDynamicSharedMemorySize, SMG);
    cudaFuncSetAttribute(gemm_bb<3>, cudaFuncAttributeMaxDynamicSharedMemorySize, SMG);
    cudaFuncSetAttribute(attn_pv_bb, cudaFuncAttributeMaxDynamicSharedMemorySize, SMPV);

    dim3 tsG512(8, 8, 4), tsG1024(8, 16, 4);

    split_w<<<20096, 256>>>(e1_pw, e2_pw, ei_pw,
        (const float*)d_in[9], (const float*)d_in[11], (const float*)d_in[13],
        (const float*)d_in[15], (const float*)d_in[18], (const float*)d_in[19],
        (const float*)d_in[20], (const float*)d_in[22], (const float*)d_in[24]);

    // encoder
    tsplit<<<tsG1024, 256>>>(x, ath, atl, 1024);
    gemm_bb<0><<<dim3(4, 8, 4), 256, SMG>>>(wh + OFF_E1, wl + OFF_E1, ath, atl, nullptr, big, nullptr, nullptr, 512, 1024, 0);
    mix_k<true, false><<<4096, 256>>>(big, e1_dw, nullptr, q, 512);
    tsplit<<<tsG512, 256>>>(q, hth, htl, 512);
    gemm_bb<0><<<dim3(4, 8, 4), 256, SMG>>>(wh + OFF_E2, wl + OFF_E2, hth, htl, nullptr, big, nullptr, nullptr, 512, 512, 0);
    mix_k<false, false><<<4096, 256>>>(big, e2_dw, nullptr, s, 512);
    gemm_bb<0><<<dim3(4, 8, 4), 256, SMG>>>(wh + OFF_EI, wl + OFF_EI, ath, atl, nullptr, big, nullptr, nullptr, 512, 1024, 0);
    mix_k<false, true><<<4096, 256>>>(big, ei_dw, s, e, 512);

    for (int i = 0; i < NLAYER; i++) {
        long lw = (long)i * 524288;
        fn_tsplit<<<dim3(8, 4), 256>>>(e, n1_w + (size_t)i * 1024, n1_b + (size_t)i * 1024, hth, htl);
        gemm_bb<0><<<dim3(4, 8, 12), 256, SMG>>>(wh + OFF_Q + lw, wl + OFF_Q + lw, hth, htl,
                                                 nullptr, big, nullptr, nullptr, 512, 512, OFF_K - OFF_Q);
        rope_tsplit<<<dim3(8, 8, 8), 256>>>(big, q_dw + i * 4, k_dw + i * 4, qth, qtl, kth, ktl);
        qkv_v<<<4096, 256>>>(big, v_dw + i * 4, vh, vl);
        attn_qk_bb<<<dim3(4, 8, 32), 256>>>(qth, qtl, kth, ktl, s);
        softmax_split<<<2048, 256>>>(s, ph, pl);
        attn_pv_bb<<<dim3(8, 1, 32), 256, SMPV>>>(ph, pl, vh, vl, oth, otl);
        gemm_bb<2><<<dim3(4, 8, 4), 256, SMG>>>(wh + OFF_O + lw, wl + OFF_O + lw, oth, otl,
                                                e, e, nullptr, nullptr, 512, 512, 0);
        fn_tsplit<<<dim3(8, 4), 256>>>(e, n2_w + (size_t)i * 1024, n2_b + (size_t)i * 1024, hth, htl);
        long lf = (long)i * 2097152;
        gemm_bb<3><<<dim3(4, 32, 4), 256, SMG>>>(wh + OFF_F1 + lf, wl + OFF_F1 + lf, hth, htl,
                                                 nullptr, nullptr, ath, atl, 2048, 512, 0);
        gemm_bb<2><<<dim3(4, 8, 4), 256, SMG>>>(wh + OFF_F2 + lf, wl + OFF_F2 + lf, ath, atl,
                                                e, e, nullptr, nullptr, 512, 2048, 0);
    }

    // decoder
    tsplit<<<tsG512, 256>>>(e, hth, htl, 512);
    gemm_bb<0><<<dim3(4, 16, 4), 256, SMG>>>(wh + OFF_D1, wl + OFF_D1, hth, htl, nullptr, big, nullptr, nullptr, 1024, 512, 0);
    mix_k<true, false><<<8192, 256>>>(big, d1_dw, nullptr, s, 1024);
    tsplit<<<tsG1024, 256>>>(s, ath, atl, 1024);
    gemm_bb<0><<<dim3(4, 16, 4), 256, SMG>>>(wh + OFF_D2, wl + OFF_D2, ath, atl, nullptr, big + 2097152, nullptr, nullptr, 1024, 1024, 0);
    mix_k<false, false><<<8192, 256>>>(big + 2097152, d2_dw, nullptr, s + 4194304, 1024);
    gemm_bb<0><<<dim3(4, 16, 4), 256, SMG>>>(wh + OFF_DI, wl + OFF_DI, hth, htl, nullptr, big, nullptr, nullptr, 1024, 512, 0);
    mix_k<false, true><<<8192, 256>>>(big, di_dw, s + 4194304, out, 1024);
}

// round 13
// speedup vs baseline: 1.7147x; 1.1271x over previous
#include <cuda_runtime.h>
#include <cuda_bf16.h>
#include <math.h>
#include <stdint.h>

#define NLAYER 12
#define EPSV 1e-5f
typedef unsigned short u16;

// ---------------- f32 scratch ------------------------------------------------
__device__ float g_e  [1048576];
__device__ float g_q  [1048576];
__device__ float g_big[4194304];
__device__ float g_s  [8388608];

// ---------------- bf16 hi/lo buffers -----------------------------------------
#define OFF_E1 0L
#define OFF_E2 1048576L
#define OFF_EI 1572864L
#define OFF_Q  2621440L
#define OFF_K  8912896L
#define OFF_V  15204352L
#define OFF_O  21495808L
#define OFF_F1 27787264L
#define OFF_F2 52953088L
#define OFF_D1 78118912L
#define OFF_D2 79167488L
#define OFF_DI 81264640L
#define W_TOT  82313216L
__device__ u16 g_wh[W_TOT];
__device__ u16 g_wl[W_TOT];
__device__ u16 g_ath[4194304], g_atl[4194304];
__device__ u16 g_hth[1048576], g_htl[1048576];
__device__ u16 g_qth[1048576], g_qtl[1048576];
__device__ u16 g_kth[1048576], g_ktl[1048576];
__device__ u16 g_vh [1048576], g_vl [1048576];
__device__ u16 g_ph [8388608], g_pl [8388608];
__device__ u16 g_oth[1048576], g_otl[1048576];

// ---------------- helpers ----------------------------------------------------
__device__ __forceinline__ uint32_t smem_u32(const void* p) {
    uint32_t a;
    asm("{ .reg .u64 t; cvta.to.shared.u64 t, %1; cvt.u32.u64 %0, t; }" : "=r"(a) : "l"(p));
    return a;
}
#define SWZ(x) ((x) ^ (((x) >> 3) & 0x70))

__device__ __forceinline__ void cp16(uint32_t d, const void* g) {
    asm volatile("cp.async.cg.shared.global [%0], [%1], 16;" :: "r"(d), "l"(g));
}
__device__ __forceinline__ void cp_commit() { asm volatile("cp.async.commit_group;"); }
template<int N> __device__ __forceinline__ void cp_wait() {
    asm volatile("cp.async.wait_group %0;" :: "n"(N));
}
__device__ __forceinline__ void ldsm4(uint32_t* r, uint32_t a) {
    asm volatile("ldmatrix.sync.aligned.m8n8.x4.shared.b16 {%0,%1,%2,%3}, [%4];"
                 : "=r"(r[0]), "=r"(r[1]), "=r"(r[2]), "=r"(r[3]) : "r"(a));
}
__device__ __forceinline__ void mma16816(float* c, const uint32_t* a, const uint32_t* b) {
    asm volatile(
        "mma.sync.aligned.m16n8k16.row.col.f32.bf16.bf16.f32 "
        "{%0,%1,%2,%3}, {%4,%5,%6,%7}, {%8,%9}, {%0,%1,%2,%3};"
        : "+f"(c[0]), "+f"(c[1]), "+f"(c[2]), "+f"(c[3])
        : "r"(a[0]), "r"(a[1]), "r"(a[2]), "r"(a[3]), "r"(b[0]), "r"(b[1]));
}
__device__ __forceinline__ void splt(float v, u16& h, u16& l) {
    __nv_bfloat16 hb = __float2bfloat16(v);
    h = __bfloat16_as_ushort(hb);
    l = __bfloat16_as_ushort(__float2bfloat16(v - __bfloat162float(hb)));
}

// warp computes 32m x (NT*8)n over one K-chunk of 64, 3-term split (verified)
template<int NT>
__device__ __forceinline__ void mma_chunk(
    float (&acc)[2][NT][4], uint32_t aHi, uint32_t aLo, uint32_t bHi, uint32_t bLo,
    int wm, int wn, int lane)
{
    int la = lane & 7, j = lane >> 3;
    #pragma unroll
    for (int ks = 0; ks < 4; ks++) {
        uint32_t ah[2][4], al[2][4];
        #pragma unroll
        for (int mi = 0; mi < 2; mi++) {
            uint32_t off = SWZ((uint32_t)((wm * 32 + mi * 16 + ((j & 1) << 3) + la) * 128 + ks * 32 + ((j >> 1) << 4)));
            ldsm4(ah[mi], aHi + off);
            ldsm4(al[mi], aLo + off);
        }
        uint32_t bh[NT][2], bl[NT][2];
        #pragma unroll
        for (int nt = 0; nt < NT; nt += 2) {
            uint32_t off = SWZ((uint32_t)((wn * NT * 8 + nt * 8 + ((j >> 1) << 3) + la) * 128 + ks * 32 + ((j & 1) << 4)));
            uint32_t t[4];
            ldsm4(t, bHi + off);
            bh[nt][0] = t[0]; bh[nt][1] = t[1]; bh[nt + 1][0] = t[2]; bh[nt + 1][1] = t[3];
            ldsm4(t, bLo + off);
            bl[nt][0] = t[0]; bl[nt][1] = t[1]; bl[nt + 1][0] = t[2]; bl[nt + 1][1] = t[3];
        }
        #pragma unroll
        for (int mi = 0; mi < 2; mi++)
            #pragma unroll
            for (int nt = 0; nt < NT; nt++) {
                mma16816(acc[mi][nt], ah[mi], bh[nt]);
                mma16816(acc[mi][nt], ah[mi], bl[nt]);
                mma16816(acc[mi][nt], al[mi], bh[nt]);
            }
    }
}

// ---------------- one-time weight split --------------------------------------
__global__ void __launch_bounds__(256) split_w(
    const float* p0, const float* p1, const float* p2, const float* p3,
    const float* p4, const float* p5, const float* p6, const float* p7,
    const float* p8, const float* p9, const float* p10, const float* p11)
{
    const long offs[12] = {OFF_E1, OFF_E2, OFF_EI, OFF_Q, OFF_K, OFF_V,
                           OFF_O, OFF_F1, OFF_F2, OFF_D1, OFF_D2, OFF_DI};
    const float* ptrs[12] = {p0, p1, p2, p3, p4, p5, p6, p7, p8, p9, p10, p11};
    long base = ((long)blockIdx.x * 256 + threadIdx.x) * 16;
    if (base >= W_TOT) return;
    int seg = 0;
    #pragma unroll
    for (int i = 1; i < 12; i++) if (base >= offs[i]) seg = i;
    const float* src = ptrs[seg] + (base - offs[seg]);
    u16 hb[16], lb[16];
    #pragma unroll
    for (int t = 0; t < 16; t += 4) {
        float4 x = *reinterpret_cast<const float4*>(src + t);
        splt(x.x, hb[t], lb[t]); splt(x.y, hb[t+1], lb[t+1]);
        splt(x.z, hb[t+2], lb[t+2]); splt(x.w, hb[t+3], lb[t+3]);
    }
    uint4* dh = reinterpret_cast<uint4*>(&g_wh[base]);
    uint4* dl = reinterpret_cast<uint4*>(&g_wl[base]);
    dh[0] = ((uint4*)hb)[0]; dh[1] = ((uint4*)hb)[1];
    dl[0] = ((uint4*)lb)[0]; dl[1] = ((uint4*)lb)[1];
}

// ---------------- transpose-split (plain) ------------------------------------
__global__ void __launch_bounds__(256) tsplit(
    const float* __restrict__ X, u16* __restrict__ Th, u16* __restrict__ Tl, int R)
{
    __shared__ float s[64][65];
    int tid = threadIdx.x;
    int z = blockIdx.z, f0 = blockIdx.y * 64, w0 = blockIdx.x * 64;
    const float* Xb = X + ((size_t)z * R + f0) * 512 + w0;
    for (int it = tid; it < 1024; it += 256) {
        int r = it >> 4, cg = it & 15;
        float4 v = *reinterpret_cast<const float4*>(Xb + (size_t)r * 512 + cg * 4);
        s[r][cg * 4 + 0] = v.x; s[r][cg * 4 + 1] = v.y;
        s[r][cg * 4 + 2] = v.z; s[r][cg * 4 + 3] = v.w;
    }
    __syncthreads();
    for (int it = tid; it < 512; it += 256) {
        int w = it >> 3, cg = it & 7;
        u16 hb[8], lb[8];
        #pragma unroll
        for (int j = 0; j < 8; j++) splt(s[cg * 8 + j][w], hb[j], lb[j]);
        size_t o = ((size_t)z * 512 + w0 + w) * R + f0 + cg * 8;
        *reinterpret_cast<uint4*>(Th + o) = *reinterpret_cast<uint4*>(hb);
        *reinterpret_cast<uint4*>(Tl + o) = *reinterpret_cast<uint4*>(lb);
    }
}

// ---------------- frame_norm fused with transpose-split (256 blocks) ---------
__global__ void __launch_bounds__(256) fn_tsplit(
    const float* __restrict__ X, const float* __restrict__ gw, const float* __restrict__ gb,
    u16* __restrict__ Th, u16* __restrict__ Tl)
{
    int tid = threadIdx.x;
    int bc = blockIdx.z, c = bc & 1;
    int w0 = blockIdx.x * 64;
    int ft = blockIdx.y;                       // f-tile 0..7
    const float* Xb = X + (size_t)bc * 262144;

    // stats over full F for this block's 64 w-columns (recomputed per f-tile)
    int wl = tid & 63, part = tid >> 6;
    float sum = 0.f, sq = 0.f;
    for (int f = part; f < 512; f += 4) {
        float v = Xb[(size_t)f * 512 + w0 + wl];
        sum += v; sq += v * v;
    }
    __shared__ float r1[4][64], r2[4][64];
    __shared__ float smu[64], srs[64];
    r1[part][wl] = sum; r2[part][wl] = sq;
    __syncthreads();
    if (tid < 64) {
        float s = r1[0][tid] + r1[1][tid] + r1[2][tid] + r1[3][tid];
        float q = r2[0][tid] + r2[1][tid] + r2[2][tid] + r2[3][tid];
        float mu = s * (1.f / 512.f);
        float var = q * (1.f / 512.f) - mu * mu;
        smu[tid] = mu; srs[tid] = rsqrtf(var + EPSV);
    }
    __syncthreads();

    __shared__ float tile[64][65];
    for (int it = tid; it < 1024; it += 256) {
        int r = it >> 4, cg = it & 15;
        float4 v = *reinterpret_cast<const float4*>(Xb + (size_t)(ft * 64 + r) * 512 + w0 + cg * 4);
        tile[r][cg * 4 + 0] = v.x; tile[r][cg * 4 + 1] = v.y;
        tile[r][cg * 4 + 2] = v.z; tile[r][cg * 4 + 3] = v.w;
    }
    __syncthreads();
    int w = tid >> 2, seg = tid & 3;
    float mu = smu[w], rs = srs[w];
    u16 hb[16], lb[16];
    #pragma unroll
    for (int j = 0; j < 16; j++) {
        int f = seg * 16 + j, fg = ft * 64 + f;
        float v = (tile[f][w] - mu) * rs * gw[c * 512 + fg] + gb[c * 512 + fg];
        splt(v, hb[j], lb[j]);
    }
    size_t o = ((size_t)bc * 512 + w0 + w) * 512 + ft * 64 + seg * 16;
    reinterpret_cast<uint4*>(Th + o)[0] = ((uint4*)hb)[0];
    reinterpret_cast<uint4*>(Th + o)[1] = ((uint4*)hb)[1];
    reinterpret_cast<uint4*>(Tl + o)[0] = ((uint4*)lb)[0];
    reinterpret_cast<uint4*>(Tl + o)[1] = ((uint4*)lb)[1];
}

// ---------------- channel-mix + RoPE + transpose-split (Q,K) -----------------
__global__ void __launch_bounds__(256) rope_tsplit(
    const float* __restrict__ big, const float* __restrict__ qdw, const float* __restrict__ kdw,
    u16* __restrict__ Qh, u16* __restrict__ Ql, u16* __restrict__ Kh, u16* __restrict__ Kl)
{
    __shared__ float tile[64][65];
    int tid = threadIdx.x;
    int zz = blockIdx.z;
    int proj = zz >> 2, bd = zz & 3;
    int b = bd >> 1, d = bd & 1;
    int f0 = blockIdx.y * 64, w0 = blockIdx.x * 64;
    const float* dw = proj ? kdw : qdw;
    float d0 = dw[d * 2 + 0], d1 = dw[d * 2 + 1];
    const float* X0 = big + ((size_t)(proj * 4 + b * 2) * 512 + f0) * 512 + w0;
    const float* X1 = X0 + 262144;
    for (int it = tid; it < 1024; it += 256) {
        int r = it >> 4, cg = it & 15;
        float4 a = *reinterpret_cast<const float4*>(X0 + (size_t)r * 512 + cg * 4);
        float4 bb = *reinterpret_cast<const float4*>(X1 + (size_t)r * 512 + cg * 4);
        tile[r][cg * 4 + 0] = d0 * a.x + d1 * bb.x;
        tile[r][cg * 4 + 1] = d0 * a.y + d1 * bb.y;
        tile[r][cg * 4 + 2] = d0 * a.z + d1 * bb.z;
        tile[r][cg * 4 + 3] = d0 * a.w + d1 * bb.w;
    }
    __syncthreads();
    int w = tid >> 2, seg = tid & 3;
    int wg = w0 + w;
    u16 hb[16], lb[16];
    #pragma unroll
    for (int j2 = 0; j2 < 8; j2++) {
        int fe = seg * 16 + j2 * 2, fg = f0 + fe;
        int i = (fg & 63) >> 1;
        float inv = powf(10000.f, -(float)(2 * i) / 64.f);
        float sn, cs;
        sincosf((float)wg * inv, &sn, &cs);
        float v0 = tile[fe][w], v1 = tile[fe + 1][w];
        splt(v0 * cs - v1 * sn, hb[j2 * 2], lb[j2 * 2]);
        splt(v1 * cs + v0 * sn, hb[j2 * 2 + 1], lb[j2 * 2 + 1]);
    }
    u16* Th = proj ? Kh : Qh;
    u16* Tl = proj ? Kl : Ql;
    size_t o = ((size_t)bd * 512 + wg) * 512 + f0 + seg * 16;
    reinterpret_cast<uint4*>(Th + o)[0] = ((uint4*)hb)[0];
    reinterpret_cast<uint4*>(Th + o)[1] = ((uint4*)hb)[1];
    reinterpret_cast<uint4*>(Tl + o)[0] = ((uint4*)lb)[0];
    reinterpret_cast<uint4*>(Tl + o)[1] = ((uint4*)lb)[1];
}

// ---------------- V channel-mix -> bf16 hi/lo natural ------------------------
__global__ void __launch_bounds__(256) qkv_v(
    const float* __restrict__ big, const float* __restrict__ vdw,
    u16* __restrict__ Vh, u16* __restrict__ Vl)
{
    int idx = blockIdx.x * 256 + threadIdx.x;
    int w = idx & 511, f = (idx >> 9) & 511, bd = idx >> 18;
    int b = bd >> 1, d = bd & 1;
    size_t base = ((size_t)(8 + b * 2) * 512 + f) * 512 + w;
    float v = vdw[d * 2 + 0] * big[base] + vdw[d * 2 + 1] * big[base + 262144];
    u16 h, l;
    splt(v, h, l);
    size_t o = ((size_t)bd * 512 + f) * 512 + w;
    Vh[o] = h; Vl[o] = l;
}

// ---------------- pipelined bf16 GEMM, templated tile-N ----------------------
// OUT: 0 f32 ; 2 f32+res ; 3 sqrelu -> bf16T (NT=4 only)
template<int OUT, int NT>
__global__ void __launch_bounds__(256, 2) gemm_bb(
    const u16* __restrict__ Ah, const u16* __restrict__ Al,
    const u16* __restrict__ Bh, const u16* __restrict__ Bl,
    const float* __restrict__ Res, float* __restrict__ C,
    u16* __restrict__ CTh, u16* __restrict__ CTl,
    int M, int K, long projStride)
{
    constexpr int BN = NT * 32;             // 128 or 64
    constexpr int BSZ = BN * 128;           // bytes per B half per stage
    constexpr int STG = 16384 + 2 * BSZ;    // stage stride
    extern __shared__ char sm[];
    uint32_t sb = smem_u32(sm);
    int tid = threadIdx.x, wid = tid >> 5, lane = tid & 31;
    int wm = wid >> 2, wn = wid & 3;
    int proj = blockIdx.z >> 2, bc = blockIdx.z & 3, c = bc & 1;
    const u16* Ab_h = Ah + proj * projStride + (size_t)c * M * K;
    const u16* Ab_l = Al + proj * projStride + (size_t)c * M * K;
    const u16* Bb_h = Bh + (size_t)bc * 512 * K;
    const u16* Bb_l = Bl + (size_t)bc * 512 * K;
    int m0 = blockIdx.y * 64, n0 = blockIdx.x * BN;

    auto load_stage = [&](int ch, int s) {
        uint32_t st = sb + s * STG;
        const u16* ah = Ab_h + (size_t)m0 * K + ch * 64;
        const u16* al = Ab_l + (size_t)m0 * K + ch * 64;
        for (int it = tid; it < 512; it += 256) {
            int r = it >> 3, cg = it & 7;
            uint32_t o = SWZ((uint32_t)(r * 128 + cg * 16));
            size_t gof = (size_t)r * K + cg * 8;
            cp16(st + o, ah + gof);
            cp16(st + 8192 + o, al + gof);
        }
        const u16* bh = Bb_h + (size_t)n0 * K + ch * 64;
        const u16* bl = Bb_l + (size_t)n0 * K + ch * 64;
        for (int it = tid; it < BN * 8; it += 256) {
            int r = it >> 3, cg = it & 7;
            uint32_t o = SWZ((uint32_t)(r * 128 + cg * 16));
            size_t gof = (size_t)r * K + cg * 8;
            cp16(st + 16384 + o, bh + gof);
            cp16(st + 16384 + BSZ + o, bl + gof);
        }
    };

    float acc[2][NT][4] = {};
    int NC = K >> 6;
    load_stage(0, 0); cp_commit();
    for (int ch = 0; ch < NC; ch++) {
        if (ch + 1 < NC) { load_stage(ch + 1, (ch + 1) & 1); cp_commit(); cp_wait<1>(); }
        else cp_wait<0>();
        __syncthreads();
        uint32_t st = sb + (ch & 1) * STG;
        mma_chunk<NT>(acc, st, st + 8192, st + 16384, st + 16384 + BSZ, wm, wn, lane);
        __syncthreads();
    }

    float* stg = (float*)sm;  // 64 x (BN+4)
    #pragma unroll
    for (int mi = 0; mi < 2; mi++)
        #pragma unroll
        for (int nt = 0; nt < NT; nt++) {
            int row = wm * 32 + mi * 16 + (lane >> 2);
            int col = wn * NT * 8 + nt * 8 + (lane & 3) * 2;
            stg[row * (BN + 4) + col] = acc[mi][nt][0];
            stg[row * (BN + 4) + col + 1] = acc[mi][nt][1];
            stg[(row + 8) * (BN + 4) + col] = acc[mi][nt][2];
            stg[(row + 8) * (BN + 4) + col + 1] = acc[mi][nt][3];
        }
    __syncthreads();

    if (OUT == 3) {
        // NT == 4 only (BN = 128)
        int j = tid >> 1, msel = tid & 1;
        u16 hb[32], lb[32];
        #pragma unroll
        for (int i = 0; i < 32; i++) {
            float v = stg[(msel * 32 + i) * (BN + 4) + j];
            float r = fmaxf(v, 0.f); v = r * r;
            splt(v, hb[i], lb[i]);
        }
        size_t o = ((size_t)bc * 512 + n0 + j) * (size_t)M + m0 + msel * 32;
        #pragma unroll
        for (int t = 0; t < 4; t++) {
            reinterpret_cast<uint4*>(CTh + o)[t] = ((uint4*)hb)[t];
            reinterpret_cast<uint4*>(CTl + o)[t] = ((uint4*)lb)[t];
        }
    } else {
        float* Cb = C + (size_t)(proj * 4 + bc) * M * 512;
        constexpr int CPR = BN / 4;         // float4 per row
        #pragma unroll
        for (int it = 0; it < 64 * CPR / 256; it++) {
            int idx = it * 256 + tid;
            int row = idx / CPR, c4 = idx % CPR;
            float4 v = *reinterpret_cast<float4*>(stg + row * (BN + 4) + c4 * 4);
            float vv[4] = {v.x, v.y, v.z, v.w};
            if (OUT == 2) {
                float4 rv = *reinterpret_cast<const float4*>(
                    Res + (size_t)bc * M * 512 + (size_t)(m0 + row) * 512 + n0 + c4 * 4);
                vv[0] += rv.x; vv[1] += rv.y; vv[2] += rv.z; vv[3] += rv.w;
            }
            float4 ov = {vv[0], vv[1], vv[2], vv[3]};
            *reinterpret_cast<float4*>(Cb + (size_t)(m0 + row) * 512 + n0 + c4 * 4) = ov;
        }
    }
}

// ---------------- attention scores: S = scale * QT @ KT^T --------------------
__global__ void __launch_bounds__(256, 2) attn_qk_bb(
    const u16* __restrict__ QTh, const u16* __restrict__ QTl,
    const u16* __restrict__ KTh, const u16* __restrict__ KTl,
    float* __restrict__ S)
{
    __shared__ char sm[49152];
    uint32_t sb = smem_u32(sm);
    int tid = threadIdx.x, wid = tid >> 5, lane = tid & 31;
    int wm = wid >> 2, wn = wid & 3;
    int z = blockIdx.z, bc = z >> 3, hd = z & 7;
    int q0 = blockIdx.y * 64, k0 = blockIdx.x * 128;
    size_t qbase = ((size_t)bc * 512 + q0) * 512 + hd * 64;
    size_t kbase = ((size_t)bc * 512 + k0) * 512 + hd * 64;

    for (int it = tid; it < 512; it += 256) {
        int r = it >> 3, cg = it & 7;
        uint32_t o = SWZ((uint32_t)(r * 128 + cg * 16));
        cp16(sb + o, QTh + qbase + (size_t)r * 512 + cg * 8);
        cp16(sb + 8192 + o, QTl + qbase + (size_t)r * 512 + cg * 8);
    }
    for (int it = tid; it < 1024; it += 256) {
        int r = it >> 3, cg = it & 7;
        uint32_t o = SWZ((uint32_t)(r * 128 + cg * 16));
        cp16(sb + 16384 + o, KTh + kbase + (size_t)r * 512 + cg * 8);
        cp16(sb + 32768 + o, KTl + kbase + (size_t)r * 512 + cg * 8);
    }
    cp_commit(); cp_wait<0>();
    __syncthreads();

    float acc[2][4][4] = {};
    mma_chunk<4>(acc, sb, sb + 8192, sb + 16384, sb + 32768, wm, wn, lane);
    __syncthreads();
    float* stg = (float*)sm;
    #pragma unroll
    for (int mi = 0; mi < 2; mi++)
        #pragma unroll
        for (int nt = 0; nt < 4; nt++) {
            int row = wm * 32 + mi * 16 + (lane >> 2);
            int col = wn * 32 + nt * 8 + (lane & 3) * 2;
            stg[row * 132 + col] = acc[mi][nt][0];
            stg[row * 132 + col + 1] = acc[mi][nt][1];
            stg[(row + 8) * 132 + col] = acc[mi][nt][2];
            stg[(row + 8) * 132 + col + 1] = acc[mi][nt][3];
        }
    __syncthreads();
    const float scale = 0.044194173824159216f;  // 1/sqrt(512)
    float* Sb = S + (size_t)z * 262144;
    #pragma unroll
    for (int r8 = 0; r8 < 8; r8++) {
        int row = wid + r8 * 8;
        float4 v = *reinterpret_cast<float4*>(stg + row * 132 + lane * 4);
        float4 o = {v.x * scale, v.y * scale, v.z * scale, v.w * scale};
        *reinterpret_cast<float4*>(Sb + (size_t)(q0 + row) * 512 + k0 + lane * 4) = o;
    }
}

// ---------------- softmax: S f32 -> P bf16 hi/lo -----------------------------
__global__ void __launch_bounds__(256) softmax_split(
    const float* __restrict__ S, u16* __restrict__ Ph, u16* __restrict__ Pl)
{
    int row = blockIdx.x * 8 + (threadIdx.x >> 5);
    int lane = threadIdx.x & 31;
    const float* p = S + (size_t)row * 512 + lane * 16;
    float v[16];
    #pragma unroll
    for (int g = 0; g < 4; g++) {
        float4 x = *reinterpret_cast<const float4*>(p + g * 4);
        v[g*4] = x.x; v[g*4+1] = x.y; v[g*4+2] = x.z; v[g*4+3] = x.w;
    }
    float mx = -1e30f;
    #pragma unroll
    for (int i = 0; i < 16; i++) mx = fmaxf(mx, v[i]);
    #pragma unroll
    for (int o = 16; o; o >>= 1) mx = fmaxf(mx, __shfl_xor_sync(0xffffffffu, mx, o));
    float sum = 0.f;
    #pragma unroll
    for (int i = 0; i < 16; i++) { v[i] = __expf(v[i] - mx); sum += v[i]; }
    #pragma unroll
    for (int o = 16; o; o >>= 1) sum += __shfl_xor_sync(0xffffffffu, sum, o);
    float inv = 1.f / sum;
    u16 hb[16], lb[16];
    #pragma unroll
    for (int i = 0; i < 16; i++) splt(v[i] * inv, hb[i], lb[i]);
    size_t o = (size_t)row * 512 + lane * 16;
    reinterpret_cast<uint4*>(Ph + o)[0] = ((uint4*)hb)[0];
    reinterpret_cast<uint4*>(Ph + o)[1] = ((uint4*)hb)[1];
    reinterpret_cast<uint4*>(Pl + o)[0] = ((uint4*)lb)[0];
    reinterpret_cast<uint4*>(Pl + o)[1] = ((uint4*)lb)[1];
}

// ---------------- attention output: OT[q,d] = sum_k P[q,k] V[d,k] ------------
__global__ void __launch_bounds__(256, 2) attn_pv_bb(
    const u16* __restrict__ Ph, const u16* __restrict__ Pl,
    const u16* __restrict__ Vh, const u16* __restrict__ Vl,
    u16* __restrict__ OTh, u16* __restrict__ OTl)
{
    extern __shared__ char sm[];
    uint32_t sb = smem_u32(sm);
    int tid = threadIdx.x, wid = tid >> 5, lane = tid & 31;
    int wm = wid >> 2, wn = wid & 3;
    int z = blockIdx.z, bc = z >> 3, hd = z & 7;
    int q0 = blockIdx.x * 64;
    size_t pbase = ((size_t)z * 512 + q0) * 512;
    size_t vbase = ((size_t)bc * 512 + hd * 64) * 512;

    auto load_stage = [&](int ch, int s) {
        uint32_t st = sb + s * 32768;
        for (int it = tid; it < 512; it += 256) {
            int r = it >> 3, cg = it & 7;
            uint32_t o = SWZ((uint32_t)(r * 128 + cg * 16));
            size_t pof = pbase + (size_t)r * 512 + ch * 64 + cg * 8;
            size_t vof = vbase + (size_t)r * 512 + ch * 64 + cg * 8;
            cp16(st + o, Ph + pof);
            cp16(st + 8192 + o, Pl + pof);
            cp16(st + 16384 + o, Vh + vof);
            cp16(st + 24576 + o, Vl + vof);
        }
    };

    float acc[2][2][4] = {};
    load_stage(0, 0); cp_commit();
    for (int ch = 0; ch < 8; ch++) {
        if (ch + 1 < 8) { load_stage(ch + 1, (ch + 1) & 1); cp_commit(); cp_wait<1>(); }
        else cp_wait<0>();
        __syncthreads();
        uint32_t st = sb + (ch & 1) * 32768;
        mma_chunk<2>(acc, st, st + 8192, st + 16384, st + 24576, wm, wn, lane);
        __syncthreads();
    }
    float* stg = (float*)sm;  // 64 x 68
    #pragma unroll
    for (int mi = 0; mi < 2; mi++)
        #pragma unroll
        for (int nt = 0; nt < 2; nt++) {
            int row = wm * 32 + mi * 16 + (lane >> 2);
            int col = wn * 16 + nt * 8 + (lane & 3) * 2;
            stg[row * 68 + col] = acc[mi][nt][0];
            stg[row * 68 + col + 1] = acc[mi][nt][1];
            stg[(row + 8) * 68 + col] = acc[mi][nt][2];
            stg[(row + 8) * 68 + col + 1] = acc[mi][nt][3];
        }
    __syncthreads();
    int row = tid >> 2, dseg = tid & 3;
    u16 hb[16], lb[16];
    #pragma unroll
    for (int j = 0; j < 16; j++) splt(stg[row * 68 + dseg * 16 + j], hb[j], lb[j]);
    size_t o = ((size_t)bc * 512 + q0 + row) * 512 + hd * 64 + dseg * 16;
    reinterpret_cast<uint4*>(OTh + o)[0] = ((uint4*)hb)[0];
    reinterpret_cast<uint4*>(OTh + o)[1] = ((uint4*)hb)[1];
    reinterpret_cast<uint4*>(OTl + o)[0] = ((uint4*)lb)[0];
    reinterpret_cast<uint4*>(OTl + o)[1] = ((uint4*)lb)[1];
}

// ---------------- channel mix (enc/dec, f32) ---------------------------------
template<bool SQRELU, bool HASADD>
__global__ void __launch_bounds__(256) mix_k(
    const float* __restrict__ X, const float* __restrict__ dw,
    const float* __restrict__ Add, float* __restrict__ Y, int Fd)
{
    int idx = blockIdx.x * 256 + threadIdx.x;
    int w = idx & 511;
    int f = (idx >> 9) % Fd;
    int bd = idx / (512 * Fd);
    int b = bd >> 1, d = bd & 1;
    size_t base = ((size_t)(b * 2) * Fd + f) * 512 + w;
    float v = dw[d * 2 + 0] * X[base] + dw[d * 2 + 1] * X[base + (size_t)Fd * 512];
    if (SQRELU) { float r = fmaxf(v, 0.f); v = r * r; }
    if (HASADD) v += Add[idx];
    Y[idx] = v;
}

// ---------------- host --------------------------------------------------------
extern "C" void kernel_launch(void* const* d_in, const int* in_sizes, int n_in,
                              void* d_out, int out_size)
{
    const float* x     = (const float*)d_in[0];
    const float* e1_pw = (const float*)d_in[1];
    const float* e1_dw = (const float*)d_in[2];
    const float* e2_pw = (const float*)d_in[3];
    const float* e2_dw = (const float*)d_in[4];
    const float* ei_pw = (const float*)d_in[5];
    const float* ei_dw = (const float*)d_in[6];
    const float* n1_w  = (const float*)d_in[7];
    const float* n1_b  = (const float*)d_in[8];
    const float* q_dw  = (const float*)d_in[10];
    const float* k_dw  = (const float*)d_in[12];
    const float* v_dw  = (const float*)d_in[14];
    const float* n2_w  = (const float*)d_in[16];
    const float* n2_b  = (const float*)d_in[17];
    const float* d1_dw = (const float*)d_in[21];
    const float* d2_dw = (const float*)d_in[23];
    const float* di_dw = (const float*)d_in[25];
    float* out = (float*)d_out;
    (void)in_sizes; (void)n_in; (void)out_size;

    float *e, *q, *big, *s;
    cudaGetSymbolAddress((void**)&e, g_e);
    cudaGetSymbolAddress((void**)&q, g_q);
    cudaGetSymbolAddress((void**)&big, g_big);
    cudaGetSymbolAddress((void**)&s, g_s);
    u16 *wh, *wl, *ath, *atl, *hth, *htl, *qth, *qtl, *kth, *ktl, *vh, *vl, *ph, *pl, *oth, *otl;
    cudaGetSymbolAddress((void**)&wh, g_wh);   cudaGetSymbolAddress((void**)&wl, g_wl);
    cudaGetSymbolAddress((void**)&ath, g_ath); cudaGetSymbolAddress((void**)&atl, g_atl);
    cudaGetSymbolAddress((void**)&hth, g_hth); cudaGetSymbolAddress((void**)&htl, g_htl);
    cudaGetSymbolAddress((void**)&qth, g_qth); cudaGetSymbolAddress((void**)&qtl, g_qtl);
    cudaGetSymbolAddress((void**)&kth, g_kth); cudaGetSymbolAddress((void**)&ktl, g_ktl);
    cudaGetSymbolAddress((void**)&vh, g_vh);   cudaGetSymbolAddress((void**)&vl, g_vl);
    cudaGetSymbolAddress((void**)&ph, g_ph);   cudaGetSymbolAddress((void**)&pl, g_pl);
    cudaGetSymbolAddress((void**)&oth, g_oth); cudaGetSymbolAddress((void**)&otl, g_otl);

    const int SMG4 = 98304, SMG2 = 65536, SMPV = 65536;
    cudaFuncSetAttribute(gemm_bb<0,4>, cudaFuncAttributeMaxDynamicSharedMemorySize, SMG4);
    cudaFuncSetAttribute(gemm_bb<3,4>, cudaFuncAttributeMaxDynamicSharedMemorySize, SMG4);
    cudaFuncSetAttribute(gemm_bb<0,2>, cudaFuncAttributeMaxDynamicSharedMemorySize, SMG2);
    cudaFuncSetAttribute(gemm_bb<2,2>, cudaFuncAttributeMaxDynamicSharedMemorySize, SMG2);
    cudaFuncSetAttribute(attn_pv_bb, cudaFuncAttributeMaxDynamicSharedMemorySize, SMPV);

    dim3 tsG512(8, 8, 4), tsG1024(8, 16, 4);

    split_w<<<20096, 256>>>(e1_pw, e2_pw, ei_pw,
        (const float*)d_in[9], (const float*)d_in[11], (const float*)d_in[13],
        (const float*)d_in[15], (const float*)d_in[18], (const float*)d_in[19],
        (const float*)d_in[20], (const float*)d_in[22], (const float*)d_in[24]);

    // encoder (BN=64 tiles: 256 blocks per launch)
    tsplit<<<tsG1024, 256>>>(x, ath, atl, 1024);
    gemm_bb<0,2><<<dim3(8, 8, 4), 256, SMG2>>>(wh + OFF_E1, wl + OFF_E1, ath, atl, nullptr, big, nullptr, nullptr, 512, 1024, 0);
    mix_k<true, false><<<4096, 256>>>(big, e1_dw, nullptr, q, 512);
    tsplit<<<tsG512, 256>>>(q, hth, htl, 512);
    gemm_bb<0,2><<<dim3(8, 8, 4), 256, SMG2>>>(wh + OFF_E2, wl + OFF_E2, hth, htl, nullptr, big, nullptr, nullptr, 512, 512, 0);
    mix_k<false, false><<<4096, 256>>>(big, e2_dw, nullptr, s, 512);
    gemm_bb<0,2><<<dim3(8, 8, 4), 256, SMG2>>>(wh + OFF_EI, wl + OFF_EI, ath, atl, nullptr, big, nullptr, nullptr, 512, 1024, 0);
    mix_k<false, true><<<4096, 256>>>(big, ei_dw, s, e, 512);

    for (int i = 0; i < NLAYER; i++) {
        long lw = (long)i * 524288;
        fn_tsplit<<<dim3(8, 8, 4), 256>>>(e, n1_w + (size_t)i * 1024, n1_b + (size_t)i * 1024, hth, htl);
        gemm_bb<0,4><<<dim3(4, 8, 12), 256, SMG4>>>(wh + OFF_Q + lw, wl + OFF_Q + lw, hth, htl,
                                                    nullptr, big, nullptr, nullptr, 512, 512, OFF_K - OFF_Q);
        rope_tsplit<<<dim3(8, 8, 8), 256>>>(big, q_dw + i * 4, k_dw + i * 4, qth, qtl, kth, ktl);
        qkv_v<<<4096, 256>>>(big, v_dw + i * 4, vh, vl);
        attn_qk_bb<<<dim3(4, 8, 32), 256>>>(qth, qtl, kth, ktl, s);
        softmax_split<<<2048, 256>>>(s, ph, pl);
        attn_pv_bb<<<dim3(8, 1, 32), 256, SMPV>>>(ph, pl, vh, vl, oth, otl);
        gemm_bb<2,2><<<dim3(8, 8, 4), 256, SMG2>>>(wh + OFF_O + lw, wl + OFF_O + lw, oth, otl,
                                                   e, e, nullptr, nullptr, 512, 512, 0);
        fn_tsplit<<<dim3(8, 8, 4), 256>>>(e, n2_w + (size_t)i * 1024, n2_b + (size_t)i * 1024, hth, htl);
        long lf = (long)i * 2097152;
        gemm_bb<3,4><<<dim3(4, 32, 4), 256, SMG4>>>(wh + OFF_F1 + lf, wl + OFF_F1 + lf, hth, htl,
                                                    nullptr, nullptr, ath, atl, 2048, 512, 0);
        gemm_bb<2,2><<<dim3(8, 8, 4), 256, SMG2>>>(wh + OFF_F2 + lf, wl + OFF_F2 + lf, ath, atl,
                                                   e, e, nullptr, nullptr, 512, 2048, 0);
    }

    // decoder (BN=64: 512 blocks per launch)
    tsplit<<<tsG512, 256>>>(e, hth, htl, 512);
    gemm_bb<0,2><<<dim3(8, 16, 4), 256, SMG2>>>(wh + OFF_D1, wl + OFF_D1, hth, htl, nullptr, big, nullptr, nullptr, 1024, 512, 0);
    mix_k<true, false><<<8192, 256>>>(big, d1_dw, nullptr, s, 1024);
    tsplit<<<tsG1024, 256>>>(s, ath, atl, 1024);
    gemm_bb<0,2><<<dim3(8, 16, 4), 256, SMG2>>>(wh + OFF_D2, wl + OFF_D2, ath, atl, nullptr, big + 2097152, nullptr, nullptr, 1024, 1024, 0);
    mix_k<false, false><<<8192, 256>>>(big + 2097152, d2_dw, nullptr, s + 4194304, 1024);
    gemm_bb<0,2><<<dim3(8, 16, 4), 256, SMG2>>>(wh + OFF_DI, wl + OFF_DI, hth, htl, nullptr, big, nullptr, nullptr, 1024, 512, 0);
    mix_k<false, true><<<8192, 256>>>(big, di_dw, s + 4194304, out, 1024);
}

// round 14
// speedup vs baseline: 1.9784x; 1.1538x over previous
#include <cuda_runtime.h>
#include <cuda_bf16.h>
#include <cuda_fp16.h>
#include <math.h>
#include <stdint.h>

#define NLAYER 12
#define EPSV 1e-5f
typedef unsigned short u16;

// ---------------- f32 scratch ------------------------------------------------
__device__ float g_e  [1048576];
__device__ float g_q  [1048576];
__device__ float g_big[4194304];
__device__ float g_s  [8388608];

// ---------------- weight fp16 hi/lo ------------------------------------------
#define OFF_E1 0L
#define OFF_E2 1048576L
#define OFF_EI 1572864L
#define OFF_Q  2621440L
#define OFF_K  8912896L
#define OFF_V  15204352L
#define OFF_O  21495808L
#define OFF_F1 27787264L
#define OFF_F2 52953088L
#define OFF_D1 78118912L
#define OFF_D2 79167488L
#define OFF_DI 81264640L
#define W_TOT  82313216L
__device__ u16 g_wh[W_TOT];
__device__ u16 g_wl[W_TOT];
// fp16 single activations (B operands of weight GEMMs)
__device__ u16 g_ath[4194304];
__device__ u16 g_hth[1048576];
__device__ u16 g_oth[1048576];
// bf16 hi/lo attention operands (3-term path, verified)
__device__ u16 g_qth[1048576], g_qtl[1048576];
__device__ u16 g_kth[1048576], g_ktl[1048576];
__device__ u16 g_vh [1048576], g_vl [1048576];
__device__ u16 g_ph [8388608], g_pl [8388608];

// ---------------- helpers ----------------------------------------------------
__device__ __forceinline__ uint32_t smem_u32(const void* p) {
    uint32_t a;
    asm("{ .reg .u64 t; cvta.to.shared.u64 t, %1; cvt.u32.u64 %0, t; }" : "=r"(a) : "l"(p));
    return a;
}
#define SWZ(x) ((x) ^ (((x) >> 3) & 0x70))

__device__ __forceinline__ void cp16(uint32_t d, const void* g) {
    asm volatile("cp.async.cg.shared.global [%0], [%1], 16;" :: "r"(d), "l"(g));
}
__device__ __forceinline__ void cp_commit() { asm volatile("cp.async.commit_group;"); }
template<int N> __device__ __forceinline__ void cp_wait() {
    asm volatile("cp.async.wait_group %0;" :: "n"(N));
}
__device__ __forceinline__ void ldsm4(uint32_t* r, uint32_t a) {
    asm volatile("ldmatrix.sync.aligned.m8n8.x4.shared.b16 {%0,%1,%2,%3}, [%4];"
                 : "=r"(r[0]), "=r"(r[1]), "=r"(r[2]), "=r"(r[3]) : "r"(a));
}
__device__ __forceinline__ void mma_bf(float* c, const uint32_t* a, const uint32_t* b) {
    asm volatile(
        "mma.sync.aligned.m16n8k16.row.col.f32.bf16.bf16.f32 "
        "{%0,%1,%2,%3}, {%4,%5,%6,%7}, {%8,%9}, {%0,%1,%2,%3};"
        : "+f"(c[0]), "+f"(c[1]), "+f"(c[2]), "+f"(c[3])
        : "r"(a[0]), "r"(a[1]), "r"(a[2]), "r"(a[3]), "r"(b[0]), "r"(b[1]));
}
__device__ __forceinline__ void mma_fp(float* c, const uint32_t* a, const uint32_t* b) {
    asm volatile(
        "mma.sync.aligned.m16n8k16.row.col.f32.f16.f16.f32 "
        "{%0,%1,%2,%3}, {%4,%5,%6,%7}, {%8,%9}, {%0,%1,%2,%3};"
        : "+f"(c[0]), "+f"(c[1]), "+f"(c[2]), "+f"(c[3])
        : "r"(a[0]), "r"(a[1]), "r"(a[2]), "r"(a[3]), "r"(b[0]), "r"(b[1]));
}
__device__ __forceinline__ void splt(float v, u16& h, u16& l) {   // bf16 hi/lo
    __nv_bfloat16 hb = __float2bfloat16(v);
    h = __bfloat16_as_ushort(hb);
    l = __bfloat16_as_ushort(__float2bfloat16(v - __bfloat162float(hb)));
}
__device__ __forceinline__ void splth(float v, u16& h, u16& l) {  // fp16 hi/lo
    __half hh = __float2half(v);
    h = __half_as_ushort(hh);
    l = __half_as_ushort(__float2half(v - __half2float(hh)));
}
__device__ __forceinline__ u16 f2h(float v) { return __half_as_ushort(__float2half(v)); }

// bf16 3-term chunk (verified): acc += Ah*Bh + Ah*Bl + Al*Bh
template<int NT>
__device__ __forceinline__ void mma_chunk(
    float (&acc)[2][NT][4], uint32_t aHi, uint32_t aLo, uint32_t bHi, uint32_t bLo,
    int wm, int wn, int lane)
{
    int la = lane & 7, j = lane >> 3;
    #pragma unroll
    for (int ks = 0; ks < 4; ks++) {
        uint32_t ah[2][4], al[2][4];
        #pragma unroll
        for (int mi = 0; mi < 2; mi++) {
            uint32_t off = SWZ((uint32_t)((wm * 32 + mi * 16 + ((j & 1) << 3) + la) * 128 + ks * 32 + ((j >> 1) << 4)));
            ldsm4(ah[mi], aHi + off);
            ldsm4(al[mi], aLo + off);
        }
        uint32_t bh[NT][2], bl[NT][2];
        #pragma unroll
        for (int nt = 0; nt < NT; nt += 2) {
            uint32_t off = SWZ((uint32_t)((wn * NT * 8 + nt * 8 + ((j >> 1) << 3) + la) * 128 + ks * 32 + ((j & 1) << 4)));
            uint32_t t[4];
            ldsm4(t, bHi + off);
            bh[nt][0] = t[0]; bh[nt][1] = t[1]; bh[nt + 1][0] = t[2]; bh[nt + 1][1] = t[3];
            ldsm4(t, bLo + off);
            bl[nt][0] = t[0]; bl[nt][1] = t[1]; bl[nt + 1][0] = t[2]; bl[nt + 1][1] = t[3];
        }
        #pragma unroll
        for (int mi = 0; mi < 2; mi++)
            #pragma unroll
            for (int nt = 0; nt < NT; nt++) {
                mma_bf(acc[mi][nt], ah[mi], bh[nt]);
                mma_bf(acc[mi][nt], ah[mi], bl[nt]);
                mma_bf(acc[mi][nt], al[mi], bh[nt]);
            }
    }
}

// fp16 2-term chunk: acc += Ah*B + Al*B  (A = weights hi/lo, B single)
template<int NT>
__device__ __forceinline__ void mma2_chunk(
    float (&acc)[2][NT][4], uint32_t aHi, uint32_t aLo, uint32_t bS,
    int wm, int wn, int lane)
{
    int la = lane & 7, j = lane >> 3;
    #pragma unroll
    for (int ks = 0; ks < 4; ks++) {
        uint32_t ah[2][4], al[2][4];
        #pragma unroll
        for (int mi = 0; mi < 2; mi++) {
            uint32_t off = SWZ((uint32_t)((wm * 32 + mi * 16 + ((j & 1) << 3) + la) * 128 + ks * 32 + ((j >> 1) << 4)));
            ldsm4(ah[mi], aHi + off);
            ldsm4(al[mi], aLo + off);
        }
        uint32_t bh[NT][2];
        #pragma unroll
        for (int nt = 0; nt < NT; nt += 2) {
            uint32_t off = SWZ((uint32_t)((wn * NT * 8 + nt * 8 + ((j >> 1) << 3) + la) * 128 + ks * 32 + ((j & 1) << 4)));
            uint32_t t[4];
            ldsm4(t, bS + off);
            bh[nt][0] = t[0]; bh[nt][1] = t[1]; bh[nt + 1][0] = t[2]; bh[nt + 1][1] = t[3];
        }
        #pragma unroll
        for (int mi = 0; mi < 2; mi++)
            #pragma unroll
            for (int nt = 0; nt < NT; nt++) {
                mma_fp(acc[mi][nt], ah[mi], bh[nt]);
                mma_fp(acc[mi][nt], al[mi], bh[nt]);
            }
    }
}

// ---------------- one-time weight split (fp16 hi/lo) --------------------------
__global__ void __launch_bounds__(256) split_w(
    const float* p0, const float* p1, const float* p2, const float* p3,
    const float* p4, const float* p5, const float* p6, const float* p7,
    const float* p8, const float* p9, const float* p10, const float* p11)
{
    const long offs[12] = {OFF_E1, OFF_E2, OFF_EI, OFF_Q, OFF_K, OFF_V,
                           OFF_O, OFF_F1, OFF_F2, OFF_D1, OFF_D2, OFF_DI};
    const float* ptrs[12] = {p0, p1, p2, p3, p4, p5, p6, p7, p8, p9, p10, p11};
    long base = ((long)blockIdx.x * 256 + threadIdx.x) * 16;
    if (base >= W_TOT) return;
    int seg = 0;
    #pragma unroll
    for (int i = 1; i < 12; i++) if (base >= offs[i]) seg = i;
    const float* src = ptrs[seg] + (base - offs[seg]);
    u16 hb[16], lb[16];
    #pragma unroll
    for (int t = 0; t < 16; t += 4) {
        float4 x = *reinterpret_cast<const float4*>(src + t);
        splth(x.x, hb[t], lb[t]); splth(x.y, hb[t+1], lb[t+1]);
        splth(x.z, hb[t+2], lb[t+2]); splth(x.w, hb[t+3], lb[t+3]);
    }
    uint4* dh = reinterpret_cast<uint4*>(&g_wh[base]);
    uint4* dl = reinterpret_cast<uint4*>(&g_wl[base]);
    dh[0] = ((uint4*)hb)[0]; dh[1] = ((uint4*)hb)[1];
    dl[0] = ((uint4*)lb)[0]; dl[1] = ((uint4*)lb)[1];
}

// ---------------- transpose to single fp16: X (z,R,512) -> T (z,512,R) -------
__global__ void __launch_bounds__(256) tsplit(
    const float* __restrict__ X, u16* __restrict__ Th, int R)
{
    __shared__ float s[64][65];
    int tid = threadIdx.x;
    int z = blockIdx.z, f0 = blockIdx.y * 64, w0 = blockIdx.x * 64;
    const float* Xb = X + ((size_t)z * R + f0) * 512 + w0;
    for (int it = tid; it < 1024; it += 256) {
        int r = it >> 4, cg = it & 15;
        float4 v = *reinterpret_cast<const float4*>(Xb + (size_t)r * 512 + cg * 4);
        s[r][cg * 4 + 0] = v.x; s[r][cg * 4 + 1] = v.y;
        s[r][cg * 4 + 2] = v.z; s[r][cg * 4 + 3] = v.w;
    }
    __syncthreads();
    for (int it = tid; it < 512; it += 256) {
        int w = it >> 3, cg = it & 7;
        u16 hb[8];
        #pragma unroll
        for (int j = 0; j < 8; j++) hb[j] = f2h(s[cg * 8 + j][w]);
        size_t o = ((size_t)z * 512 + w0 + w) * R + f0 + cg * 8;
        *reinterpret_cast<uint4*>(Th + o) = *reinterpret_cast<uint4*>(hb);
    }
}

// ---------------- frame_norm fused with transpose (single fp16 out) ----------
__global__ void __launch_bounds__(256) fn_tsplit(
    const float* __restrict__ X, const float* __restrict__ gw, const float* __restrict__ gb,
    u16* __restrict__ Th)
{
    int tid = threadIdx.x;
    int bc = blockIdx.z, c = bc & 1;
    int w0 = blockIdx.x * 64;
    int ft = blockIdx.y;
    const float* Xb = X + (size_t)bc * 262144;

    int wl = tid & 63, part = tid >> 6;
    float sum = 0.f, sq = 0.f;
    for (int f = part; f < 512; f += 4) {
        float v = Xb[(size_t)f * 512 + w0 + wl];
        sum += v; sq += v * v;
    }
    __shared__ float r1[4][64], r2[4][64];
    __shared__ float smu[64], srs[64];
    r1[part][wl] = sum; r2[part][wl] = sq;
    __syncthreads();
    if (tid < 64) {
        float s = r1[0][tid] + r1[1][tid] + r1[2][tid] + r1[3][tid];
        float q = r2[0][tid] + r2[1][tid] + r2[2][tid] + r2[3][tid];
        float mu = s * (1.f / 512.f);
        float var = q * (1.f / 512.f) - mu * mu;
        smu[tid] = mu; srs[tid] = rsqrtf(var + EPSV);
    }
    __syncthreads();

    __shared__ float tile[64][65];
    for (int it = tid; it < 1024; it += 256) {
        int r = it >> 4, cg = it & 15;
        float4 v = *reinterpret_cast<const float4*>(Xb + (size_t)(ft * 64 + r) * 512 + w0 + cg * 4);
        tile[r][cg * 4 + 0] = v.x; tile[r][cg * 4 + 1] = v.y;
        tile[r][cg * 4 + 2] = v.z; tile[r][cg * 4 + 3] = v.w;
    }
    __syncthreads();
    int w = tid >> 2, seg = tid & 3;
    float mu = smu[w], rs = srs[w];
    u16 hb[16];
    #pragma unroll
    for (int j = 0; j < 16; j++) {
        int f = seg * 16 + j, fg = ft * 64 + f;
        hb[j] = f2h((tile[f][w] - mu) * rs * gw[c * 512 + fg] + gb[c * 512 + fg]);
    }
    size_t o = ((size_t)bc * 512 + w0 + w) * 512 + ft * 64 + seg * 16;
    reinterpret_cast<uint4*>(Th + o)[0] = ((uint4*)hb)[0];
    reinterpret_cast<uint4*>(Th + o)[1] = ((uint4*)hb)[1];
}

// ---------------- channel-mix + RoPE + transpose (Q bf16 hi/lo, K bf16 hi/lo)
__global__ void __launch_bounds__(256) rope_tsplit(
    const float* __restrict__ big, const float* __restrict__ qdw, const float* __restrict__ kdw,
    u16* __restrict__ Qh, u16* __restrict__ Ql, u16* __restrict__ Kh, u16* __restrict__ Kl)
{
    __shared__ float tile[64][65];
    int tid = threadIdx.x;
    int zz = blockIdx.z;
    int proj = zz >> 2, bd = zz & 3;
    int b = bd >> 1, d = bd & 1;
    int f0 = blockIdx.y * 64, w0 = blockIdx.x * 64;
    const float* dw = proj ? kdw : qdw;
    float d0 = dw[d * 2 + 0], d1 = dw[d * 2 + 1];
    const float* X0 = big + ((size_t)(proj * 4 + b * 2) * 512 + f0) * 512 + w0;
    const float* X1 = X0 + 262144;
    for (int it = tid; it < 1024; it += 256) {
        int r = it >> 4, cg = it & 15;
        float4 a = *reinterpret_cast<const float4*>(X0 + (size_t)r * 512 + cg * 4);
        float4 bb = *reinterpret_cast<const float4*>(X1 + (size_t)r * 512 + cg * 4);
        tile[r][cg * 4 + 0] = d0 * a.x + d1 * bb.x;
        tile[r][cg * 4 + 1] = d0 * a.y + d1 * bb.y;
        tile[r][cg * 4 + 2] = d0 * a.z + d1 * bb.z;
        tile[r][cg * 4 + 3] = d0 * a.w + d1 * bb.w;
    }
    __syncthreads();
    int w = tid >> 2, seg = tid & 3;
    int wg = w0 + w;
    u16 hb[16], lb[16];
    #pragma unroll
    for (int j2 = 0; j2 < 8; j2++) {
        int fe = seg * 16 + j2 * 2, fg = f0 + fe;
        int i = (fg & 63) >> 1;
        float inv = powf(10000.f, -(float)(2 * i) / 64.f);
        float sn, cs;
        sincosf((float)wg * inv, &sn, &cs);
        float v0 = tile[fe][w], v1 = tile[fe + 1][w];
        splt(v0 * cs - v1 * sn, hb[j2 * 2], lb[j2 * 2]);
        splt(v1 * cs + v0 * sn, hb[j2 * 2 + 1], lb[j2 * 2 + 1]);
    }
    u16* Th = proj ? Kh : Qh;
    u16* Tl = proj ? Kl : Ql;
    size_t o = ((size_t)bd * 512 + wg) * 512 + f0 + seg * 16;
    reinterpret_cast<uint4*>(Th + o)[0] = ((uint4*)hb)[0];
    reinterpret_cast<uint4*>(Th + o)[1] = ((uint4*)hb)[1];
    reinterpret_cast<uint4*>(Tl + o)[0] = ((uint4*)lb)[0];
    reinterpret_cast<uint4*>(Tl + o)[1] = ((uint4*)lb)[1];
}

// ---------------- V channel-mix -> bf16 hi/lo natural ------------------------
__global__ void __launch_bounds__(256) qkv_v(
    const float* __restrict__ big, const float* __restrict__ vdw,
    u16* __restrict__ Vh, u16* __restrict__ Vl)
{
    int idx = blockIdx.x * 256 + threadIdx.x;
    int w = idx & 511, f = (idx >> 9) & 511, bd = idx >> 18;
    int b = bd >> 1, d = bd & 1;
    size_t base = ((size_t)(8 + b * 2) * 512 + f) * 512 + w;
    float v = vdw[d * 2 + 0] * big[base] + vdw[d * 2 + 1] * big[base + 262144];
    u16 h, l;
    splt(v, h, l);
    size_t o = ((size_t)bd * 512 + f) * 512 + w;
    Vh[o] = h; Vl[o] = l;
}

// ---------------- pipelined fp16 2-term GEMM, templated tile-N ---------------
// OUT: 0 f32 ; 2 f32+res ; 3 sqrelu -> fp16 single CT (NT=4 only)
template<int OUT, int NT>
__global__ void __launch_bounds__(256, 2) gemm_bb(
    const u16* __restrict__ Ah, const u16* __restrict__ Al,
    const u16* __restrict__ Bs,
    const float* __restrict__ Res, float* __restrict__ C,
    u16* __restrict__ CT,
    int M, int K, long projStride)
{
    constexpr int BN = NT * 32;
    constexpr int BSZ = BN * 128;
    constexpr int STG = 16384 + BSZ;
    extern __shared__ char sm[];
    uint32_t sb = smem_u32(sm);
    int tid = threadIdx.x, wid = tid >> 5, lane = tid & 31;
    int wm = wid >> 2, wn = wid & 3;
    int proj = blockIdx.z >> 2, bc = blockIdx.z & 3, c = bc & 1;
    const u16* Ab_h = Ah + proj * projStride + (size_t)c * M * K;
    const u16* Ab_l = Al + proj * projStride + (size_t)c * M * K;
    const u16* Bb = Bs + (size_t)bc * 512 * K;
    int m0 = blockIdx.y * 64, n0 = blockIdx.x * BN;

    auto load_stage = [&](int ch, int s) {
        uint32_t st = sb + s * STG;
        const u16* ah = Ab_h + (size_t)m0 * K + ch * 64;
        const u16* al = Ab_l + (size_t)m0 * K + ch * 64;
        for (int it = tid; it < 512; it += 256) {
            int r = it >> 3, cg = it & 7;
            uint32_t o = SWZ((uint32_t)(r * 128 + cg * 16));
            size_t gof = (size_t)r * K + cg * 8;
            cp16(st + o, ah + gof);
            cp16(st + 8192 + o, al + gof);
        }
        const u16* bh = Bb + (size_t)n0 * K + ch * 64;
        for (int it = tid; it < BN * 8; it += 256) {
            int r = it >> 3, cg = it & 7;
            uint32_t o = SWZ((uint32_t)(r * 128 + cg * 16));
            cp16(st + 16384 + o, bh + (size_t)r * K + cg * 8);
        }
    };

    float acc[2][NT][4] = {};
    int NC = K >> 6;
    load_stage(0, 0); cp_commit();
    for (int ch = 0; ch < NC; ch++) {
        if (ch + 1 < NC) { load_stage(ch + 1, (ch + 1) & 1); cp_commit(); cp_wait<1>(); }
        else cp_wait<0>();
        __syncthreads();
        uint32_t st = sb + (ch & 1) * STG;
        mma2_chunk<NT>(acc, st, st + 8192, st + 16384, wm, wn, lane);
        __syncthreads();
    }

    float* stg = (float*)sm;  // 64 x (BN+4)
    #pragma unroll
    for (int mi = 0; mi < 2; mi++)
        #pragma unroll
        for (int nt = 0; nt < NT; nt++) {
            int row = wm * 32 + mi * 16 + (lane >> 2);
            int col = wn * NT * 8 + nt * 8 + (lane & 3) * 2;
            stg[row * (BN + 4) + col] = acc[mi][nt][0];
            stg[row * (BN + 4) + col + 1] = acc[mi][nt][1];
            stg[(row + 8) * (BN + 4) + col] = acc[mi][nt][2];
            stg[(row + 8) * (BN + 4) + col + 1] = acc[mi][nt][3];
        }
    __syncthreads();

    if (OUT == 3) {
        int j = tid >> 1, msel = tid & 1;
        u16 hb[32];
        #pragma unroll
        for (int i = 0; i < 32; i++) {
            float v = stg[(msel * 32 + i) * (BN + 4) + j];
            float r = fmaxf(v, 0.f);
            hb[i] = f2h(r * r);
        }
        size_t o = ((size_t)bc * 512 + n0 + j) * (size_t)M + m0 + msel * 32;
        #pragma unroll
        for (int t = 0; t < 4; t++)
            reinterpret_cast<uint4*>(CT + o)[t] = ((uint4*)hb)[t];
    } else {
        float* Cb = C + (size_t)(proj * 4 + bc) * M * 512;
        constexpr int CPR = BN / 4;
        #pragma unroll
        for (int it = 0; it < 64 * CPR / 256; it++) {
            int idx = it * 256 + tid;
            int row = idx / CPR, c4 = idx % CPR;
            float4 v = *reinterpret_cast<float4*>(stg + row * (BN + 4) + c4 * 4);
            float vv[4] = {v.x, v.y, v.z, v.w};
            if (OUT == 2) {
                float4 rv = *reinterpret_cast<const float4*>(
                    Res + (size_t)bc * M * 512 + (size_t)(m0 + row) * 512 + n0 + c4 * 4);
                vv[0] += rv.x; vv[1] += rv.y; vv[2] += rv.z; vv[3] += rv.w;
            }
            float4 ov = {vv[0], vv[1], vv[2], vv[3]};
            *reinterpret_cast<float4*>(Cb + (size_t)(m0 + row) * 512 + n0 + c4 * 4) = ov;
        }
    }
}

// ---------------- attention scores (bf16 3-term, verified) -------------------
__global__ void __launch_bounds__(256, 2) attn_qk_bb(
    const u16* __restrict__ QTh, const u16* __restrict__ QTl,
    const u16* __restrict__ KTh, const u16* __restrict__ KTl,
    float* __restrict__ S)
{
    __shared__ char sm[49152];
    uint32_t sb = smem_u32(sm);
    int tid = threadIdx.x, wid = tid >> 5, lane = tid & 31;
    int wm = wid >> 2, wn = wid & 3;
    int z = blockIdx.z, bc = z >> 3, hd = z & 7;
    int q0 = blockIdx.y * 64, k0 = blockIdx.x * 128;
    size_t qbase = ((size_t)bc * 512 + q0) * 512 + hd * 64;
    size_t kbase = ((size_t)bc * 512 + k0) * 512 + hd * 64;

    for (int it = tid; it < 512; it += 256) {
        int r = it >> 3, cg = it & 7;
        uint32_t o = SWZ((uint32_t)(r * 128 + cg * 16));
        cp16(sb + o, QTh + qbase + (size_t)r * 512 + cg * 8);
        cp16(sb + 8192 + o, QTl + qbase + (size_t)r * 512 + cg * 8);
    }
    for (int it = tid; it < 1024; it += 256) {
        int r = it >> 3, cg = it & 7;
        uint32_t o = SWZ((uint32_t)(r * 128 + cg * 16));
        cp16(sb + 16384 + o, KTh + kbase + (size_t)r * 512 + cg * 8);
        cp16(sb + 32768 + o, KTl + kbase + (size_t)r * 512 + cg * 8);
    }
    cp_commit(); cp_wait<0>();
    __syncthreads();

    float acc[2][4][4] = {};
    mma_chunk<4>(acc, sb, sb + 8192, sb + 16384, sb + 32768, wm, wn, lane);
    __syncthreads();
    float* stg = (float*)sm;
    #pragma unroll
    for (int mi = 0; mi < 2; mi++)
        #pragma unroll
        for (int nt = 0; nt < 4; nt++) {
            int row = wm * 32 + mi * 16 + (lane >> 2);
            int col = wn * 32 + nt * 8 + (lane & 3) * 2;
            stg[row * 132 + col] = acc[mi][nt][0];
            stg[row * 132 + col + 1] = acc[mi][nt][1];
            stg[(row + 8) * 132 + col] = acc[mi][nt][2];
            stg[(row + 8) * 132 + col + 1] = acc[mi][nt][3];
        }
    __syncthreads();
    const float scale = 0.044194173824159216f;  // 1/sqrt(512)
    float* Sb = S + (size_t)z * 262144;
    #pragma unroll
    for (int r8 = 0; r8 < 8; r8++) {
        int row = wid + r8 * 8;
        float4 v = *reinterpret_cast<float4*>(stg + row * 132 + lane * 4);
        float4 o = {v.x * scale, v.y * scale, v.z * scale, v.w * scale};
        *reinterpret_cast<float4*>(Sb + (size_t)(q0 + row) * 512 + k0 + lane * 4) = o;
    }
}

// ---------------- softmax: S f32 -> P bf16 hi/lo -----------------------------
__global__ void __launch_bounds__(256) softmax_split(
    const float* __restrict__ S, u16* __restrict__ Ph, u16* __restrict__ Pl)
{
    int row = blockIdx.x * 8 + (threadIdx.x >> 5);
    int lane = threadIdx.x & 31;
    const float* p = S + (size_t)row * 512 + lane * 16;
    float v[16];
    #pragma unroll
    for (int g = 0; g < 4; g++) {
        float4 x = *reinterpret_cast<const float4*>(p + g * 4);
        v[g*4] = x.x; v[g*4+1] = x.y; v[g*4+2] = x.z; v[g*4+3] = x.w;
    }
    float mx = -1e30f;
    #pragma unroll
    for (int i = 0; i < 16; i++) mx = fmaxf(mx, v[i]);
    #pragma unroll
    for (int o = 16; o; o >>= 1) mx = fmaxf(mx, __shfl_xor_sync(0xffffffffu, mx, o));
    float sum = 0.f;
    #pragma unroll
    for (int i = 0; i < 16; i++) { v[i] = __expf(v[i] - mx); sum += v[i]; }
    #pragma unroll
    for (int o = 16; o; o >>= 1) sum += __shfl_xor_sync(0xffffffffu, sum, o);
    float inv = 1.f / sum;
    u16 hb[16], lb[16];
    #pragma unroll
    for (int i = 0; i < 16; i++) splt(v[i] * inv, hb[i], lb[i]);
    size_t o = (size_t)row * 512 + lane * 16;
    reinterpret_cast<uint4*>(Ph + o)[0] = ((uint4*)hb)[0];
    reinterpret_cast<uint4*>(Ph + o)[1] = ((uint4*)hb)[1];
    reinterpret_cast<uint4*>(Pl + o)[0] = ((uint4*)lb)[0];
    reinterpret_cast<uint4*>(Pl + o)[1] = ((uint4*)lb)[1];
}

// ---------------- attention output (bf16 3-term); OT out single fp16 ---------
__global__ void __launch_bounds__(256, 2) attn_pv_bb(
    const u16* __restrict__ Ph, const u16* __restrict__ Pl,
    const u16* __restrict__ Vh, const u16* __restrict__ Vl,
    u16* __restrict__ OT)
{
    extern __shared__ char sm[];
    uint32_t sb = smem_u32(sm);
    int tid = threadIdx.x, wid = tid >> 5, lane = tid & 31;
    int wm = wid >> 2, wn = wid & 3;
    int z = blockIdx.z, bc = z >> 3, hd = z & 7;
    int q0 = blockIdx.x * 64;
    size_t pbase = ((size_t)z * 512 + q0) * 512;
    size_t vbase = ((size_t)bc * 512 + hd * 64) * 512;

    auto load_stage = [&](int ch, int s) {
        uint32_t st = sb + s * 32768;
        for (int it = tid; it < 512; it += 256) {
            int r = it >> 3, cg = it & 7;
            uint32_t o = SWZ((uint32_t)(r * 128 + cg * 16));
            size_t pof = pbase + (size_t)r * 512 + ch * 64 + cg * 8;
            size_t vof = vbase + (size_t)r * 512 + ch * 64 + cg * 8;
            cp16(st + o, Ph + pof);
            cp16(st + 8192 + o, Pl + pof);
            cp16(st + 16384 + o, Vh + vof);
            cp16(st + 24576 + o, Vl + vof);
        }
    };

    float acc[2][2][4] = {};
    load_stage(0, 0); cp_commit();
    for (int ch = 0; ch < 8; ch++) {
        if (ch + 1 < 8) { load_stage(ch + 1, (ch + 1) & 1); cp_commit(); cp_wait<1>(); }
        else cp_wait<0>();
        __syncthreads();
        uint32_t st = sb + (ch & 1) * 32768;
        mma_chunk<2>(acc, st, st + 8192, st + 16384, st + 24576, wm, wn, lane);
        __syncthreads();
    }
    float* stg = (float*)sm;  // 64 x 68
    #pragma unroll
    for (int mi = 0; mi < 2; mi++)
        #pragma unroll
        for (int nt = 0; nt < 2; nt++) {
            int row = wm * 32 + mi * 16 + (lane >> 2);
            int col = wn * 16 + nt * 8 + (lane & 3) * 2;
            stg[row * 68 + col] = acc[mi][nt][0];
            stg[row * 68 + col + 1] = acc[mi][nt][1];
            stg[(row + 8) * 68 + col] = acc[mi][nt][2];
            stg[(row + 8) * 68 + col + 1] = acc[mi][nt][3];
        }
    __syncthreads();
    int row = tid >> 2, dseg = tid & 3;
    u16 hb[16];
    #pragma unroll
    for (int j = 0; j < 16; j++) hb[j] = f2h(stg[row * 68 + dseg * 16 + j]);
    size_t o = ((size_t)bc * 512 + q0 + row) * 512 + hd * 64 + dseg * 16;
    reinterpret_cast<uint4*>(OT + o)[0] = ((uint4*)hb)[0];
    reinterpret_cast<uint4*>(OT + o)[1] = ((uint4*)hb)[1];
}

// ---------------- channel mix (enc/dec, f32) ---------------------------------
template<bool SQRELU, bool HASADD>
__global__ void __launch_bounds__(256) mix_k(
    const float* __restrict__ X, const float* __restrict__ dw,
    const float* __restrict__ Add, float* __restrict__ Y, int Fd)
{
    int idx = blockIdx.x * 256 + threadIdx.x;
    int w = idx & 511;
    int f = (idx >> 9) % Fd;
    int bd = idx / (512 * Fd);
    int b = bd >> 1, d = bd & 1;
    size_t base = ((size_t)(b * 2) * Fd + f) * 512 + w;
    float v = dw[d * 2 + 0] * X[base] + dw[d * 2 + 1] * X[base + (size_t)Fd * 512];
    if (SQRELU) { float r = fmaxf(v, 0.f); v = r * r; }
    if (HASADD) v += Add[idx];
    Y[idx] = v;
}

// ---------------- host --------------------------------------------------------
extern "C" void kernel_launch(void* const* d_in, const int* in_sizes, int n_in,
                              void* d_out, int out_size)
{
    const float* x     = (const float*)d_in[0];
    const float* e1_pw = (const float*)d_in[1];
    const float* e1_dw = (const float*)d_in[2];
    const float* e2_pw = (const float*)d_in[3];
    const float* e2_dw = (const float*)d_in[4];
    const float* ei_pw = (const float*)d_in[5];
    const float* ei_dw = (const float*)d_in[6];
    const float* n1_w  = (const float*)d_in[7];
    const float* n1_b  = (const float*)d_in[8];
    const float* q_dw  = (const float*)d_in[10];
    const float* k_dw  = (const float*)d_in[12];
    const float* v_dw  = (const float*)d_in[14];
    const float* n2_w  = (const float*)d_in[16];
    const float* n2_b  = (const float*)d_in[17];
    const float* d1_dw = (const float*)d_in[21];
    const float* d2_dw = (const float*)d_in[23];
    const float* di_dw = (const float*)d_in[25];
    float* out = (float*)d_out;
    (void)in_sizes; (void)n_in; (void)out_size;

    float *e, *q, *big, *s;
    cudaGetSymbolAddress((void**)&e, g_e);
    cudaGetSymbolAddress((void**)&q, g_q);
    cudaGetSymbolAddress((void**)&big, g_big);
    cudaGetSymbolAddress((void**)&s, g_s);
    u16 *wh, *wl, *ath, *hth, *oth, *qth, *qtl, *kth, *ktl, *vh, *vl, *ph, *pl;
    cudaGetSymbolAddress((void**)&wh, g_wh);   cudaGetSymbolAddress((void**)&wl, g_wl);
    cudaGetSymbolAddress((void**)&ath, g_ath);
    cudaGetSymbolAddress((void**)&hth, g_hth);
    cudaGetSymbolAddress((void**)&oth, g_oth);
    cudaGetSymbolAddress((void**)&qth, g_qth); cudaGetSymbolAddress((void**)&qtl, g_qtl);
    cudaGetSymbolAddress((void**)&kth, g_kth); cudaGetSymbolAddress((void**)&ktl, g_ktl);
    cudaGetSymbolAddress((void**)&vh, g_vh);   cudaGetSymbolAddress((void**)&vl, g_vl);
    cudaGetSymbolAddress((void**)&ph, g_ph);   cudaGetSymbolAddress((void**)&pl, g_pl);

    const int SMG4 = 65536, SMG2 = 49152, SMPV = 65536;
    cudaFuncSetAttribute(gemm_bb<0,4>, cudaFuncAttributeMaxDynamicSharedMemorySize, SMG4);
    cudaFuncSetAttribute(gemm_bb<3,4>, cudaFuncAttributeMaxDynamicSharedMemorySize, SMG4);
    cudaFuncSetAttribute(gemm_bb<0,2>, cudaFuncAttributeMaxDynamicSharedMemorySize, SMG2);
    cudaFuncSetAttribute(gemm_bb<2,2>, cudaFuncAttributeMaxDynamicSharedMemorySize, SMG2);
    cudaFuncSetAttribute(attn_pv_bb, cudaFuncAttributeMaxDynamicSharedMemorySize, SMPV);

    dim3 tsG512(8, 8, 4), tsG1024(8, 16, 4);

    split_w<<<20096, 256>>>(e1_pw, e2_pw, ei_pw,
        (const float*)d_in[9], (const float*)d_in[11], (const float*)d_in[13],
        (const float*)d_in[15], (const float*)d_in[18], (const float*)d_in[19],
        (const float*)d_in[20], (const float*)d_in[22], (const float*)d_in[24]);

    // encoder (BN=64: 256 blocks per launch)
    tsplit<<<tsG1024, 256>>>(x, ath, 1024);
    gemm_bb<0,2><<<dim3(8, 8, 4), 256, SMG2>>>(wh + OFF_E1, wl + OFF_E1, ath, nullptr, big, nullptr, 512, 1024, 0);
    mix_k<true, false><<<4096, 256>>>(big, e1_dw, nullptr, q, 512);
    tsplit<<<tsG512, 256>>>(q, hth, 512);
    gemm_bb<0,2><<<dim3(8, 8, 4), 256, SMG2>>>(wh + OFF_E2, wl + OFF_E2, hth, nullptr, big, nullptr, 512, 512, 0);
    mix_k<false, false><<<4096, 256>>>(big, e2_dw, nullptr, s, 512);
    gemm_bb<0,2><<<dim3(8, 8, 4), 256, SMG2>>>(wh + OFF_EI, wl + OFF_EI, ath, nullptr, big, nullptr, 512, 1024, 0);
    mix_k<false, true><<<4096, 256>>>(big, ei_dw, s, e, 512);

    for (int i = 0; i < NLAYER; i++) {
        long lw = (long)i * 524288;
        fn_tsplit<<<dim3(8, 8, 4), 256>>>(e, n1_w + (size_t)i * 1024, n1_b + (size_t)i * 1024, hth);
        gemm_bb<0,4><<<dim3(4, 8, 12), 256, SMG4>>>(wh + OFF_Q + lw, wl + OFF_Q + lw, hth,
                                                    nullptr, big, nullptr, 512, 512, OFF_K - OFF_Q);
        rope_tsplit<<<dim3(8, 8, 8), 256>>>(big, q_dw + i * 4, k_dw + i * 4, qth, qtl, kth, ktl);
        qkv_v<<<4096, 256>>>(big, v_dw + i * 4, vh, vl);
        attn_qk_bb<<<dim3(4, 8, 32), 256>>>(qth, qtl, kth, ktl, s);
        softmax_split<<<2048, 256>>>(s, ph, pl);
        attn_pv_bb<<<dim3(8, 1, 32), 256, SMPV>>>(ph, pl, vh, vl, oth);
        gemm_bb<2,2><<<dim3(8, 8, 4), 256, SMG2>>>(wh + OFF_O + lw, wl + OFF_O + lw, oth,
                                                   e, e, nullptr, 512, 512, 0);
        fn_tsplit<<<dim3(8, 8, 4), 256>>>(e, n2_w + (size_t)i * 1024, n2_b + (size_t)i * 1024, hth);
        long lf = (long)i * 2097152;
        gemm_bb<3,4><<<dim3(4, 32, 4), 256, SMG4>>>(wh + OFF_F1 + lf, wl + OFF_F1 + lf, hth,
                                                    nullptr, nullptr, ath, 2048, 512, 0);
        gemm_bb<2,2><<<dim3(8, 8, 4), 256, SMG2>>>(wh + OFF_F2 + lf, wl + OFF_F2 + lf, ath,
                                                   e, e, nullptr, 512, 2048, 0);
    }

    // decoder (BN=64: 512 blocks per launch)
    tsplit<<<tsG512, 256>>>(e, hth, 512);
    gemm_bb<0,2><<<dim3(8, 16, 4), 256, SMG2>>>(wh + OFF_D1, wl + OFF_D1, hth, nullptr, big, nullptr, 1024, 512, 0);
    mix_k<true, false><<<8192, 256>>>(big, d1_dw, nullptr, s, 1024);
    tsplit<<<tsG1024, 256>>>(s, ath, 1024);
    gemm_bb<0,2><<<dim3(8, 16, 4), 256, SMG2>>>(wh + OFF_D2, wl + OFF_D2, ath, nullptr, big + 2097152, nullptr, 1024, 1024, 0);
    mix_k<false, false><<<8192, 256>>>(big + 2097152, d2_dw, nullptr, s + 4194304, 1024);
    gemm_bb<0,2><<<dim3(8, 16, 4), 256, SMG2>>>(wh + OFF_DI, wl + OFF_DI, hth, nullptr, big, nullptr, 1024, 512, 0);
    mix_k<false, true><<<8192, 256>>>(big, di_dw, s + 4194304, out, 1024);
}

// round 15
// speedup vs baseline: 2.0587x; 1.0406x over previous
#include <cuda_runtime.h>
#include <cuda_bf16.h>
#include <cuda_fp16.h>
#include <math.h>
#include <stdint.h>

#define NLAYER 12
#define EPSV 1e-5f
typedef unsigned short u16;

// ---------------- f32 scratch ------------------------------------------------
__device__ float g_e  [1048576];
__device__ float g_q  [1048576];
__device__ float g_big[4194304];
__device__ float g_s  [8388608];

// ---------------- weight fp16 hi/lo ------------------------------------------
#define OFF_E1 0L
#define OFF_E2 1048576L
#define OFF_EI 1572864L
#define OFF_Q  2621440L
#define OFF_K  8912896L
#define OFF_V  15204352L
#define OFF_O  21495808L
#define OFF_F1 27787264L
#define OFF_F2 52953088L
#define OFF_D1 78118912L
#define OFF_D2 79167488L
#define OFF_DI 81264640L
#define W_TOT  82313216L
__device__ u16 g_wh[W_TOT];
__device__ u16 g_wl[W_TOT];
// fp16 single activations (B operands of weight GEMMs)
__device__ u16 g_ath[4194304];
__device__ u16 g_hth[1048576];
__device__ u16 g_oth[1048576];
// attention operands
__device__ u16 g_qth[1048576], g_qtl[1048576];   // bf16 hi/lo
__device__ u16 g_kth[1048576], g_ktl[1048576];   // bf16 hi/lo
__device__ u16 g_vh [1048576], g_vl [1048576];   // fp16 hi/lo
__device__ u16 g_ph [8388608];                   // fp16 single

// ---------------- helpers ----------------------------------------------------
__device__ __forceinline__ uint32_t smem_u32(const void* p) {
    uint32_t a;
    asm("{ .reg .u64 t; cvta.to.shared.u64 t, %1; cvt.u32.u64 %0, t; }" : "=r"(a) : "l"(p));
    return a;
}
#define SWZ(x) ((x) ^ (((x) >> 3) & 0x70))

__device__ __forceinline__ void cp16(uint32_t d, const void* g) {
    asm volatile("cp.async.cg.shared.global [%0], [%1], 16;" :: "r"(d), "l"(g));
}
__device__ __forceinline__ void cp_commit() { asm volatile("cp.async.commit_group;"); }
template<int N> __device__ __forceinline__ void cp_wait() {
    asm volatile("cp.async.wait_group %0;" :: "n"(N));
}
__device__ __forceinline__ void ldsm4(uint32_t* r, uint32_t a) {
    asm volatile("ldmatrix.sync.aligned.m8n8.x4.shared.b16 {%0,%1,%2,%3}, [%4];"
                 : "=r"(r[0]), "=r"(r[1]), "=r"(r[2]), "=r"(r[3]) : "r"(a));
}
__device__ __forceinline__ void mma_bf(float* c, const uint32_t* a, const uint32_t* b) {
    asm volatile(
        "mma.sync.aligned.m16n8k16.row.col.f32.bf16.bf16.f32 "
        "{%0,%1,%2,%3}, {%4,%5,%6,%7}, {%8,%9}, {%0,%1,%2,%3};"
        : "+f"(c[0]), "+f"(c[1]), "+f"(c[2]), "+f"(c[3])
        : "r"(a[0]), "r"(a[1]), "r"(a[2]), "r"(a[3]), "r"(b[0]), "r"(b[1]));
}
__device__ __forceinline__ void mma_fp(float* c, const uint32_t* a, const uint32_t* b) {
    asm volatile(
        "mma.sync.aligned.m16n8k16.row.col.f32.f16.f16.f32 "
        "{%0,%1,%2,%3}, {%4,%5,%6,%7}, {%8,%9}, {%0,%1,%2,%3};"
        : "+f"(c[0]), "+f"(c[1]), "+f"(c[2]), "+f"(c[3])
        : "r"(a[0]), "r"(a[1]), "r"(a[2]), "r"(a[3]), "r"(b[0]), "r"(b[1]));
}
__device__ __forceinline__ void splt(float v, u16& h, u16& l) {   // bf16 hi/lo
    __nv_bfloat16 hb = __float2bfloat16(v);
    h = __bfloat16_as_ushort(hb);
    l = __bfloat16_as_ushort(__float2bfloat16(v - __bfloat162float(hb)));
}
__device__ __forceinline__ void splth(float v, u16& h, u16& l) {  // fp16 hi/lo
    __half hh = __float2half(v);
    h = __half_as_ushort(hh);
    l = __half_as_ushort(__float2half(v - __half2float(hh)));
}
__device__ __forceinline__ u16 f2h(float v) { return __half_as_ushort(__float2half(v)); }

// bf16 3-term chunk (verified): acc += Ah*Bh + Ah*Bl + Al*Bh
template<int NT>
__device__ __forceinline__ void mma_chunk(
    float (&acc)[2][NT][4], uint32_t aHi, uint32_t aLo, uint32_t bHi, uint32_t bLo,
    int wm, int wn, int lane)
{
    int la = lane & 7, j = lane >> 3;
    #pragma unroll
    for (int ks = 0; ks < 4; ks++) {
        uint32_t ah[2][4], al[2][4];
        #pragma unroll
        for (int mi = 0; mi < 2; mi++) {
            uint32_t off = SWZ((uint32_t)((wm * 32 + mi * 16 + ((j & 1) << 3) + la) * 128 + ks * 32 + ((j >> 1) << 4)));
            ldsm4(ah[mi], aHi + off);
            ldsm4(al[mi], aLo + off);
        }
        uint32_t bh[NT][2], bl[NT][2];
        #pragma unroll
        for (int nt = 0; nt < NT; nt += 2) {
            uint32_t off = SWZ((uint32_t)((wn * NT * 8 + nt * 8 + ((j >> 1) << 3) + la) * 128 + ks * 32 + ((j & 1) << 4)));
            uint32_t t[4];
            ldsm4(t, bHi + off);
            bh[nt][0] = t[0]; bh[nt][1] = t[1]; bh[nt + 1][0] = t[2]; bh[nt + 1][1] = t[3];
            ldsm4(t, bLo + off);
            bl[nt][0] = t[0]; bl[nt][1] = t[1]; bl[nt + 1][0] = t[2]; bl[nt + 1][1] = t[3];
        }
        #pragma unroll
        for (int mi = 0; mi < 2; mi++)
            #pragma unroll
            for (int nt = 0; nt < NT; nt++) {
                mma_bf(acc[mi][nt], ah[mi], bh[nt]);
                mma_bf(acc[mi][nt], ah[mi], bl[nt]);
                mma_bf(acc[mi][nt], al[mi], bh[nt]);
            }
    }
}

// fp16 2-term, A hi/lo x B single: acc += Ah*B + Al*B
template<int NT>
__device__ __forceinline__ void mma2_chunk(
    float (&acc)[2][NT][4], uint32_t aHi, uint32_t aLo, uint32_t bS,
    int wm, int wn, int lane)
{
    int la = lane & 7, j = lane >> 3;
    #pragma unroll
    for (int ks = 0; ks < 4; ks++) {
        uint32_t ah[2][4], al[2][4];
        #pragma unroll
        for (int mi = 0; mi < 2; mi++) {
            uint32_t off = SWZ((uint32_t)((wm * 32 + mi * 16 + ((j & 1) << 3) + la) * 128 + ks * 32 + ((j >> 1) << 4)));
            ldsm4(ah[mi], aHi + off);
            ldsm4(al[mi], aLo + off);
        }
        uint32_t bh[NT][2];
        #pragma unroll
        for (int nt = 0; nt < NT; nt += 2) {
            uint32_t off = SWZ((uint32_t)((wn * NT * 8 + nt * 8 + ((j >> 1) << 3) + la) * 128 + ks * 32 + ((j & 1) << 4)));
            uint32_t t[4];
            ldsm4(t, bS + off);
            bh[nt][0] = t[0]; bh[nt][1] = t[1]; bh[nt + 1][0] = t[2]; bh[nt + 1][1] = t[3];
        }
        #pragma unroll
        for (int mi = 0; mi < 2; mi++)
            #pragma unroll
            for (int nt = 0; nt < NT; nt++) {
                mma_fp(acc[mi][nt], ah[mi], bh[nt]);
                mma_fp(acc[mi][nt], al[mi], bh[nt]);
            }
    }
}

// fp16 2-term, A single x B hi/lo: acc += A*Bh + A*Bl
template<int NT>
__device__ __forceinline__ void mma2b_chunk(
    float (&acc)[2][NT][4], uint32_t aS, uint32_t bHi, uint32_t bLo,
    int wm, int wn, int lane)
{
    int la = lane & 7, j = lane >> 3;
    #pragma unroll
    for (int ks = 0; ks < 4; ks++) {
        uint32_t ah[2][4];
        #pragma unroll
        for (int mi = 0; mi < 2; mi++) {
            uint32_t off = SWZ((uint32_t)((wm * 32 + mi * 16 + ((j & 1) << 3) + la) * 128 + ks * 32 + ((j >> 1) << 4)));
            ldsm4(ah[mi], aS + off);
        }
        uint32_t bh[NT][2], bl[NT][2];
        #pragma unroll
        for (int nt = 0; nt < NT; nt += 2) {
            uint32_t off = SWZ((uint32_t)((wn * NT * 8 + nt * 8 + ((j >> 1) << 3) + la) * 128 + ks * 32 + ((j & 1) << 4)));
            uint32_t t[4];
            ldsm4(t, bHi + off);
            bh[nt][0] = t[0]; bh[nt][1] = t[1]; bh[nt + 1][0] = t[2]; bh[nt + 1][1] = t[3];
            ldsm4(t, bLo + off);
            bl[nt][0] = t[0]; bl[nt][1] = t[1]; bl[nt + 1][0] = t[2]; bl[nt + 1][1] = t[3];
        }
        #pragma unroll
        for (int mi = 0; mi < 2; mi++)
            #pragma unroll
            for (int nt = 0; nt < NT; nt++) {
                mma_fp(acc[mi][nt], ah[mi], bh[nt]);
                mma_fp(acc[mi][nt], ah[mi], bl[nt]);
            }
    }
}

// ---------------- one-time weight split (fp16 hi/lo) --------------------------
__global__ void __launch_bounds__(256) split_w(
    const float* p0, const float* p1, const float* p2, const float* p3,
    const float* p4, const float* p5, const float* p6, const float* p7,
    const float* p8, const float* p9, const float* p10, const float* p11)
{
    const long offs[12] = {OFF_E1, OFF_E2, OFF_EI, OFF_Q, OFF_K, OFF_V,
                           OFF_O, OFF_F1, OFF_F2, OFF_D1, OFF_D2, OFF_DI};
    const float* ptrs[12] = {p0, p1, p2, p3, p4, p5, p6, p7, p8, p9, p10, p11};
    long base = ((long)blockIdx.x * 256 + threadIdx.x) * 16;
    if (base >= W_TOT) return;
    int seg = 0;
    #pragma unroll
    for (int i = 1; i < 12; i++) if (base >= offs[i]) seg = i;
    const float* src = ptrs[seg] + (base - offs[seg]);
    u16 hb[16], lb[16];
    #pragma unroll
    for (int t = 0; t < 16; t += 4) {
        float4 x = *reinterpret_cast<const float4*>(src + t);
        splth(x.x, hb[t], lb[t]); splth(x.y, hb[t+1], lb[t+1]);
        splth(x.z, hb[t+2], lb[t+2]); splth(x.w, hb[t+3], lb[t+3]);
    }
    uint4* dh = reinterpret_cast<uint4*>(&g_wh[base]);
    uint4* dl = reinterpret_cast<uint4*>(&g_wl[base]);
    dh[0] = ((uint4*)hb)[0]; dh[1] = ((uint4*)hb)[1];
    dl[0] = ((uint4*)lb)[0]; dl[1] = ((uint4*)lb)[1];
}

// ---------------- transpose to single fp16 -----------------------------------
__global__ void __launch_bounds__(256) tsplit(
    const float* __restrict__ X, u16* __restrict__ Th, int R)
{
    __shared__ float s[64][65];
    int tid = threadIdx.x;
    int z = blockIdx.z, f0 = blockIdx.y * 64, w0 = blockIdx.x * 64;
    const float* Xb = X + ((size_t)z * R + f0) * 512 + w0;
    for (int it = tid; it < 1024; it += 256) {
        int r = it >> 4, cg = it & 15;
        float4 v = *reinterpret_cast<const float4*>(Xb + (size_t)r * 512 + cg * 4);
        s[r][cg * 4 + 0] = v.x; s[r][cg * 4 + 1] = v.y;
        s[r][cg * 4 + 2] = v.z; s[r][cg * 4 + 3] = v.w;
    }
    __syncthreads();
    for (int it = tid; it < 512; it += 256) {
        int w = it >> 3, cg = it & 7;
        u16 hb[8];
        #pragma unroll
        for (int j = 0; j < 8; j++) hb[j] = f2h(s[cg * 8 + j][w]);
        size_t o = ((size_t)z * 512 + w0 + w) * R + f0 + cg * 8;
        *reinterpret_cast<uint4*>(Th + o) = *reinterpret_cast<uint4*>(hb);
    }
}

// ---------------- frame_norm fused with transpose (single fp16 out) ----------
__global__ void __launch_bounds__(256) fn_tsplit(
    const float* __restrict__ X, const float* __restrict__ gw, const float* __restrict__ gb,
    u16* __restrict__ Th)
{
    int tid = threadIdx.x;
    int bc = blockIdx.z, c = bc & 1;
    int w0 = blockIdx.x * 64;
    int ft = blockIdx.y;
    const float* Xb = X + (size_t)bc * 262144;

    int wl = tid & 63, part = tid >> 6;
    float sum = 0.f, sq = 0.f;
    for (int f = part; f < 512; f += 4) {
        float v = Xb[(size_t)f * 512 + w0 + wl];
        sum += v; sq += v * v;
    }
    __shared__ float r1[4][64], r2[4][64];
    __shared__ float smu[64], srs[64];
    r1[part][wl] = sum; r2[part][wl] = sq;
    __syncthreads();
    if (tid < 64) {
        float s = r1[0][tid] + r1[1][tid] + r1[2][tid] + r1[3][tid];
        float q = r2[0][tid] + r2[1][tid] + r2[2][tid] + r2[3][tid];
        float mu = s * (1.f / 512.f);
        float var = q * (1.f / 512.f) - mu * mu;
        smu[tid] = mu; srs[tid] = rsqrtf(var + EPSV);
    }
    __syncthreads();

    __shared__ float tile[64][65];
    for (int it = tid; it < 1024; it += 256) {
        int r = it >> 4, cg = it & 15;
        float4 v = *reinterpret_cast<const float4*>(Xb + (size_t)(ft * 64 + r) * 512 + w0 + cg * 4);
        tile[r][cg * 4 + 0] = v.x; tile[r][cg * 4 + 1] = v.y;
        tile[r][cg * 4 + 2] = v.z; tile[r][cg * 4 + 3] = v.w;
    }
    __syncthreads();
    int w = tid >> 2, seg = tid & 3;
    float mu = smu[w], rs = srs[w];
    u16 hb[16];
    #pragma unroll
    for (int j = 0; j < 16; j++) {
        int f = seg * 16 + j, fg = ft * 64 + f;
        hb[j] = f2h((tile[f][w] - mu) * rs * gw[c * 512 + fg] + gb[c * 512 + fg]);
    }
    size_t o = ((size_t)bc * 512 + w0 + w) * 512 + ft * 64 + seg * 16;
    reinterpret_cast<uint4*>(Th + o)[0] = ((uint4*)hb)[0];
    reinterpret_cast<uint4*>(Th + o)[1] = ((uint4*)hb)[1];
}

// ---------------- channel-mix + RoPE + transpose (Q,K bf16 hi/lo) ------------
__global__ void __launch_bounds__(256) rope_tsplit(
    const float* __restrict__ big, const float* __restrict__ qdw, const float* __restrict__ kdw,
    u16* __restrict__ Qh, u16* __restrict__ Ql, u16* __restrict__ Kh, u16* __restrict__ Kl)
{
    __shared__ float tile[64][65];
    int tid = threadIdx.x;
    int zz = blockIdx.z;
    int proj = zz >> 2, bd = zz & 3;
    int b = bd >> 1, d = bd & 1;
    int f0 = blockIdx.y * 64, w0 = blockIdx.x * 64;
    const float* dw = proj ? kdw : qdw;
    float d0 = dw[d * 2 + 0], d1 = dw[d * 2 + 1];
    const float* X0 = big + ((size_t)(proj * 4 + b * 2) * 512 + f0) * 512 + w0;
    const float* X1 = X0 + 262144;
    for (int it = tid; it < 1024; it += 256) {
        int r = it >> 4, cg = it & 15;
        float4 a = *reinterpret_cast<const float4*>(X0 + (size_t)r * 512 + cg * 4);
        float4 bb = *reinterpret_cast<const float4*>(X1 + (size_t)r * 512 + cg * 4);
        tile[r][cg * 4 + 0] = d0 * a.x + d1 * bb.x;
        tile[r][cg * 4 + 1] = d0 * a.y + d1 * bb.y;
        tile[r][cg * 4 + 2] = d0 * a.z + d1 * bb.z;
        tile[r][cg * 4 + 3] = d0 * a.w + d1 * bb.w;
    }
    __syncthreads();
    int w = tid >> 2, seg = tid & 3;
    int wg = w0 + w;
    u16 hb[16], lb[16];
    #pragma unroll
    for (int j2 = 0; j2 < 8; j2++) {
        int fe = seg * 16 + j2 * 2, fg = f0 + fe;
        int i = (fg & 63) >> 1;
        float inv = powf(10000.f, -(float)(2 * i) / 64.f);
        float sn, cs;
        sincosf((float)wg * inv, &sn, &cs);
        float v0 = tile[fe][w], v1 = tile[fe + 1][w];
        splt(v0 * cs - v1 * sn, hb[j2 * 2], lb[j2 * 2]);
        splt(v1 * cs + v0 * sn, hb[j2 * 2 + 1], lb[j2 * 2 + 1]);
    }
    u16* Th = proj ? Kh : Qh;
    u16* Tl = proj ? Kl : Ql;
    size_t o = ((size_t)bd * 512 + wg) * 512 + f0 + seg * 16;
    reinterpret_cast<uint4*>(Th + o)[0] = ((uint4*)hb)[0];
    reinterpret_cast<uint4*>(Th + o)[1] = ((uint4*)hb)[1];
    reinterpret_cast<uint4*>(Tl + o)[0] = ((uint4*)lb)[0];
    reinterpret_cast<uint4*>(Tl + o)[1] = ((uint4*)lb)[1];
}

// ---------------- V channel-mix -> fp16 hi/lo natural ------------------------
__global__ void __launch_bounds__(256) qkv_v(
    const float* __restrict__ big, const float* __restrict__ vdw,
    u16* __restrict__ Vh, u16* __restrict__ Vl)
{
    int idx = blockIdx.x * 256 + threadIdx.x;
    int w = idx & 511, f = (idx >> 9) & 511, bd = idx >> 18;
    int b = bd >> 1, d = bd & 1;
    size_t base = ((size_t)(8 + b * 2) * 512 + f) * 512 + w;
    float v = vdw[d * 2 + 0] * big[base] + vdw[d * 2 + 1] * big[base + 262144];
    u16 h, l;
    splth(v, h, l);
    size_t o = ((size_t)bd * 512 + f) * 512 + w;
    Vh[o] = h; Vl[o] = l;
}

// ---------------- pipelined fp16 2-term weight GEMM --------------------------
// OUT: 0 f32 ; 2 f32+res ; 3 sqrelu -> fp16 single CT (NT=4 only)
template<int OUT, int NT>
__global__ void __launch_bounds__(256, 2) gemm_bb(
    const u16* __restrict__ Ah, const u16* __restrict__ Al,
    const u16* __restrict__ Bs,
    const float* __restrict__ Res, float* __restrict__ C,
    u16* __restrict__ CT,
    int M, int K, long projStride)
{
    constexpr int BN = NT * 32;
    constexpr int BSZ = BN * 128;
    constexpr int STG = 16384 + BSZ;
    extern __shared__ char sm[];
    uint32_t sb = smem_u32(sm);
    int tid = threadIdx.x, wid = tid >> 5, lane = tid & 31;
    int wm = wid >> 2, wn = wid & 3;
    int proj = blockIdx.z >> 2, bc = blockIdx.z & 3, c = bc & 1;
    const u16* Ab_h = Ah + proj * projStride + (size_t)c * M * K;
    const u16* Ab_l = Al + proj * projStride + (size_t)c * M * K;
    const u16* Bb = Bs + (size_t)bc * 512 * K;
    int m0 = blockIdx.y * 64, n0 = blockIdx.x * BN;

    auto load_stage = [&](int ch, int s) {
        uint32_t st = sb + s * STG;
        const u16* ah = Ab_h + (size_t)m0 * K + ch * 64;
        const u16* al = Ab_l + (size_t)m0 * K + ch * 64;
        for (int it = tid; it < 512; it += 256) {
            int r = it >> 3, cg = it & 7;
            uint32_t o = SWZ((uint32_t)(r * 128 + cg * 16));
            size_t gof = (size_t)r * K + cg * 8;
            cp16(st + o, ah + gof);
            cp16(st + 8192 + o, al + gof);
        }
        const u16* bh = Bb + (size_t)n0 * K + ch * 64;
        for (int it = tid; it < BN * 8; it += 256) {
            int r = it >> 3, cg = it & 7;
            uint32_t o = SWZ((uint32_t)(r * 128 + cg * 16));
            cp16(st + 16384 + o, bh + (size_t)r * K + cg * 8);
        }
    };

    float acc[2][NT][4] = {};
    int NC = K >> 6;
    load_stage(0, 0); cp_commit();
    for (int ch = 0; ch < NC; ch++) {
        if (ch + 1 < NC) { load_stage(ch + 1, (ch + 1) & 1); cp_commit(); cp_wait<1>(); }
        else cp_wait<0>();
        __syncthreads();
        uint32_t st = sb + (ch & 1) * STG;
        mma2_chunk<NT>(acc, st, st + 8192, st + 16384, wm, wn, lane);
        __syncthreads();
    }

    float* stg = (float*)sm;  // 64 x (BN+4)
    #pragma unroll
    for (int mi = 0; mi < 2; mi++)
        #pragma unroll
        for (int nt = 0; nt < NT; nt++) {
            int row = wm * 32 + mi * 16 + (lane >> 2);
            int col = wn * NT * 8 + nt * 8 + (lane & 3) * 2;
            stg[row * (BN + 4) + col] = acc[mi][nt][0];
            stg[row * (BN + 4) + col + 1] = acc[mi][nt][1];
            stg[(row + 8) * (BN + 4) + col] = acc[mi][nt][2];
            stg[(row + 8) * (BN + 4) + col + 1] = acc[mi][nt][3];
        }
    __syncthreads();

    if (OUT == 3) {
        int j = tid >> 1, msel = tid & 1;
        u16 hb[32];
        #pragma unroll
        for (int i = 0; i < 32; i++) {
            float v = stg[(msel * 32 + i) * (BN + 4) + j];
            float r = fmaxf(v, 0.f);
            hb[i] = f2h(r * r);
        }
        size_t o = ((size_t)bc * 512 + n0 + j) * (size_t)M + m0 + msel * 32;
        #pragma unroll
        for (int t = 0; t < 4; t++)
            reinterpret_cast<uint4*>(CT + o)[t] = ((uint4*)hb)[t];
    } else {
        float* Cb = C + (size_t)(proj * 4 + bc) * M * 512;
        constexpr int CPR = BN / 4;
        #pragma unroll
        for (int it = 0; it < 64 * CPR / 256; it++) {
            int idx = it * 256 + tid;
            int row = idx / CPR, c4 = idx % CPR;
            float4 v = *reinterpret_cast<float4*>(stg + row * (BN + 4) + c4 * 4);
            float vv[4] = {v.x, v.y, v.z, v.w};
            if (OUT == 2) {
                float4 rv = *reinterpret_cast<const float4*>(
                    Res + (size_t)bc * M * 512 + (size_t)(m0 + row) * 512 + n0 + c4 * 4);
                vv[0] += rv.x; vv[1] += rv.y; vv[2] += rv.z; vv[3] += rv.w;
            }
            float4 ov = {vv[0], vv[1], vv[2], vv[3]};
            *reinterpret_cast<float4*>(Cb + (size_t)(m0 + row) * 512 + n0 + c4 * 4) = ov;
        }
    }
}

// ---------------- attention scores (bf16 3-term, verified) -------------------
__global__ void __launch_bounds__(256, 2) attn_qk_bb(
    const u16* __restrict__ QTh, const u16* __restrict__ QTl,
    const u16* __restrict__ KTh, const u16* __restrict__ KTl,
    float* __restrict__ S)
{
    __shared__ char sm[49152];
    uint32_t sb = smem_u32(sm);
    int tid = threadIdx.x, wid = tid >> 5, lane = tid & 31;
    int wm = wid >> 2, wn = wid & 3;
    int z = blockIdx.z, bc = z >> 3, hd = z & 7;
    int q0 = blockIdx.y * 64, k0 = blockIdx.x * 128;
    size_t qbase = ((size_t)bc * 512 + q0) * 512 + hd * 64;
    size_t kbase = ((size_t)bc * 512 + k0) * 512 + hd * 64;

    for (int it = tid; it < 512; it += 256) {
        int r = it >> 3, cg = it & 7;
        uint32_t o = SWZ((uint32_t)(r * 128 + cg * 16));
        cp16(sb + o, QTh + qbase + (size_t)r * 512 + cg * 8);
        cp16(sb + 8192 + o, QTl + qbase + (size_t)r * 512 + cg * 8);
    }
    for (int it = tid; it < 1024; it += 256) {
        int r = it >> 3, cg = it & 7;
        uint32_t o = SWZ((uint32_t)(r * 128 + cg * 16));
        cp16(sb + 16384 + o, KTh + kbase + (size_t)r * 512 + cg * 8);
        cp16(sb + 32768 + o, KTl + kbase + (size_t)r * 512 + cg * 8);
    }
    cp_commit(); cp_wait<0>();
    __syncthreads();

    float acc[2][4][4] = {};
    mma_chunk<4>(acc, sb, sb + 8192, sb + 16384, sb + 32768, wm, wn, lane);
    __syncthreads();
    float* stg = (float*)sm;
    #pragma unroll
    for (int mi = 0; mi < 2; mi++)
        #pragma unroll
        for (int nt = 0; nt < 4; nt++) {
            int row = wm * 32 + mi * 16 + (lane >> 2);
            int col = wn * 32 + nt * 8 + (lane & 3) * 2;
            stg[row * 132 + col] = acc[mi][nt][0];
            stg[row * 132 + col + 1] = acc[mi][nt][1];
            stg[(row + 8) * 132 + col] = acc[mi][nt][2];
            stg[(row + 8) * 132 + col + 1] = acc[mi][nt][3];
        }
    __syncthreads();
    const float scale = 0.044194173824159216f;  // 1/sqrt(512)
    float* Sb = S + (size_t)z * 262144;
    #pragma unroll
    for (int r8 = 0; r8 < 8; r8++) {
        int row = wid + r8 * 8;
        float4 v = *reinterpret_cast<float4*>(stg + row * 132 + lane * 4);
        float4 o = {v.x * scale, v.y * scale, v.z * scale, v.w * scale};
        *reinterpret_cast<float4*>(Sb + (size_t)(q0 + row) * 512 + k0 + lane * 4) = o;
    }
}

// ---------------- softmax: S f32 -> P single fp16 ----------------------------
__global__ void __launch_bounds__(256) softmax_split(
    const float* __restrict__ S, u16* __restrict__ Ph)
{
    int row = blockIdx.x * 8 + (threadIdx.x >> 5);
    int lane = threadIdx.x & 31;
    const float* p = S + (size_t)row * 512 + lane * 16;
    float v[16];
    #pragma unroll
    for (int g = 0; g < 4; g++) {
        float4 x = *reinterpret_cast<const float4*>(p + g * 4);
        v[g*4] = x.x; v[g*4+1] = x.y; v[g*4+2] = x.z; v[g*4+3] = x.w;
    }
    float mx = -1e30f;
    #pragma unroll
    for (int i = 0; i < 16; i++) mx = fmaxf(mx, v[i]);
    #pragma unroll
    for (int o = 16; o; o >>= 1) mx = fmaxf(mx, __shfl_xor_sync(0xffffffffu, mx, o));
    float sum = 0.f;
    #pragma unroll
    for (int i = 0; i < 16; i++) { v[i] = __expf(v[i] - mx); sum += v[i]; }
    #pragma unroll
    for (int o = 16; o; o >>= 1) sum += __shfl_xor_sync(0xffffffffu, sum, o);
    float inv = 1.f / sum;
    u16 hb[16];
    #pragma unroll
    for (int i = 0; i < 16; i++) hb[i] = f2h(v[i] * inv);
    size_t o = (size_t)row * 512 + lane * 16;
    reinterpret_cast<uint4*>(Ph + o)[0] = ((uint4*)hb)[0];
    reinterpret_cast<uint4*>(Ph + o)[1] = ((uint4*)hb)[1];
}

// ---------------- attention output: P single fp16 x V fp16 hi/lo -------------
__global__ void __launch_bounds__(256, 2) attn_pv_bb(
    const u16* __restrict__ Ph,
    const u16* __restrict__ Vh, const u16* __restrict__ Vl,
    u16* __restrict__ OT)
{
    extern __shared__ char sm[];
    uint32_t sb = smem_u32(sm);
    int tid = threadIdx.x, wid = tid >> 5, lane = tid & 31;
    int wm = wid >> 2, wn = wid & 3;
    int z = blockIdx.z, bc = z >> 3, hd = z & 7;
    int q0 = blockIdx.x * 64;
    size_t pbase = ((size_t)z * 512 + q0) * 512;
    size_t vbase = ((size_t)bc * 512 + hd * 64) * 512;

    auto load_stage = [&](int ch, int s) {
        uint32_t st = sb + s * 24576;
        for (int it = tid; it < 512; it += 256) {
            int r = it >> 3, cg = it & 7;
            uint32_t o = SWZ((uint32_t)(r * 128 + cg * 16));
            size_t pof = pbase + (size_t)r * 512 + ch * 64 + cg * 8;
            size_t vof = vbase + (size_t)r * 512 + ch * 64 + cg * 8;
            cp16(st + o, Ph + pof);
            cp16(st + 8192 + o, Vh + vof);
            cp16(st + 16384 + o, Vl + vof);
        }
    };

    float acc[2][2][4] = {};
    load_stage(0, 0); cp_commit();
    for (int ch = 0; ch < 8; ch++) {
        if (ch + 1 < 8) { load_stage(ch + 1, (ch + 1) & 1); cp_commit(); cp_wait<1>(); }
        else cp_wait<0>();
        __syncthreads();
        uint32_t st = sb + (ch & 1) * 24576;
        mma2b_chunk<2>(acc, st, st + 8192, st + 16384, wm, wn, lane);
        __syncthreads();
    }
    float* stg = (float*)sm;  // 64 x 68
    #pragma unroll
    for (int mi = 0; mi < 2; mi++)
        #pragma unroll
        for (int nt = 0; nt < 2; nt++) {
            int row = wm * 32 + mi * 16 + (lane >> 2);
            int col = wn * 16 + nt * 8 + (lane & 3) * 2;
            stg[row * 68 + col] = acc[mi][nt][0];
            stg[row * 68 + col + 1] = acc[mi][nt][1];
            stg[(row + 8) * 68 + col] = acc[mi][nt][2];
            stg[(row + 8) * 68 + col + 1] = acc[mi][nt][3];
        }
    __syncthreads();
    int row = tid >> 2, dseg = tid & 3;
    u16 hb[16];
    #pragma unroll
    for (int j = 0; j < 16; j++) hb[j] = f2h(stg[row * 68 + dseg * 16 + j]);
    size_t o = ((size_t)bc * 512 + q0 + row) * 512 + hd * 64 + dseg * 16;
    reinterpret_cast<uint4*>(OT + o)[0] = ((uint4*)hb)[0];
    reinterpret_cast<uint4*>(OT + o)[1] = ((uint4*)hb)[1];
}

// ---------------- channel mix (enc/dec, f32) ---------------------------------
template<bool SQRELU, bool HASADD>
__global__ void __launch_bounds__(256) mix_k(
    const float* __restrict__ X, const float* __restrict__ dw,
    const float* __restrict__ Add, float* __restrict__ Y, int Fd)
{
    int idx = blockIdx.x * 256 + threadIdx.x;
    int w = idx & 511;
    int f = (idx >> 9) % Fd;
    int bd = idx / (512 * Fd);
    int b = bd >> 1, d = bd & 1;
    size_t base = ((size_t)(b * 2) * Fd + f) * 512 + w;
    float v = dw[d * 2 + 0] * X[base] + dw[d * 2 + 1] * X[base + (size_t)Fd * 512];
    if (SQRELU) { float r = fmaxf(v, 0.f); v = r * r; }
    if (HASADD) v += Add[idx];
    Y[idx] = v;
}

// ---------------- host --------------------------------------------------------
extern "C" void kernel_launch(void* const* d_in, const int* in_sizes, int n_in,
                              void* d_out, int out_size)
{
    const float* x     = (const float*)d_in[0];
    const float* e1_pw = (const float*)d_in[1];
    const float* e1_dw = (const float*)d_in[2];
    const float* e2_pw = (const float*)d_in[3];
    const float* e2_dw = (const float*)d_in[4];
    const float* ei_pw = (const float*)d_in[5];
    const float* ei_dw = (const float*)d_in[6];
    const float* n1_w  = (const float*)d_in[7];
    const float* n1_b  = (const float*)d_in[8];
    const float* q_dw  = (const float*)d_in[10];
    const float* k_dw  = (const float*)d_in[12];
    const float* v_dw  = (const float*)d_in[14];
    const float* n2_w  = (const float*)d_in[16];
    const float* n2_b  = (const float*)d_in[17];
    const float* d1_dw = (const float*)d_in[21];
    const float* d2_dw = (const float*)d_in[23];
    const float* di_dw = (const float*)d_in[25];
    float* out = (float*)d_out;
    (void)in_sizes; (void)n_in; (void)out_size;

    float *e, *q, *big, *s;
    cudaGetSymbolAddress((void**)&e, g_e);
    cudaGetSymbolAddress((void**)&q, g_q);
    cudaGetSymbolAddress((void**)&big, g_big);
    cudaGetSymbolAddress((void**)&s, g_s);
    u16 *wh, *wl, *ath, *hth, *oth, *qth, *qtl, *kth, *ktl, *vh, *vl, *ph;
    cudaGetSymbolAddress((void**)&wh, g_wh);   cudaGetSymbolAddress((void**)&wl, g_wl);
    cudaGetSymbolAddress((void**)&ath, g_ath);
    cudaGetSymbolAddress((void**)&hth, g_hth);
    cudaGetSymbolAddress((void**)&oth, g_oth);
    cudaGetSymbolAddress((void**)&qth, g_qth); cudaGetSymbolAddress((void**)&qtl, g_qtl);
    cudaGetSymbolAddress((void**)&kth, g_kth); cudaGetSymbolAddress((void**)&ktl, g_ktl);
    cudaGetSymbolAddress((void**)&vh, g_vh);   cudaGetSymbolAddress((void**)&vl, g_vl);
    cudaGetSymbolAddress((void**)&ph, g_ph);

    const int SMG4 = 65536, SMG2 = 49152, SMPV = 49152;
    cudaFuncSetAttribute(gemm_bb<0,4>, cudaFuncAttributeMaxDynamicSharedMemorySize, SMG4);
    cudaFuncSetAttribute(gemm_bb<3,4>, cudaFuncAttributeMaxDynamicSharedMemorySize, SMG4);
    cudaFuncSetAttribute(gemm_bb<0,2>, cudaFuncAttributeMaxDynamicSharedMemorySize, SMG2);
    cudaFuncSetAttribute(gemm_bb<2,2>, cudaFuncAttributeMaxDynamicSharedMemorySize, SMG2);
    cudaFuncSetAttribute(attn_pv_bb, cudaFuncAttributeMaxDynamicSharedMemorySize, SMPV);

    dim3 tsG512(8, 8, 4), tsG1024(8, 16, 4);

    split_w<<<20096, 256>>>(e1_pw, e2_pw, ei_pw,
        (const float*)d_in[9], (const float*)d_in[11], (const float*)d_in[13],
        (const float*)d_in[15], (const float*)d_in[18], (const float*)d_in[19],
        (const float*)d_in[20], (const float*)d_in[22], (const float*)d_in[24]);

    // encoder (BN=64: 256 blocks per launch)
    tsplit<<<tsG1024, 256>>>(x, ath, 1024);
    gemm_bb<0,2><<<dim3(8, 8, 4), 256, SMG2>>>(wh + OFF_E1, wl + OFF_E1, ath, nullptr, big, nullptr, 512, 1024, 0);
    mix_k<true, false><<<4096, 256>>>(big, e1_dw, nullptr, q, 512);
    tsplit<<<tsG512, 256>>>(q, hth, 512);
    gemm_bb<0,2><<<dim3(8, 8, 4), 256, SMG2>>>(wh + OFF_E2, wl + OFF_E2, hth, nullptr, big, nullptr, 512, 512, 0);
    mix_k<false, false><<<4096, 256>>>(big, e2_dw, nullptr, s, 512);
    gemm_bb<0,2><<<dim3(8, 8, 4), 256, SMG2>>>(wh + OFF_EI, wl + OFF_EI, ath, nullptr, big, nullptr, 512, 1024, 0);
    mix_k<false, true><<<4096, 256>>>(big, ei_dw, s, e, 512);

    for (int i = 0; i < NLAYER; i++) {
        long lw = (long)i * 524288;
        fn_tsplit<<<dim3(8, 8, 4), 256>>>(e, n1_w + (size_t)i * 1024, n1_b + (size_t)i * 1024, hth);
        gemm_bb<0,4><<<dim3(4, 8, 12), 256, SMG4>>>(wh + OFF_Q + lw, wl + OFF_Q + lw, hth,
                                                    nullptr, big, nullptr, 512, 512, OFF_K - OFF_Q);
        rope_tsplit<<<dim3(8, 8, 8), 256>>>(big, q_dw + i * 4, k_dw + i * 4, qth, qtl, kth, ktl);
        qkv_v<<<4096, 256>>>(big, v_dw + i * 4, vh, vl);
        attn_qk_bb<<<dim3(4, 8, 32), 256>>>(qth, qtl, kth, ktl, s);
        softmax_split<<<2048, 256>>>(s, ph);
        attn_pv_bb<<<dim3(8, 1, 32), 256, SMPV>>>(ph, vh, vl, oth);
        gemm_bb<2,2><<<dim3(8, 8, 4), 256, SMG2>>>(wh + OFF_O + lw, wl + OFF_O + lw, oth,
                                                   e, e, nullptr, 512, 512, 0);
        fn_tsplit<<<dim3(8, 8, 4), 256>>>(e, n2_w + (size_t)i * 1024, n2_b + (size_t)i * 1024, hth);
        long lf = (long)i * 2097152;
        gemm_bb<3,4><<<dim3(4, 32, 4), 256, SMG4>>>(wh + OFF_F1 + lf, wl + OFF_F1 + lf, hth,
                                                    nullptr, nullptr, ath, 2048, 512, 0);
        gemm_bb<2,2><<<dim3(8, 8, 4), 256, SMG2>>>(wh + OFF_F2 + lf, wl + OFF_F2 + lf, ath,
                                                   e, e, nullptr, 512, 2048, 0);
    }

    // decoder (BN=64: 512 blocks per launch)
    tsplit<<<tsG512, 256>>>(e, hth, 512);
    gemm_bb<0,2><<<dim3(8, 16, 4), 256, SMG2>>>(wh + OFF_D1, wl + OFF_D1, hth, nullptr, big, nullptr, 1024, 512, 0);
    mix_k<true, false><<<8192, 256>>>(big, d1_dw, nullptr, s, 1024);
    tsplit<<<tsG1024, 256>>>(s, ath, 1024);
    gemm_bb<0,2><<<dim3(8, 16, 4), 256, SMG2>>>(wh + OFF_D2, wl + OFF_D2, ath, nullptr, big + 2097152, nullptr, 1024, 1024, 0);
    mix_k<false, false><<<8192, 256>>>(big + 2097152, d2_dw, nullptr, s + 4194304, 1024);
    gemm_bb<0,2><<<dim3(8, 16, 4), 256, SMG2>>>(wh + OFF_DI, wl + OFF_DI, hth, nullptr, big, nullptr, 1024, 512, 0);
    mix_k<false, true><<<8192, 256>>>(big, di_dw, s + 4194304, out, 1024);
}

// round 16
// speedup vs baseline: 2.1008x; 1.0204x over previous
#include <cuda_runtime.h>
#include <cuda_bf16.h>
#include <cuda_fp16.h>
#include <math.h>
#include <stdint.h>

#define NLAYER 12
#define EPSV 1e-5f
typedef unsigned short u16;

// ---------------- f32 scratch ------------------------------------------------
__device__ float g_e  [1048576];
__device__ float g_q  [1048576];
__device__ float g_big[4194304];
__device__ float g_s  [8388608];
__device__ float g_rowsum[16384];

// ---------------- weight fp16 hi/lo ------------------------------------------
#define OFF_E1 0L
#define OFF_E2 1048576L
#define OFF_EI 1572864L
#define OFF_Q  2621440L
#define OFF_K  8912896L
#define OFF_V  15204352L
#define OFF_O  21495808L
#define OFF_F1 27787264L
#define OFF_F2 52953088L
#define OFF_D1 78118912L
#define OFF_D2 79167488L
#define OFF_DI 81264640L
#define W_TOT  82313216L
__device__ u16 g_wh[W_TOT];
__device__ u16 g_wl[W_TOT];
// fp16 single activations
__device__ u16 g_ath[4194304];
__device__ u16 g_hth[1048576];
__device__ u16 g_oth[1048576];
// attention operands
__device__ u16 g_qth[1048576], g_qtl[1048576];   // bf16 hi/lo
__device__ u16 g_kth[1048576], g_ktl[1048576];   // bf16 hi/lo
__device__ u16 g_vh [1048576], g_vl [1048576];   // fp16 hi/lo
__device__ u16 g_ph [8388608];                   // fp16 unnormalized expS

// ---------------- helpers ----------------------------------------------------
__device__ __forceinline__ uint32_t smem_u32(const void* p) {
    uint32_t a;
    asm("{ .reg .u64 t; cvta.to.shared.u64 t, %1; cvt.u32.u64 %0, t; }" : "=r"(a) : "l"(p));
    return a;
}
#define SWZ(x) ((x) ^ (((x) >> 3) & 0x70))

__device__ __forceinline__ void cp16(uint32_t d, const void* g) {
    asm volatile("cp.async.cg.shared.global [%0], [%1], 16;" :: "r"(d), "l"(g));
}
__device__ __forceinline__ void cp_commit() { asm volatile("cp.async.commit_group;"); }
template<int N> __device__ __forceinline__ void cp_wait() {
    asm volatile("cp.async.wait_group %0;" :: "n"(N));
}
__device__ __forceinline__ void ldsm4(uint32_t* r, uint32_t a) {
    asm volatile("ldmatrix.sync.aligned.m8n8.x4.shared.b16 {%0,%1,%2,%3}, [%4];"
                 : "=r"(r[0]), "=r"(r[1]), "=r"(r[2]), "=r"(r[3]) : "r"(a));
}
__device__ __forceinline__ void mma_bf(float* c, const uint32_t* a, const uint32_t* b) {
    asm volatile(
        "mma.sync.aligned.m16n8k16.row.col.f32.bf16.bf16.f32 "
        "{%0,%1,%2,%3}, {%4,%5,%6,%7}, {%8,%9}, {%0,%1,%2,%3};"
        : "+f"(c[0]), "+f"(c[1]), "+f"(c[2]), "+f"(c[3])
        : "r"(a[0]), "r"(a[1]), "r"(a[2]), "r"(a[3]), "r"(b[0]), "r"(b[1]));
}
__device__ __forceinline__ void mma_fp(float* c, const uint32_t* a, const uint32_t* b) {
    asm volatile(
        "mma.sync.aligned.m16n8k16.row.col.f32.f16.f16.f32 "
        "{%0,%1,%2,%3}, {%4,%5,%6,%7}, {%8,%9}, {%0,%1,%2,%3};"
        : "+f"(c[0]), "+f"(c[1]), "+f"(c[2]), "+f"(c[3])
        : "r"(a[0]), "r"(a[1]), "r"(a[2]), "r"(a[3]), "r"(b[0]), "r"(b[1]));
}
__device__ __forceinline__ void splt(float v, u16& h, u16& l) {   // bf16 hi/lo
    __nv_bfloat16 hb = __float2bfloat16(v);
    h = __bfloat16_as_ushort(hb);
    l = __bfloat16_as_ushort(__float2bfloat16(v - __bfloat162float(hb)));
}
__device__ __forceinline__ void splth(float v, u16& h, u16& l) {  // fp16 hi/lo
    __half hh = __float2half(v);
    h = __half_as_ushort(hh);
    l = __half_as_ushort(__float2half(v - __half2float(hh)));
}
__device__ __forceinline__ u16 f2h(float v) { return __half_as_ushort(__float2half(v)); }

// bf16 3-term chunk: acc += Ah*Bh + Ah*Bl + Al*Bh
template<int NT>
__device__ __forceinline__ void mma_chunk(
    float (&acc)[2][NT][4], uint32_t aHi, uint32_t aLo, uint32_t bHi, uint32_t bLo,
    int wm, int wn, int lane)
{
    int la = lane & 7, j = lane >> 3;
    #pragma unroll
    for (int ks = 0; ks < 4; ks++) {
        uint32_t ah[2][4], al[2][4];
        #pragma unroll
        for (int mi = 0; mi < 2; mi++) {
            uint32_t off = SWZ((uint32_t)((wm * 32 + mi * 16 + ((j & 1) << 3) + la) * 128 + ks * 32 + ((j >> 1) << 4)));
            ldsm4(ah[mi], aHi + off);
            ldsm4(al[mi], aLo + off);
        }
        uint32_t bh[NT][2], bl[NT][2];
        #pragma unroll
        for (int nt = 0; nt < NT; nt += 2) {
            uint32_t off = SWZ((uint32_t)((wn * NT * 8 + nt * 8 + ((j >> 1) << 3) + la) * 128 + ks * 32 + ((j & 1) << 4)));
            uint32_t t[4];
            ldsm4(t, bHi + off);
            bh[nt][0] = t[0]; bh[nt][1] = t[1]; bh[nt + 1][0] = t[2]; bh[nt + 1][1] = t[3];
            ldsm4(t, bLo + off);
            bl[nt][0] = t[0]; bl[nt][1] = t[1]; bl[nt + 1][0] = t[2]; bl[nt + 1][1] = t[3];
        }
        #pragma unroll
        for (int mi = 0; mi < 2; mi++)
            #pragma unroll
            for (int nt = 0; nt < NT; nt++) {
                mma_bf(acc[mi][nt], ah[mi], bh[nt]);
                mma_bf(acc[mi][nt], ah[mi], bl[nt]);
                mma_bf(acc[mi][nt], al[mi], bh[nt]);
            }
    }
}

// fp16 2-term, A hi/lo x B single
template<int NT>
__device__ __forceinline__ void mma2_chunk(
    float (&acc)[2][NT][4], uint32_t aHi, uint32_t aLo, uint32_t bS,
    int wm, int wn, int lane)
{
    int la = lane & 7, j = lane >> 3;
    #pragma unroll
    for (int ks = 0; ks < 4; ks++) {
        uint32_t ah[2][4], al[2][4];
        #pragma unroll
        for (int mi = 0; mi < 2; mi++) {
            uint32_t off = SWZ((uint32_t)((wm * 32 + mi * 16 + ((j & 1) << 3) + la) * 128 + ks * 32 + ((j >> 1) << 4)));
            ldsm4(ah[mi], aHi + off);
            ldsm4(al[mi], aLo + off);
        }
        uint32_t bh[NT][2];
        #pragma unroll
        for (int nt = 0; nt < NT; nt += 2) {
            uint32_t off = SWZ((uint32_t)((wn * NT * 8 + nt * 8 + ((j >> 1) << 3) + la) * 128 + ks * 32 + ((j & 1) << 4)));
            uint32_t t[4];
            ldsm4(t, bS + off);
            bh[nt][0] = t[0]; bh[nt][1] = t[1]; bh[nt + 1][0] = t[2]; bh[nt + 1][1] = t[3];
        }
        #pragma unroll
        for (int mi = 0; mi < 2; mi++)
            #pragma unroll
            for (int nt = 0; nt < NT; nt++) {
                mma_fp(acc[mi][nt], ah[mi], bh[nt]);
                mma_fp(acc[mi][nt], al[mi], bh[nt]);
            }
    }
}

// fp16 2-term, A single x B hi/lo
template<int NT>
__device__ __forceinline__ void mma2b_chunk(
    float (&acc)[2][NT][4], uint32_t aS, uint32_t bHi, uint32_t bLo,
    int wm, int wn, int lane)
{
    int la = lane & 7, j = lane >> 3;
    #pragma unroll
    for (int ks = 0; ks < 4; ks++) {
        uint32_t ah[2][4];
        #pragma unroll
        for (int mi = 0; mi < 2; mi++) {
            uint32_t off = SWZ((uint32_t)((wm * 32 + mi * 16 + ((j & 1) << 3) + la) * 128 + ks * 32 + ((j >> 1) << 4)));
            ldsm4(ah[mi], aS + off);
        }
        uint32_t bh[NT][2], bl[NT][2];
        #pragma unroll
        for (int nt = 0; nt < NT; nt += 2) {
            uint32_t off = SWZ((uint32_t)((wn * NT * 8 + nt * 8 + ((j >> 1) << 3) + la) * 128 + ks * 32 + ((j & 1) << 4)));
            uint32_t t[4];
            ldsm4(t, bHi + off);
            bh[nt][0] = t[0]; bh[nt][1] = t[1]; bh[nt + 1][0] = t[2]; bh[nt + 1][1] = t[3];
            ldsm4(t, bLo + off);
            bl[nt][0] = t[0]; bl[nt][1] = t[1]; bl[nt + 1][0] = t[2]; bl[nt + 1][1] = t[3];
        }
        #pragma unroll
        for (int mi = 0; mi < 2; mi++)
            #pragma unroll
            for (int nt = 0; nt < NT; nt++) {
                mma_fp(acc[mi][nt], ah[mi], bh[nt]);
                mma_fp(acc[mi][nt], ah[mi], bl[nt]);
            }
    }
}

// ---------------- one-time weight split --------------------------------------
__global__ void __launch_bounds__(256) split_w(
    const float* p0, const float* p1, const float* p2, const float* p3,
    const float* p4, const float* p5, const float* p6, const float* p7,
    const float* p8, const float* p9, const float* p10, const float* p11)
{
    const long offs[12] = {OFF_E1, OFF_E2, OFF_EI, OFF_Q, OFF_K, OFF_V,
                           OFF_O, OFF_F1, OFF_F2, OFF_D1, OFF_D2, OFF_DI};
    const float* ptrs[12] = {p0, p1, p2, p3, p4, p5, p6, p7, p8, p9, p10, p11};
    long base = ((long)blockIdx.x * 256 + threadIdx.x) * 16;
    if (base >= W_TOT) return;
    int seg = 0;
    #pragma unroll
    for (int i = 1; i < 12; i++) if (base >= offs[i]) seg = i;
    const float* src = ptrs[seg] + (base - offs[seg]);
    u16 hb[16], lb[16];
    #pragma unroll
    for (int t = 0; t < 16; t += 4) {
        float4 x = *reinterpret_cast<const float4*>(src + t);
        splth(x.x, hb[t], lb[t]); splth(x.y, hb[t+1], lb[t+1]);
        splth(x.z, hb[t+2], lb[t+2]); splth(x.w, hb[t+3], lb[t+3]);
    }
    uint4* dh = reinterpret_cast<uint4*>(&g_wh[base]);
    uint4* dl = reinterpret_cast<uint4*>(&g_wl[base]);
    dh[0] = ((uint4*)hb)[0]; dh[1] = ((uint4*)hb)[1];
    dl[0] = ((uint4*)lb)[0]; dl[1] = ((uint4*)lb)[1];
}

// ---------------- transpose to single fp16 -----------------------------------
__global__ void __launch_bounds__(256) tsplit(
    const float* __restrict__ X, u16* __restrict__ Th, int R)
{
    __shared__ float s[64][65];
    int tid = threadIdx.x;
    int z = blockIdx.z, f0 = blockIdx.y * 64, w0 = blockIdx.x * 64;
    const float* Xb = X + ((size_t)z * R + f0) * 512 + w0;
    for (int it = tid; it < 1024; it += 256) {
        int r = it >> 4, cg = it & 15;
        float4 v = *reinterpret_cast<const float4*>(Xb + (size_t)r * 512 + cg * 4);
        s[r][cg * 4 + 0] = v.x; s[r][cg * 4 + 1] = v.y;
        s[r][cg * 4 + 2] = v.z; s[r][cg * 4 + 3] = v.w;
    }
    __syncthreads();
    for (int it = tid; it < 512; it += 256) {
        int w = it >> 3, cg = it & 7;
        u16 hb[8];
        #pragma unroll
        for (int j = 0; j < 8; j++) hb[j] = f2h(s[cg * 8 + j][w]);
        size_t o = ((size_t)z * 512 + w0 + w) * R + f0 + cg * 8;
        *reinterpret_cast<uint4*>(Th + o) = *reinterpret_cast<uint4*>(hb);
    }
}

// ---------------- frame_norm fused with transpose ----------------------------
__global__ void __launch_bounds__(256) fn_tsplit(
    const float* __restrict__ X, const float* __restrict__ gw, const float* __restrict__ gb,
    u16* __restrict__ Th)
{
    int tid = threadIdx.x;
    int bc = blockIdx.z, c = bc & 1;
    int w0 = blockIdx.x * 64;
    int ft = blockIdx.y;
    const float* Xb = X + (size_t)bc * 262144;

    int wl = tid & 63, part = tid >> 6;
    float sum = 0.f, sq = 0.f;
    for (int f = part; f < 512; f += 4) {
        float v = Xb[(size_t)f * 512 + w0 + wl];
        sum += v; sq += v * v;
    }
    __shared__ float r1[4][64], r2[4][64];
    __shared__ float smu[64], srs[64];
    r1[part][wl] = sum; r2[part][wl] = sq;
    __syncthreads();
    if (tid < 64) {
        float s = r1[0][tid] + r1[1][tid] + r1[2][tid] + r1[3][tid];
        float q = r2[0][tid] + r2[1][tid] + r2[2][tid] + r2[3][tid];
        float mu = s * (1.f / 512.f);
        float var = q * (1.f / 512.f) - mu * mu;
        smu[tid] = mu; srs[tid] = rsqrtf(var + EPSV);
    }
    __syncthreads();

    __shared__ float tile[64][65];
    for (int it = tid; it < 1024; it += 256) {
        int r = it >> 4, cg = it & 15;
        float4 v = *reinterpret_cast<const float4*>(Xb + (size_t)(ft * 64 + r) * 512 + w0 + cg * 4);
        tile[r][cg * 4 + 0] = v.x; tile[r][cg * 4 + 1] = v.y;
        tile[r][cg * 4 + 2] = v.z; tile[r][cg * 4 + 3] = v.w;
    }
    __syncthreads();
    int w = tid >> 2, seg = tid & 3;
    float mu = smu[w], rs = srs[w];
    u16 hb[16];
    #pragma unroll
    for (int j = 0; j < 16; j++) {
        int f = seg * 16 + j, fg = ft * 64 + f;
        hb[j] = f2h((tile[f][w] - mu) * rs * gw[c * 512 + fg] + gb[c * 512 + fg]);
    }
    size_t o = ((size_t)bc * 512 + w0 + w) * 512 + ft * 64 + seg * 16;
    reinterpret_cast<uint4*>(Th + o)[0] = ((uint4*)hb)[0];
    reinterpret_cast<uint4*>(Th + o)[1] = ((uint4*)hb)[1];
}

// ---------------- channel-mix + RoPE + transpose (Q,K bf16 hi/lo) ------------
__global__ void __launch_bounds__(256) rope_tsplit(
    const float* __restrict__ big, const float* __restrict__ qdw, const float* __restrict__ kdw,
    u16* __restrict__ Qh, u16* __restrict__ Ql, u16* __restrict__ Kh, u16* __restrict__ Kl)
{
    __shared__ float tile[64][65];
    int tid = threadIdx.x;
    int zz = blockIdx.z;
    int proj = zz >> 2, bd = zz & 3;
    int b = bd >> 1, d = bd & 1;
    int f0 = blockIdx.y * 64, w0 = blockIdx.x * 64;
    const float* dw = proj ? kdw : qdw;
    float d0 = dw[d * 2 + 0], d1 = dw[d * 2 + 1];
    const float* X0 = big + ((size_t)(proj * 4 + b * 2) * 512 + f0) * 512 + w0;
    const float* X1 = X0 + 262144;
    for (int it = tid; it < 1024; it += 256) {
        int r = it >> 4, cg = it & 15;
        float4 a = *reinterpret_cast<const float4*>(X0 + (size_t)r * 512 + cg * 4);
        float4 bb = *reinterpret_cast<const float4*>(X1 + (size_t)r * 512 + cg * 4);
        tile[r][cg * 4 + 0] = d0 * a.x + d1 * bb.x;
        tile[r][cg * 4 + 1] = d0 * a.y + d1 * bb.y;
        tile[r][cg * 4 + 2] = d0 * a.z + d1 * bb.z;
        tile[r][cg * 4 + 3] = d0 * a.w + d1 * bb.w;
    }
    __syncthreads();
    int w = tid >> 2, seg = tid & 3;
    int wg = w0 + w;
    u16 hb[16], lb[16];
    #pragma unroll
    for (int j2 = 0; j2 < 8; j2++) {
        int fe = seg * 16 + j2 * 2, fg = f0 + fe;
        int i = (fg & 63) >> 1;
        float inv = powf(10000.f, -(float)(2 * i) / 64.f);
        float sn, cs;
        sincosf((float)wg * inv, &sn, &cs);
        float v0 = tile[fe][w], v1 = tile[fe + 1][w];
        splt(v0 * cs - v1 * sn, hb[j2 * 2], lb[j2 * 2]);
        splt(v1 * cs + v0 * sn, hb[j2 * 2 + 1], lb[j2 * 2 + 1]);
    }
    u16* Th = proj ? Kh : Qh;
    u16* Tl = proj ? Kl : Ql;
    size_t o = ((size_t)bd * 512 + wg) * 512 + f0 + seg * 16;
    reinterpret_cast<uint4*>(Th + o)[0] = ((uint4*)hb)[0];
    reinterpret_cast<uint4*>(Th + o)[1] = ((uint4*)hb)[1];
    reinterpret_cast<uint4*>(Tl + o)[0] = ((uint4*)lb)[0];
    reinterpret_cast<uint4*>(Tl + o)[1] = ((uint4*)lb)[1];
}

// ---------------- V channel-mix -> fp16 hi/lo ; also zero rowsum --------------
__global__ void __launch_bounds__(256) qkv_v(
    const float* __restrict__ big, const float* __restrict__ vdw,
    u16* __restrict__ Vh, u16* __restrict__ Vl, float* __restrict__ rowsum)
{
    int idx = blockIdx.x * 256 + threadIdx.x;
    if (idx < 16384) rowsum[idx] = 0.f;
    int w = idx & 511, f = (idx >> 9) & 511, bd = idx >> 18;
    int b = bd >> 1, d = bd & 1;
    size_t base = ((size_t)(8 + b * 2) * 512 + f) * 512 + w;
    float v = vdw[d * 2 + 0] * big[base] + vdw[d * 2 + 1] * big[base + 262144];
    u16 h, l;
    splth(v, h, l);
    size_t o = ((size_t)bd * 512 + f) * 512 + w;
    Vh[o] = h; Vl[o] = l;
}

// ---------------- pipelined fp16 2-term weight GEMM --------------------------
template<int OUT, int NT>  // OUT: 0 f32 ; 2 f32+res ; 3 sqrelu -> fp16 CT (NT=4)
__global__ void __launch_bounds__(256, 2) gemm_bb(
    const u16* __restrict__ Ah, const u16* __restrict__ Al,
    const u16* __restrict__ Bs,
    const float* __restrict__ Res, float* __restrict__ C,
    u16* __restrict__ CT,
    int M, int K, long projStride)
{
    constexpr int BN = NT * 32;
    constexpr int BSZ = BN * 128;
    constexpr int STG = 16384 + BSZ;
    extern __shared__ char sm[];
    uint32_t sb = smem_u32(sm);
    int tid = threadIdx.x, wid = tid >> 5, lane = tid & 31;
    int wm = wid >> 2, wn = wid & 3;
    int proj = blockIdx.z >> 2, bc = blockIdx.z & 3, c = bc & 1;
    const u16* Ab_h = Ah + proj * projStride + (size_t)c * M * K;
    const u16* Ab_l = Al + proj * projStride + (size_t)c * M * K;
    const u16* Bb = Bs + (size_t)bc * 512 * K;
    int m0 = blockIdx.y * 64, n0 = blockIdx.x * BN;

    auto load_stage = [&](int ch, int s) {
        uint32_t st = sb + s * STG;
        const u16* ah = Ab_h + (size_t)m0 * K + ch * 64;
        const u16* al = Ab_l + (size_t)m0 * K + ch * 64;
        for (int it = tid; it < 512; it += 256) {
            int r = it >> 3, cg = it & 7;
            uint32_t o = SWZ((uint32_t)(r * 128 + cg * 16));
            size_t gof = (size_t)r * K + cg * 8;
            cp16(st + o, ah + gof);
            cp16(st + 8192 + o, al + gof);
        }
        const u16* bh = Bb + (size_t)n0 * K + ch * 64;
        for (int it = tid; it < BN * 8; it += 256) {
            int r = it >> 3, cg = it & 7;
            uint32_t o = SWZ((uint32_t)(r * 128 + cg * 16));
            cp16(st + 16384 + o, bh + (size_t)r * K + cg * 8);
        }
    };

    float acc[2][NT][4] = {};
    int NC = K >> 6;
    load_stage(0, 0); cp_commit();
    for (int ch = 0; ch < NC; ch++) {
        if (ch + 1 < NC) { load_stage(ch + 1, (ch + 1) & 1); cp_commit(); cp_wait<1>(); }
        else cp_wait<0>();
        __syncthreads();
        uint32_t st = sb + (ch & 1) * STG;
        mma2_chunk<NT>(acc, st, st + 8192, st + 16384, wm, wn, lane);
        __syncthreads();
    }

    float* stg = (float*)sm;  // 64 x (BN+4)
    #pragma unroll
    for (int mi = 0; mi < 2; mi++)
        #pragma unroll
        for (int nt = 0; nt < NT; nt++) {
            int row = wm * 32 + mi * 16 + (lane >> 2);
            int col = wn * NT * 8 + nt * 8 + (lane & 3) * 2;
            stg[row * (BN + 4) + col] = acc[mi][nt][0];
            stg[row * (BN + 4) + col + 1] = acc[mi][nt][1];
            stg[(row + 8) * (BN + 4) + col] = acc[mi][nt][2];
            stg[(row + 8) * (BN + 4) + col + 1] = acc[mi][nt][3];
        }
    __syncthreads();

    if (OUT == 3) {
        int j = tid >> 1, msel = tid & 1;
        u16 hb[32];
        #pragma unroll
        for (int i = 0; i < 32; i++) {
            float v = stg[(msel * 32 + i) * (BN + 4) + j];
            float r = fmaxf(v, 0.f);
            hb[i] = f2h(r * r);
        }
        size_t o = ((size_t)bc * 512 + n0 + j) * (size_t)M + m0 + msel * 32;
        #pragma unroll
        for (int t = 0; t < 4; t++)
            reinterpret_cast<uint4*>(CT + o)[t] = ((uint4*)hb)[t];
    } else {
        float* Cb = C + (size_t)(proj * 4 + bc) * M * 512;
        constexpr int CPR = BN / 4;
        #pragma unroll
        for (int it = 0; it < 64 * CPR / 256; it++) {
            int idx = it * 256 + tid;
            int row = idx / CPR, c4 = idx % CPR;
            float4 v = *reinterpret_cast<float4*>(stg + row * (BN + 4) + c4 * 4);
            float vv[4] = {v.x, v.y, v.z, v.w};
            if (OUT == 2) {
                float4 rv = *reinterpret_cast<const float4*>(
                    Res + (size_t)bc * M * 512 + (size_t)(m0 + row) * 512 + n0 + c4 * 4);
                vv[0] += rv.x; vv[1] += rv.y; vv[2] += rv.z; vv[3] += rv.w;
            }
            float4 ov = {vv[0], vv[1], vv[2], vv[3]};
            *reinterpret_cast<float4*>(Cb + (size_t)(m0 + row) * 512 + n0 + c4 * 4) = ov;
        }
    }
}

// ---------------- attention scores -> exp -> unnormalized P fp16 -------------
__global__ void __launch_bounds__(256, 2) attn_qk_bb(
    const u16* __restrict__ QTh, const u16* __restrict__ QTl,
    const u16* __restrict__ KTh, const u16* __restrict__ KTl,
    u16* __restrict__ Ph, float* __restrict__ rowsum)
{
    __shared__ char sm[49152];
    uint32_t sb = smem_u32(sm);
    int tid = threadIdx.x, wid = tid >> 5, lane = tid & 31;
    int wm = wid >> 2, wn = wid & 3;
    int z = blockIdx.z, bc = z >> 3, hd = z & 7;
    int q0 = blockIdx.y * 64, k0 = blockIdx.x * 128;
    size_t qbase = ((size_t)bc * 512 + q0) * 512 + hd * 64;
    size_t kbase = ((size_t)bc * 512 + k0) * 512 + hd * 64;

    for (int it = tid; it < 512; it += 256) {
        int r = it >> 3, cg = it & 7;
        uint32_t o = SWZ((uint32_t)(r * 128 + cg * 16));
        cp16(sb + o, QTh + qbase + (size_t)r * 512 + cg * 8);
        cp16(sb + 8192 + o, QTl + qbase + (size_t)r * 512 + cg * 8);
    }
    for (int it = tid; it < 1024; it += 256) {
        int r = it >> 3, cg = it & 7;
        uint32_t o = SWZ((uint32_t)(r * 128 + cg * 16));
        cp16(sb + 16384 + o, KTh + kbase + (size_t)r * 512 + cg * 8);
        cp16(sb + 32768 + o, KTl + kbase + (size_t)r * 512 + cg * 8);
    }
    cp_commit(); cp_wait<0>();
    __syncthreads();

    float acc[2][4][4] = {};
    mma_chunk<4>(acc, sb, sb + 8192, sb + 16384, sb + 32768, wm, wn, lane);
    __syncthreads();
    float* stg = (float*)sm;
    #pragma unroll
    for (int mi = 0; mi < 2; mi++)
        #pragma unroll
        for (int nt = 0; nt < 4; nt++) {
            int row = wm * 32 + mi * 16 + (lane >> 2);
            int col = wn * 32 + nt * 8 + (lane & 3) * 2;
            stg[row * 132 + col] = acc[mi][nt][0];
            stg[row * 132 + col + 1] = acc[mi][nt][1];
            stg[(row + 8) * 132 + col] = acc[mi][nt][2];
            stg[(row + 8) * 132 + col + 1] = acc[mi][nt][3];
        }
    __syncthreads();
    const float scale = 0.044194173824159216f;  // 1/sqrt(512)
    int row = tid >> 2, seg = tid & 3;
    float lsum = 0.f;
    u16 hb[32];
    #pragma unroll
    for (int j = 0; j < 32; j++) {
        float p = __expf(stg[row * 132 + seg * 32 + j] * scale);
        lsum += p;
        hb[j] = f2h(p);
    }
    size_t o = (size_t)z * 262144 + (size_t)(q0 + row) * 512 + k0 + seg * 32;
    #pragma unroll
    for (int t = 0; t < 4; t++)
        reinterpret_cast<uint4*>(Ph + o)[t] = ((uint4*)hb)[t];
    lsum += __shfl_xor_sync(0xffffffffu, lsum, 1);
    lsum += __shfl_xor_sync(0xffffffffu, lsum, 2);
    if (seg == 0) atomicAdd(&rowsum[z * 512 + q0 + row], lsum);
}

// ---------------- attention output: P fp16 x V fp16 hi/lo, /rowsum -----------
__global__ void __launch_bounds__(256, 2) attn_pv_bb(
    const u16* __restrict__ Ph,
    const u16* __restrict__ Vh, const u16* __restrict__ Vl,
    const float* __restrict__ rowsum, u16* __restrict__ OT)
{
    extern __shared__ char sm[];
    uint32_t sb = smem_u32(sm);
    int tid = threadIdx.x, wid = tid >> 5, lane = tid & 31;
    int wm = wid >> 2, wn = wid & 3;
    int z = blockIdx.z, bc = z >> 3, hd = z & 7;
    int q0 = blockIdx.x * 64;
    size_t pbase = ((size_t)z * 512 + q0) * 512;
    size_t vbase = ((size_t)bc * 512 + hd * 64) * 512;

    auto load_stage = [&](int ch, int s) {
        uint32_t st = sb + s * 24576;
        for (int it = tid; it < 512; it += 256) {
            int r = it >> 3, cg = it & 7;
            uint32_t o = SWZ((uint32_t)(r * 128 + cg * 16));
            size_t pof = pbase + (size_t)r * 512 + ch * 64 + cg * 8;
            size_t vof = vbase + (size_t)r * 512 + ch * 64 + cg * 8;
            cp16(st + o, Ph + pof);
            cp16(st + 8192 + o, Vh + vof);
            cp16(st + 16384 + o, Vl + vof);
        }
    };

    float acc[2][2][4] = {};
    load_stage(0, 0); cp_commit();
    for (int ch = 0; ch < 8; ch++) {
        if (ch + 1 < 8) { load_stage(ch + 1, (ch + 1) & 1); cp_commit(); cp_wait<1>(); }
        else cp_wait<0>();
        __syncthreads();
        uint32_t st = sb + (ch & 1) * 24576;
        mma2b_chunk<2>(acc, st, st + 8192, st + 16384, wm, wn, lane);
        __syncthreads();
    }
    float* stg = (float*)sm;  // 64 x 68
    #pragma unroll
    for (int mi = 0; mi < 2; mi++)
        #pragma unroll
        for (int nt = 0; nt < 2; nt++) {
            int row = wm * 32 + mi * 16 + (lane >> 2);
            int col = wn * 16 + nt * 8 + (lane & 3) * 2;
            stg[row * 68 + col] = acc[mi][nt][0];
            stg[row * 68 + col + 1] = acc[mi][nt][1];
            stg[(row + 8) * 68 + col] = acc[mi][nt][2];
            stg[(row + 8) * 68 + col + 1] = acc[mi][nt][3];
        }
    __syncthreads();
    int row = tid >> 2, dseg = tid & 3;
    float inv = 1.f / rowsum[z * 512 + q0 + row];
    u16 hb[16];
    #pragma unroll
    for (int j = 0; j < 16; j++) hb[j] = f2h(stg[row * 68 + dseg * 16 + j] * inv);
    size_t o = ((size_t)bc * 512 + q0 + row) * 512 + hd * 64 + dseg * 16;
    reinterpret_cast<uint4*>(OT + o)[0] = ((uint4*)hb)[0];
    reinterpret_cast<uint4*>(OT + o)[1] = ((uint4*)hb)[1];
}

// ---------------- channel mix (enc/dec, f32) ---------------------------------
template<bool SQRELU, bool HASADD>
__global__ void __launch_bounds__(256) mix_k(
    const float* __restrict__ X, const float* __restrict__ dw,
    const float* __restrict__ Add, float* __restrict__ Y, int Fd)
{
    int idx = blockIdx.x * 256 + threadIdx.x;
    int w = idx & 511;
    int f = (idx >> 9) % Fd;
    int bd = idx / (512 * Fd);
    int b = bd >> 1, d = bd & 1;
    size_t base = ((size_t)(b * 2) * Fd + f) * 512 + w;
    float v = dw[d * 2 + 0] * X[base] + dw[d * 2 + 1] * X[base + (size_t)Fd * 512];
    if (SQRELU) { float r = fmaxf(v, 0.f); v = r * r; }
    if (HASADD) v += Add[idx];
    Y[idx] = v;
}

// ---------------- host --------------------------------------------------------
extern "C" void kernel_launch(void* const* d_in, const int* in_sizes, int n_in,
                              void* d_out, int out_size)
{
    const float* x     = (const float*)d_in[0];
    const float* e1_pw = (const float*)d_in[1];
    const float* e1_dw = (const float*)d_in[2];
    const float* e2_pw = (const float*)d_in[3];
    const float* e2_dw = (const float*)d_in[4];
    const float* ei_pw = (const float*)d_in[5];
    const float* ei_dw = (const float*)d_in[6];
    const float* n1_w  = (const float*)d_in[7];
    const float* n1_b  = (const float*)d_in[8];
    const float* q_dw  = (const float*)d_in[10];
    const float* k_dw  = (const float*)d_in[12];
    const float* v_dw  = (const float*)d_in[14];
    const float* n2_w  = (const float*)d_in[16];
    const float* n2_b  = (const float*)d_in[17];
    const float* d1_dw = (const float*)d_in[21];
    const float* d2_dw = (const float*)d_in[23];
    const float* di_dw = (const float*)d_in[25];
    float* out = (float*)d_out;
    (void)in_sizes; (void)n_in; (void)out_size;

    float *e, *q, *big, *s, *rowsum;
    cudaGetSymbolAddress((void**)&e, g_e);
    cudaGetSymbolAddress((void**)&q, g_q);
    cudaGetSymbolAddress((void**)&big, g_big);
    cudaGetSymbolAddress((void**)&s, g_s);
    cudaGetSymbolAddress((void**)&rowsum, g_rowsum);
    u16 *wh, *wl, *ath, *hth, *oth, *qth, *qtl, *kth, *ktl, *vh, *vl, *ph;
    cudaGetSymbolAddress((void**)&wh, g_wh);   cudaGetSymbolAddress((void**)&wl, g_wl);
    cudaGetSymbolAddress((void**)&ath, g_ath);
    cudaGetSymbolAddress((void**)&hth, g_hth);
    cudaGetSymbolAddress((void**)&oth, g_oth);
    cudaGetSymbolAddress((void**)&qth, g_qth); cudaGetSymbolAddress((void**)&qtl, g_qtl);
    cudaGetSymbolAddress((void**)&kth, g_kth); cudaGetSymbolAddress((void**)&ktl, g_ktl);
    cudaGetSymbolAddress((void**)&vh, g_vh);   cudaGetSymbolAddress((void**)&vl, g_vl);
    cudaGetSymbolAddress((void**)&ph, g_ph);

    const int SMG4 = 65536, SMG2 = 49152, SMPV = 49152;
    cudaFuncSetAttribute(gemm_bb<0,4>, cudaFuncAttributeMaxDynamicSharedMemorySize, SMG4);
    cudaFuncSetAttribute(gemm_bb<3,4>, cudaFuncAttributeMaxDynamicSharedMemorySize, SMG4);
    cudaFuncSetAttribute(gemm_bb<0,2>, cudaFuncAttributeMaxDynamicSharedMemorySize, SMG2);
    cudaFuncSetAttribute(gemm_bb<2,2>, cudaFuncAttributeMaxDynamicSharedMemorySize, SMG2);
    cudaFuncSetAttribute(attn_pv_bb, cudaFuncAttributeMaxDynamicSharedMemorySize, SMPV);

    dim3 tsG512(8, 8, 4), tsG1024(8, 16, 4);

    split_w<<<20096, 256>>>(e1_pw, e2_pw, ei_pw,
        (const float*)d_in[9], (const float*)d_in[11], (const float*)d_in[13],
        (const float*)d_in[15], (const float*)d_in[18], (const float*)d_in[19],
        (const float*)d_in[20], (const float*)d_in[22], (const float*)d_in[24]);

    // encoder (BN=64: 256 blocks per launch)
    tsplit<<<tsG1024, 256>>>(x, ath, 1024);
    gemm_bb<0,2><<<dim3(8, 8, 4), 256, SMG2>>>(wh + OFF_E1, wl + OFF_E1, ath, nullptr, big, nullptr, 512, 1024, 0);
    mix_k<true, false><<<4096, 256>>>(big, e1_dw, nullptr, q, 512);
    tsplit<<<tsG512, 256>>>(q, hth, 512);
    gemm_bb<0,2><<<dim3(8, 8, 4), 256, SMG2>>>(wh + OFF_E2, wl + OFF_E2, hth, nullptr, big, nullptr, 512, 512, 0);
    mix_k<false, false><<<4096, 256>>>(big, e2_dw, nullptr, s, 512);
    gemm_bb<0,2><<<dim3(8, 8, 4), 256, SMG2>>>(wh + OFF_EI, wl + OFF_EI, ath, nullptr, big, nullptr, 512, 1024, 0);
    mix_k<false, true><<<4096, 256>>>(big, ei_dw, s, e, 512);

    for (int i = 0; i < NLAYER; i++) {
        long lw = (long)i * 524288;
        fn_tsplit<<<dim3(8, 8, 4), 256>>>(e, n1_w + (size_t)i * 1024, n1_b + (size_t)i * 1024, hth);
        gemm_bb<0,4><<<dim3(4, 8, 12), 256, SMG4>>>(wh + OFF_Q + lw, wl + OFF_Q + lw, hth,
                                                    nullptr, big, nullptr, 512, 512, OFF_K - OFF_Q);
        rope_tsplit<<<dim3(8, 8, 8), 256>>>(big, q_dw + i * 4, k_dw + i * 4, qth, qtl, kth, ktl);
        qkv_v<<<4096, 256>>>(big, v_dw + i * 4, vh, vl, rowsum);
        attn_qk_bb<<<dim3(4, 8, 32), 256>>>(qth, qtl, kth, ktl, ph, rowsum);
        attn_pv_bb<<<dim3(8, 1, 32), 256, SMPV>>>(ph, vh, vl, rowsum, oth);
        gemm_bb<2,2><<<dim3(8, 8, 4), 256, SMG2>>>(wh + OFF_O + lw, wl + OFF_O + lw, oth,
                                                   e, e, nullptr, 512, 512, 0);
        fn_tsplit<<<dim3(8, 8, 4), 256>>>(e, n2_w + (size_t)i * 1024, n2_b + (size_t)i * 1024, hth);
        long lf = (long)i * 2097152;
        gemm_bb<3,4><<<dim3(4, 32, 4), 256, SMG4>>>(wh + OFF_F1 + lf, wl + OFF_F1 + lf, hth,
                                                    nullptr, nullptr, ath, 2048, 512, 0);
        gemm_bb<2,2><<<dim3(8, 8, 4), 256, SMG2>>>(wh + OFF_F2 + lf, wl + OFF_F2 + lf, ath,
                                                   e, e, nullptr, 512, 2048, 0);
    }

    // decoder (BN=64: 512 blocks per launch)
    tsplit<<<tsG512, 256>>>(e, hth, 512);
    gemm_bb<0,2><<<dim3(8, 16, 4), 256, SMG2>>>(wh + OFF_D1, wl + OFF_D1, hth, nullptr, big, nullptr, 1024, 512, 0);
    mix_k<true, false><<<8192, 256>>>(big, d1_dw, nullptr, s, 1024);
    tsplit<<<tsG1024, 256>>>(s, ath, 1024);
    gemm_bb<0,2><<<dim3(8, 16, 4), 256, SMG2>>>(wh + OFF_D2, wl + OFF_D2, ath, nullptr, big + 2097152, nullptr, 1024, 1024, 0);
    mix_k<false, false><<<8192, 256>>>(big + 2097152, d2_dw, nullptr, s + 4194304, 1024);
    gemm_bb<0,2><<<dim3(8, 16, 4), 256, SMG2>>>(wh + OFF_DI, wl + OFF_DI, hth, nullptr, big, nullptr, 1024, 512, 0);
    mix_k<false, true><<<8192, 256>>>(big, di_dw, s + 4194304, out, 1024);
}